// round 8
// baseline (speedup 1.0000x reference)
#include <cuda_runtime.h>
#include <math.h>

// ---------------- problem constants ----------------
static constexpr int Bx = 32, Lx = 680, Cx = 1024;
static constexpr int Sx = 10, SLOTSx = 32, Rx = 8, NCATx = 22;
static constexpr int MRx = 64, AHx = 128;
static constexpr int NROW = Bx * Lx;            // 21760
static constexpr int NKMAX = Sx * SLOTSx;       // 320
static constexpr int NQ = NROW * Cx;            // 22282240
static constexpr int NKB = NKMAX + 2560;        // 2880 combined rows

__constant__ int c_begin[10] = {0,1,5,14,30,55,91,155,255,424};

// ---------------- device scratch ----------------
__device__ unsigned g_x_h[NQ];
__device__ unsigned g_qs_h[NQ];
__device__ unsigned g_WqT_h[Cx*Cx], g_WqT_l[Cx*Cx];
__device__ unsigned g_WkT_h[Cx*Cx], g_WkT_l[Cx*Cx];
__device__ unsigned g_WvT_h[Cx*Cx], g_WvT_l[Cx*Cx];
__device__ unsigned g_aW1T_h[AHx*Cx], g_aW1T_l[AHx*Cx];
__device__ unsigned g_w1T_h[(2*MRx)*Cx], g_w1T_l[(2*MRx)*Cx];
__device__ unsigned g_kW2T_h[Cx*MRx], g_kW2T_l[Cx*MRx];
__device__ unsigned g_vW2T_h[Cx*MRx], g_vW2T_l[Cx*MRx];
__device__ unsigned g_skb_in_h[NKB*Cx];            // [shm ; cat_B] hi plane

__device__ float    g_skbf[NKB*Cx];                // [sk ; cbk] f32
__device__ unsigned g_skbh[NKB*Cx];                // [sk ; cbk] hi
__device__ float    g_svbTf[Cx*NKB];               // [svT | cbvT] f32
__device__ unsigned g_svbTh[Cx*NKB];               // hi
__device__ unsigned g_kc_h[Bx*NKMAX*Cx];
__device__ unsigned g_vcT_h[Bx*Cx*NKMAX];
__device__ float    g_lgsf[NROW*NKMAX], g_lgcf[NROW*NKMAX];
__device__ unsigned g_lgs_h[NROW*NKMAX], g_lgc_h[NROW*NKMAX];
__device__ float    g_qhf[NROW*AHx];
__device__ float    g_memf[NQ];
__device__ unsigned g_mem_h[NQ], g_mem_l[NQ];
__device__ unsigned g_t1_h[NROW*(2*MRx)], g_t1_l[NROW*(2*MRx)];
__device__ float    g_acat[NCATx*AHx];
__device__ float    g_ascale[Sx*AHx];
__device__ float    g_scal[4];
__device__ float    g_bias1[2*MRx];

// ---------------- helpers ----------------
__device__ __forceinline__ void split_tf32(float x, unsigned& hi, unsigned& lo) {
    unsigned h; asm("cvt.rna.tf32.f32 %0, %1;" : "=r"(h) : "f"(x));
    float hf = __uint_as_float(h);
    unsigned l; asm("cvt.rna.tf32.f32 %0, %1;" : "=r"(l) : "f"(x - hf));
    hi = h; lo = l;
}
__device__ __forceinline__ unsigned to_tf32(float x) {
    unsigned h; asm("cvt.rna.tf32.f32 %0, %1;" : "=r"(h) : "f"(x)); return h;
}
__device__ __forceinline__ void mma8(float* d, const unsigned* a, const unsigned* b) {
    asm volatile(
        "mma.sync.aligned.m16n8k8.row.col.f32.tf32.tf32.f32 "
        "{%0,%1,%2,%3}, {%4,%5,%6,%7}, {%8,%9}, {%0,%1,%2,%3};"
        : "+f"(d[0]), "+f"(d[1]), "+f"(d[2]), "+f"(d[3])
        : "r"(a[0]), "r"(a[1]), "r"(a[2]), "r"(a[3]), "r"(b[0]), "r"(b[1]));
}
__device__ __forceinline__ uint4 ldsm4(unsigned a) {
    uint4 r;
    asm volatile("ldmatrix.sync.aligned.m8n8.x4.shared.b16 {%0,%1,%2,%3}, [%4];"
        : "=r"(r.x), "=r"(r.y), "=r"(r.z), "=r"(r.w) : "r"(a));
    return r;
}
__device__ __forceinline__ unsigned smaddr(const void* p) {
    unsigned a;
    asm("{.reg .u64 u; cvta.to.shared.u64 u, %1; cvt.u32.u64 %0, u;}" : "=r"(a) : "l"(p));
    return a;
}
__device__ __forceinline__ void cp16(unsigned dst, const void* src, bool ok) {
    int sz = ok ? 16 : 0;
    asm volatile("cp.async.cg.shared.global [%0], [%1], 16, %2;\n" :: "r"(dst), "l"(src), "r"(sz));
}
__device__ __forceinline__ void cp_commit() { asm volatile("cp.async.commit_group;"); }
template<int N> __device__ __forceinline__ void cp_wait() {
    asm volatile("cp.async.wait_group %0;" :: "n"(N));
}

// ---------------- prep ----------------
__global__ void prep_kernel(const float* gk, const float* gv, const float* lt) {
    float temp = expf(lt[0]);
    temp = fminf(fmaxf(temp, 0.05f), 1.0f);
    g_scal[0] = (1.0f / 32.0f) / temp;
    g_scal[1] = 1.0f / (1.0f + expf(-gk[0]));
    g_scal[2] = 1.0f / (1.0f + expf(-gv[0]));
}

// ---------------- fp32 -> tf32 hi plane ----------------
__global__ void cvt_kernel(const float* __restrict__ in, unsigned* __restrict__ hi, int n4) {
    int i = blockIdx.x * 256 + threadIdx.x;
    if (i >= n4) return;
    float4 v = ((const float4*)in)[i];
    uint4 h;
    h.x = to_tf32(v.x); h.y = to_tf32(v.y); h.z = to_tf32(v.z); h.w = to_tf32(v.w);
    ((uint4*)hi)[i] = h;
}

// ---------------- transpose + split: in [R][C] -> planes [C][R] ----------------
__global__ void tsplit_kernel(const float* __restrict__ in, int R, int C,
                              unsigned* __restrict__ oh, unsigned* __restrict__ ol)
{
    __shared__ float t[32][33];
    int r0 = blockIdx.y * 32, c0 = blockIdx.x * 32;
    int tx = threadIdx.x, ty = threadIdx.y;
    #pragma unroll
    for (int i = 0; i < 32; i += 8) {
        int r = r0 + ty + i;
        t[ty + i][tx] = (r < R && c0 + tx < C) ? in[(size_t)r * C + c0 + tx] : 0.f;
    }
    __syncthreads();
    #pragma unroll
    for (int i = 0; i < 32; i += 8) {
        int c = c0 + ty + i, r = r0 + tx;
        if (c < C && r < R) {
            unsigned h, l; split_tf32(t[tx][ty + i], h, l);
            oh[(size_t)c * R + r] = h;
            ol[(size_t)c * R + r] = l;
        }
    }
}

// ---------------- GEMM ----------------
static constexpr int WR_F32 = 1, WR_SPLIT = 2, WR_HI = 4;

struct GemmArgs {
    int M, N, K;
    const unsigned *Ah, *Al; int lda; long long sA;
    const unsigned *Bh, *Bl; int ldb; long long sB;   // B is [N][K] (NT)
    float* Cf; unsigned *Chi, *Clo; int ldc; long long sC;
    const float* bias; const float* gate;
    int accum, wr;
};

// BN=128 (2 CTAs/SM). NPASS=1: BK=32, 3-stage ring. NPASS=3: BK=16, 2-stage.
template<int NPASS>
__global__ void __launch_bounds__(256, 2) gemm_tmpl(GemmArgs g)
{
    constexpr int BK  = (NPASS == 3) ? 16 : 32;
    constexpr int AW  = BK + 4;
    constexpr int ASZ = 128 * AW;               // words per plane tile
    constexpr int NPL = (NPASS == 3) ? 2 : 1;
    constexpr int NSTG = (NPASS == 3) ? 2 : 3;
    constexpr int STG = NPL * 2 * ASZ;          // words per stage
    constexpr int CPT = BK / 8;                 // cp16 iterations per thread per plane
    extern __shared__ unsigned sm[];

    const int tid = threadIdx.x, lane = tid & 31, wid = tid >> 5;
    const int wm = wid >> 2, wn = wid & 3, tg = lane & 3, gid = lane >> 2;
    const int bm = blockIdx.y * 128, bn = blockIdx.x * 128;
    const long long z = blockIdx.z;

    const unsigned* Ap[2];
    Ap[0] = g.Ah + z * g.sA;
    Ap[1] = (NPASS == 3) ? g.Al + z * g.sA : Ap[0];
    const unsigned* Bp[2];
    Bp[0] = g.Bh + z * g.sB;
    Bp[1] = (NPASS == 3) ? g.Bl + z * g.sB : Bp[0];

    const unsigned smbase = smaddr(sm);

    const int am = lane >> 3;
    const int a_row = (am & 1) * 8 + (lane & 7);
    const int a_kw  = (am >> 1) * 4;
    const int b_row = (am >> 1) * 8 + (lane & 7);
    const int b_kw  = (am & 1) * 4;
    unsigned aA[4], bA[2];
    #pragma unroll
    for (int mt = 0; mt < 4; mt++)
        aA[mt] = smbase + (unsigned)((wm*64 + mt*16 + a_row) * AW + a_kw) * 4u;
    #pragma unroll
    for (int pr = 0; pr < 2; pr++)
        bA[pr] = smbase + (unsigned)(NPL * ASZ) * 4u
               + (unsigned)((wn*32 + pr*16 + b_row) * AW + b_kw) * 4u;

    float acc[4][4][4];
    #pragma unroll
    for (int mt = 0; mt < 4; mt++)
        #pragma unroll
        for (int nt = 0; nt < 4; nt++)
            #pragma unroll
            for (int u = 0; u < 4; u++) acc[mt][nt][u] = 0.f;

    auto load_stage = [&](int s, int k0) {
        unsigned base = smbase + (unsigned)(s * STG) * 4u;
        #pragma unroll
        for (int p = 0; p < NPL; p++) {
            #pragma unroll
            for (int j = 0; j < CPT; j++) {
                int c = tid + j * 256;
                int row = c / (BK/4), kc = (c % (BK/4)) * 4;
                bool ok = (bm + row) < g.M;
                const unsigned* src = ok ? Ap[p] + (size_t)(bm + row) * g.lda + k0 + kc : Ap[p];
                cp16(base + (unsigned)(p * ASZ + row * AW + kc) * 4u, src, ok);
            }
        }
        unsigned bbase = base + (unsigned)(NPL * ASZ) * 4u;
        #pragma unroll
        for (int p = 0; p < NPL; p++) {
            #pragma unroll
            for (int j = 0; j < CPT; j++) {
                int c = tid + j * 256;
                int row = c / (BK/4), kc = (c % (BK/4)) * 4;
                bool ok = (bn + row) < g.N;
                const unsigned* src = ok ? Bp[p] + (size_t)(bn + row) * g.ldb + k0 + kc : Bp[p];
                cp16(bbase + (unsigned)(p * ASZ + row * AW + kc) * 4u, src, ok);
            }
        }
    };

    auto compute = [&](int s) {
        const unsigned so = (unsigned)(s * STG) * 4u;
        #pragma unroll
        for (int kk = 0; kk < BK; kk += 8) {
            const unsigned kb = so + (unsigned)kk * 4u;
            unsigned bh[4][2], bl[4][2];
            #pragma unroll
            for (int pr = 0; pr < 2; pr++) {
                uint4 r = ldsm4(bA[pr] + kb);
                bh[pr*2+0][0] = r.x; bh[pr*2+0][1] = r.y;
                bh[pr*2+1][0] = r.z; bh[pr*2+1][1] = r.w;
                if (NPASS == 3) {
                    uint4 q = ldsm4(bA[pr] + kb + (unsigned)ASZ * 4u);
                    bl[pr*2+0][0] = q.x; bl[pr*2+0][1] = q.y;
                    bl[pr*2+1][0] = q.z; bl[pr*2+1][1] = q.w;
                }
            }
            #pragma unroll
            for (int mt = 0; mt < 4; mt++) {
                uint4 ah4 = ldsm4(aA[mt] + kb);
                uint4 al4 = make_uint4(0,0,0,0);
                if (NPASS == 3) al4 = ldsm4(aA[mt] + kb + (unsigned)ASZ * 4u);
                #pragma unroll
                for (int nt = 0; nt < 4; nt++) {
                    mma8(acc[mt][nt], (const unsigned*)&ah4, bh[nt]);
                    if (NPASS == 3) {
                        mma8(acc[mt][nt], (const unsigned*)&ah4, bl[nt]);
                        mma8(acc[mt][nt], (const unsigned*)&al4, bh[nt]);
                    }
                }
            }
        }
    };

    const int nK = g.K / BK;
    if (NSTG == 3) {
        load_stage(0, 0);
        cp_commit();
        if (nK > 1) load_stage(1, BK);
        cp_commit();
        for (int kt = 0; kt < nK; kt++) {
            cp_wait<1>();
            __syncthreads();
            if (kt + 2 < nK) load_stage((kt + 2) % 3, (kt + 2) * BK);
            cp_commit();
            compute(kt % 3);
        }
    } else {
        load_stage(0, 0);
        cp_commit();
        for (int kt = 0; kt < nK; kt++) {
            if (kt + 1 < nK) {
                load_stage((kt + 1) & 1, (kt + 1) * BK);
                cp_commit();
                cp_wait<1>();
            } else {
                cp_wait<0>();
            }
            __syncthreads();
            compute(kt & 1);
            __syncthreads();
        }
    }

    // ---------------- epilogue ----------------
    const float gt = g.gate ? *g.gate : 1.0f;
    float* Cf = g.Cf + z * g.sC;
    unsigned* Chi = g.Chi + z * g.sC;
    unsigned* Clo = g.Clo + z * g.sC;
    #pragma unroll
    for (int mt = 0; mt < 4; mt++) {
        int r0 = bm + wm * 64 + mt * 16 + gid;
        int r1 = r0 + 8;
        #pragma unroll
        for (int nt = 0; nt < 4; nt++) {
            int col = bn + wn * 32 + nt * 8 + 2 * tg;
            if (col >= g.N) continue;
            float b0 = g.bias ? g.bias[col]     : 0.f;
            float b1 = g.bias ? g.bias[col + 1] : 0.f;
            #pragma unroll
            for (int half = 0; half < 2; half++) {
                int r = half ? r1 : r0;
                if (r >= g.M) continue;
                size_t o = (size_t)r * g.ldc + col;
                float v0 = gt * (acc[mt][nt][half*2+0] + b0);
                float v1 = gt * (acc[mt][nt][half*2+1] + b1);
                if (g.accum) { v0 += Cf[o]; v1 += Cf[o+1]; }
                if (g.wr & WR_F32) *(float2*)(Cf + o) = make_float2(v0, v1);
                if (g.wr & WR_SPLIT) {
                    unsigned h0,l0,h1,l1;
                    split_tf32(v0, h0, l0); split_tf32(v1, h1, l1);
                    Chi[o] = h0; Chi[o+1] = h1;
                    Clo[o] = l0; Clo[o+1] = l1;
                }
                if (g.wr & WR_HI) {
                    Chi[o] = to_tf32(v0); Chi[o+1] = to_tf32(v1);
                }
            }
        }
    }
}

// ---------------- kc (hi plane): kc = sk + sum_r a_r * cbk_r ----------------
__global__ void __launch_bounds__(256) kcvc_k_kernel(const int* __restrict__ catids,
                                                     const float* __restrict__ cat_A)
{
    int blk = blockIdx.x;            // b*320 + key
    int b = blk / 320, key = blk % 320;
    int v = key >> 5, s = key & 31;
    int cid = catids[b]; if (cid < 0) cid = 0;
    float a[Rx];
    #pragma unroll
    for (int r = 0; r < Rx; r++) a[r] = cat_A[(cid*Sx + v)*Rx + r];
    int c = threadIdx.x * 4;
    float4 ka = *(const float4*)(g_skbf + (size_t)key*Cx + c);
    #pragma unroll
    for (int r = 0; r < Rx; r++) {
        size_t idx = ((size_t)(NKMAX + (v*Rx + r)*SLOTSx + s))*Cx + c;
        float4 kb = *(const float4*)(g_skbf + idx);
        ka.x += a[r]*kb.x; ka.y += a[r]*kb.y; ka.z += a[r]*kb.z; ka.w += a[r]*kb.w;
    }
    size_t o = ((size_t)(b*320 + key))*Cx + c;
    uint4 h;
    h.x = to_tf32(ka.x); h.y = to_tf32(ka.y); h.z = to_tf32(ka.z); h.w = to_tf32(ka.w);
    *(uint4*)(g_kc_h + o) = h;
}

// ---------------- vcT (hi plane) ----------------
__global__ void __launch_bounds__(320) kcvc_v_kernel(const int* __restrict__ catids,
                                                     const float* __restrict__ cat_A)
{
    int c = blockIdx.x;        // 0..1023
    int b = blockIdx.y;        // 0..31
    int key = threadIdx.x;     // 0..319
    int cid = catids[b]; if (cid < 0) cid = 0;
    int v = key >> 5, s = key & 31;
    const float* ar = cat_A + (cid*Sx + v)*Rx;
    float acc = g_svbTf[(size_t)c*NKB + key];
    #pragma unroll
    for (int r = 0; r < Rx; r++)
        acc += ar[r] * g_svbTf[(size_t)c*NKB + NKMAX + (v*Rx + r)*SLOTSx + s];
    g_vcT_h[((size_t)b*Cx + c)*NKMAX + key] = to_tf32(acc);
}

// ---------------- alpha constant tables ----------------
__global__ void aconst_kernel(const float* __restrict__ cat_emb,
                              const float* __restrict__ scale_emb,
                              const float* __restrict__ aW1,
                              const float* __restrict__ ab1)
{
    int idx = blockIdx.x;
    int h = threadIdx.x;
    if (idx < NCATx) {
        float acc = 0.f;
        const float* ce = cat_emb + (size_t)idx * Cx;
        for (int c = 0; c < Cx; c++)
            acc += ce[c] * aW1[(size_t)(Cx + c)*AHx + h];
        g_acat[idx*AHx + h] = acc;
    } else {
        int i = idx - NCATx;
        float acc = ab1[h];
        const float* se = scale_emb + (size_t)i * Cx;
        for (int c = 0; c < Cx; c++)
            acc += se[c] * aW1[(size_t)(2*Cx + c)*AHx + h];
        g_ascale[i*AHx + h] = acc;
    }
}

// ---------------- alpha + masked softmax + prescale -> tf32 hi planes ----------------
__global__ void __launch_bounds__(256) softmax_kernel(const int* __restrict__ catids,
                                                      const float* __restrict__ aW2,
                                                      const float* __restrict__ ab2)
{
    int w = threadIdx.x >> 5, lane = threadIdx.x & 31;
    int row = blockIdx.x * 8 + w;
    if (row >= NROW) return;
    int b = row / Lx, l = row % Lx;
    int i = 0;
    #pragma unroll
    for (int u = 1; u < 10; u++) if (l >= c_begin[u]) i = u;
    int nk = (i + 1) * SLOTSx;
    float ls = g_scal[0];

    // alpha gate
    int cid = catids[b];
    float a = 0.f;
    if (cid >= 0) {
        const float* qhp = g_qhf + (size_t)row*AHx;
        const float* ac  = g_acat + cid*AHx;
        const float* as  = g_ascale + i*AHx;
        float acc = 0.f;
        #pragma unroll
        for (int h = lane; h < AHx; h += 32) {
            float xv = qhp[h] + ac[h] + as[h];
            float ge = 0.5f*xv*(1.0f + erff(xv*0.70710678118654752f));
            acc += ge * aW2[h];
        }
        #pragma unroll
        for (int o = 16; o > 0; o >>= 1) acc += __shfl_xor_sync(0xffffffffu, acc, o);
        a = 1.0f/(1.0f + expf(-(acc + ab2[0])));
    }

    #pragma unroll
    for (int s = 0; s < 2; s++) {
        const float* p = (s ? g_lgcf : g_lgsf) + (size_t)row * NKMAX;
        unsigned* q = (s ? g_lgc_h : g_lgs_h) + (size_t)row * NKMAX;
        float wgt = s ? a : (1.0f - a);
        float v[10];
        int cnt = 0;
        float mx = -3.4e38f;
        for (int j = lane; j < nk; j += 32) { float t = p[j]*ls; v[cnt++] = t; mx = fmaxf(mx, t); }
        #pragma unroll
        for (int o = 16; o > 0; o >>= 1) mx = fmaxf(mx, __shfl_xor_sync(0xffffffffu, mx, o));
        float sum = 0.f;
        for (int c2 = 0; c2 < cnt; c2++) { v[c2] = expf(v[c2] - mx); sum += v[c2]; }
        #pragma unroll
        for (int o = 16; o > 0; o >>= 1) sum += __shfl_xor_sync(0xffffffffu, sum, o);
        float inv = wgt / sum;
        cnt = 0;
        for (int j = lane; j < NKMAX; j += 32)
            q[j] = (j < nk) ? to_tf32(v[cnt++] * inv) : 0u;
    }
}

// ---------------- tail ----------------
__global__ void tail_kernel(float* out, int n2, int total) {
    int idx = n2 + blockIdx.x*blockDim.x + threadIdx.x;
    if (idx < total) out[idx] = 0.f;
}

// ---------------- host helpers ----------------
static void launch_gemm(int npass, int M, int N, int K,
                        const unsigned* Ah, const unsigned* Al, int lda, long long sA,
                        const unsigned* Bh, const unsigned* Bl, int ldb, long long sB,
                        float* Cf, unsigned* Chi, unsigned* Clo, int ldc, long long sC,
                        const float* bias, const float* gate,
                        int accum, int wr, int batches)
{
    GemmArgs g;
    g.M=M; g.N=N; g.K=K;
    g.Ah=Ah; g.Al=Al; g.lda=lda; g.sA=sA;
    g.Bh=Bh; g.Bl=Bl; g.ldb=ldb; g.sB=sB;
    g.Cf=Cf; g.Chi=Chi; g.Clo=Clo; g.ldc=ldc; g.sC=sC;
    g.bias=bias; g.gate=gate; g.accum=accum; g.wr=wr;
    dim3 grid((N + 127)/128, (M + 127)/128, batches);
    if (npass == 3) gemm_tmpl<3><<<grid, 256, 81920>>>(g);
    else            gemm_tmpl<1><<<grid, 256, 110592>>>(g);
}

static void launch_tsplit(const float* in, int R, int C, unsigned* oh, unsigned* ol)
{
    dim3 grid((C + 31)/32, (R + 31)/32);
    tsplit_kernel<<<grid, dim3(32, 8)>>>(in, R, C, oh, ol);
}

// ---------------- launch ----------------
extern "C" void kernel_launch(void* const* d_in, const int* in_sizes, int n_in,
                              void* d_out, int out_size) {
    const float* x        = (const float*)d_in[0];
    const int*   catids   = (const int*)  d_in[1];
    const float* shmem    = (const float*)d_in[2];
    const float* cat_A    = (const float*)d_in[3];
    const float* cat_B    = (const float*)d_in[4];
    const float* cat_emb  = (const float*)d_in[5];
    const float* scale_emb= (const float*)d_in[6];
    const float* Wq       = (const float*)d_in[7];
    const float* Wk       = (const float*)d_in[8];
    const float* Wv       = (const float*)d_in[9];
    const float* aW1      = (const float*)d_in[10];
    const float* ab1      = (const float*)d_in[11];
    const float* aW2      = (const float*)d_in[12];
    const float* ab2      = (const float*)d_in[13];
    const float* kW1      = (const float*)d_in[14];
    const float* kb1      = (const float*)d_in[15];
    const float* kW2      = (const float*)d_in[16];
    const float* kb2      = (const float*)d_in[17];
    const float* vW1      = (const float*)d_in[18];
    const float* vb1      = (const float*)d_in[19];
    const float* vW2      = (const float*)d_in[20];
    const float* vb2      = (const float*)d_in[21];
    const float* gk       = (const float*)d_in[22];
    const float* gv       = (const float*)d_in[23];
    const float* lt       = (const float*)d_in[24];

    cudaFuncSetAttribute(gemm_tmpl<3>, cudaFuncAttributeMaxDynamicSharedMemorySize, 81920);
    cudaFuncSetAttribute(gemm_tmpl<1>, cudaFuncAttributeMaxDynamicSharedMemorySize, 110592);

    #define SYM(t, p, s) t p; cudaGetSymbolAddress((void**)&p, s)
    SYM(unsigned*, p_x_h, g_x_h);
    SYM(unsigned*, p_qs_h, g_qs_h);
    SYM(unsigned*, p_WqT_h, g_WqT_h); SYM(unsigned*, p_WqT_l, g_WqT_l);
    SYM(unsigned*, p_WkT_h, g_WkT_h); SYM(unsigned*, p_WkT_l, g_WkT_l);
    SYM(unsigned*, p_WvT_h, g_WvT_h); SYM(unsigned*, p_WvT_l, g_WvT_l);
    SYM(unsigned*, p_aW1T_h, g_aW1T_h); SYM(unsigned*, p_aW1T_l, g_aW1T_l);
    SYM(unsigned*, p_w1T_h, g_w1T_h); SYM(unsigned*, p_w1T_l, g_w1T_l);
    SYM(unsigned*, p_kW2T_h, g_kW2T_h); SYM(unsigned*, p_kW2T_l, g_kW2T_l);
    SYM(unsigned*, p_vW2T_h, g_vW2T_h); SYM(unsigned*, p_vW2T_l, g_vW2T_l);
    SYM(unsigned*, p_skb_in_h, g_skb_in_h);
    SYM(float*,    p_skbf, g_skbf);
    SYM(unsigned*, p_skbh, g_skbh);
    SYM(float*,    p_svbTf, g_svbTf);
    SYM(unsigned*, p_svbTh, g_svbTh);
    SYM(unsigned*, p_kc_h, g_kc_h);
    SYM(unsigned*, p_vcT_h, g_vcT_h);
    SYM(float*,    p_lgsf, g_lgsf);   SYM(float*,    p_lgcf, g_lgcf);
    SYM(unsigned*, p_lgs_h, g_lgs_h); SYM(unsigned*, p_lgc_h, g_lgc_h);
    SYM(float*,    p_qhf, g_qhf);
    SYM(float*,    p_memf, g_memf);
    SYM(unsigned*, p_mem_h, g_mem_h); SYM(unsigned*, p_mem_l, g_mem_l);
    SYM(unsigned*, p_t1_h, g_t1_h);   SYM(unsigned*, p_t1_l, g_t1_l);
    SYM(float*,    p_scal, g_scal);
    SYM(float*,    p_bias1, g_bias1);
    #undef SYM

    prep_kernel<<<1, 1>>>(gk, gv, lt);

    // -------- operand preparation --------
    cvt_kernel<<<(NQ/4 + 255)/256, 256>>>(x, p_x_h, NQ/4);
    cvt_kernel<<<(NKMAX*Cx/4 + 255)/256, 256>>>(shmem, p_skb_in_h, NKMAX*Cx/4);
    cvt_kernel<<<(2560*Cx/4 + 255)/256, 256>>>(cat_B, p_skb_in_h + NKMAX*Cx, 2560*Cx/4);
    launch_tsplit(Wq, Cx, Cx, p_WqT_h, p_WqT_l);
    launch_tsplit(Wk, Cx, Cx, p_WkT_h, p_WkT_l);
    launch_tsplit(Wv, Cx, Cx, p_WvT_h, p_WvT_l);
    launch_tsplit(aW1, Cx, AHx, p_aW1T_h, p_aW1T_l);
    launch_tsplit(kW1, Cx, MRx, p_w1T_h, p_w1T_l);
    launch_tsplit(vW1, Cx, MRx, p_w1T_h + MRx*Cx, p_w1T_l + MRx*Cx);
    launch_tsplit(kW2, MRx, Cx, p_kW2T_h, p_kW2T_l);
    launch_tsplit(vW2, MRx, Cx, p_vW2T_h, p_vW2T_l);
    cudaMemcpyAsync(p_bias1, kb1, MRx*sizeof(float), cudaMemcpyDeviceToDevice);
    cudaMemcpyAsync(p_bias1 + MRx, vb1, MRx*sizeof(float), cudaMemcpyDeviceToDevice);

    // -------- projections (1-pass, BK=32) --------
    // query = x @ Wq -> hi plane
    launch_gemm(1, NROW, Cx, Cx, p_x_h, nullptr, Cx, 0, p_WqT_h, nullptr, Cx, 0,
                p_memf, p_qs_h, nullptr, Cx, 0, nullptr, nullptr, 0, WR_HI, 1);
    // [sk;cbk] = [shm;cat_B] @ Wk -> f32 + hi
    launch_gemm(1, NKB, Cx, Cx, p_skb_in_h, nullptr, Cx, 0, p_WkT_h, nullptr, Cx, 0,
                p_skbf, p_skbh, nullptr, Cx, 0, nullptr, nullptr, 0, WR_F32|WR_HI, 1);
    // [svT|cbvT] = WvT @ [shm;cat_B]^T -> f32 + hi  ([1024][2880])
    launch_gemm(1, Cx, NKB, Cx, p_WvT_h, nullptr, Cx, 0, p_skb_in_h, nullptr, Cx, 0,
                p_svbTf, p_svbTh, nullptr, NKB, 0, nullptr, nullptr, 0, WR_F32|WR_HI, 1);
    // qh = query @ aW1[:Cx] -> f32
    launch_gemm(1, NROW, AHx, Cx, p_qs_h, nullptr, Cx, 0, p_aW1T_h, nullptr, Cx, 0,
                p_qhf, p_kc_h, nullptr, AHx, 0, nullptr, nullptr, 0, WR_F32, 1);

    // per-batch kc / vcT hi planes
    kcvc_k_kernel<<<Bx*NKMAX, 256>>>(catids, cat_A);
    kcvc_v_kernel<<<dim3(Cx, Bx), 320>>>(catids, cat_A);

    // alpha constants
    aconst_kernel<<<NCATx + Sx, AHx>>>(cat_emb, scale_emb, aW1, ab1);

    // -------- logits (1-pass) --------
    launch_gemm(1, NROW, NKMAX, Cx, p_qs_h, nullptr, Cx, 0, p_skbh, nullptr, Cx, 0,
                p_lgsf, p_lgs_h, nullptr, NKMAX, 0, nullptr, nullptr, 0, WR_F32, 1);
    launch_gemm(1, Lx, NKMAX, Cx, p_qs_h, nullptr, Cx, (long long)Lx*Cx,
                p_kc_h, nullptr, Cx, (long long)NKMAX*Cx,
                p_lgcf, p_lgs_h, nullptr, NKMAX, (long long)Lx*NKMAX, nullptr, nullptr, 0, WR_F32, Bx);

    // alpha + masked softmax -> tf32 hi planes (prescaled by (1-a)/a)
    softmax_kernel<<<(NROW + 7)/8, 256>>>(catids, aW2, ab2);

    // -------- PV (1-pass) --------
    launch_gemm(1, NROW, Cx, NKMAX, p_lgs_h, nullptr, NKMAX, 0, p_svbTh, nullptr, NKB, 0,
                p_memf, p_mem_h, nullptr, Cx, 0, nullptr, nullptr, 0, WR_F32, 1);
    launch_gemm(1, Lx, Cx, NKMAX, p_lgc_h, nullptr, NKMAX, (long long)Lx*NKMAX,
                p_vcT_h, nullptr, NKMAX, (long long)Cx*NKMAX,
                p_memf, p_mem_h, p_mem_l, Cx, (long long)Lx*Cx, nullptr, nullptr, 1, WR_SPLIT, Bx);

    // -------- heads (3-pass, BK=16) --------
    launch_gemm(3, NROW, 2*MRx, Cx, p_mem_h, p_mem_l, Cx, 0, p_w1T_h, p_w1T_l, Cx, 0,
                p_memf, p_t1_h, p_t1_l, 2*MRx, 0, p_bias1, nullptr, 0, WR_SPLIT, 1);
    float* outk = (float*)d_out;
    float* outv = (float*)d_out + (size_t)NROW * Cx;
    launch_gemm(3, NROW, Cx, MRx, p_t1_h, p_t1_l, 2*MRx, 0, p_kW2T_h, p_kW2T_l, MRx, 0,
                outk, p_mem_h, nullptr, Cx, 0, kb2, p_scal + 1, 0, WR_F32, 1);
    launch_gemm(3, NROW, Cx, MRx, p_t1_h + MRx, p_t1_l + MRx, 2*MRx, 0, p_vW2T_h, p_vW2T_l, MRx, 0,
                outv, p_mem_h, nullptr, Cx, 0, vb2, p_scal + 2, 0, WR_F32, 1);

    tail_kernel<<<1, 256>>>((float*)d_out, 2 * NROW * Cx, out_size);
}

// round 11
// speedup vs baseline: 1.7392x; 1.7392x over previous
#include <cuda_runtime.h>
#include <math.h>

// ---------------- problem constants ----------------
static constexpr int Bx = 32, Lx = 680, Cx = 1024;
static constexpr int Sx = 10, SLOTSx = 32, Rx = 8, NCATx = 22;
static constexpr int MRx = 64, AHx = 128;
static constexpr int NROW = Bx * Lx;            // 21760
static constexpr int NKMAX = Sx * SLOTSx;       // 320
static constexpr int NQ = NROW * Cx;            // 22282240
static constexpr int NKB = NKMAX + 2560;        // 2880

__constant__ int c_begin[10] = {0,1,5,14,30,55,91,155,255,424};

// ---------------- device scratch ----------------
__device__ unsigned g_x_h[NQ];
__device__ unsigned g_kc2_h[Bx*NKMAX*Cx];          // folded per-batch logit weights
__device__ unsigned g_Wq_rm_h[Cx*Cx];              // Wq row-major hi plane
__device__ unsigned g_FsT_h[NKMAX*Cx];             // (sk @ Wq^T)  [320][1024]
__device__ unsigned g_FaT_h[AHx*Cx];               // (Wq @ aW1)^T [128][1024]
__device__ unsigned g_WkT_h[Cx*Cx], g_WkT_l[Cx*Cx];
__device__ unsigned g_WvT_h[Cx*Cx], g_WvT_l[Cx*Cx];
__device__ unsigned g_aW1T_h[AHx*Cx], g_aW1T_l[AHx*Cx];
__device__ unsigned g_w1T_h[(2*MRx)*Cx], g_w1T_l[(2*MRx)*Cx];
__device__ unsigned g_kW2T_h[Cx*MRx], g_kW2T_l[Cx*MRx];
__device__ unsigned g_vW2T_h[Cx*MRx], g_vW2T_l[Cx*MRx];
__device__ unsigned g_skb_in_h[NKB*Cx];            // [shm ; cat_B] hi plane

__device__ float    g_skbf[NKB*Cx];                // [sk ; cbk] f32
__device__ unsigned g_skbh[NKB*Cx];                // hi
__device__ float    g_svbTf[Cx*NKB];               // [svT | cbvT] f32
__device__ unsigned g_svbTh[Cx*NKB];               // hi
__device__ unsigned g_kc_h[Bx*NKMAX*Cx];
__device__ unsigned g_vcT_h[Bx*Cx*NKMAX];
__device__ float    g_lgsf[NROW*NKMAX], g_lgcf[NROW*NKMAX];
__device__ unsigned g_lgs_h[NROW*NKMAX], g_lgc_h[NROW*NKMAX];
__device__ float    g_qhf[NROW*AHx];
__device__ float    g_memf[NQ];
__device__ unsigned g_mem_h[NQ];
__device__ unsigned g_t1_h[NROW*(2*MRx)];
__device__ float    g_acat[NCATx*AHx];
__device__ float    g_ascale[Sx*AHx];
__device__ float    g_scal[4];
__device__ float    g_bias1[2*MRx];

// ---------------- helpers ----------------
__device__ __forceinline__ void split_tf32(float x, unsigned& hi, unsigned& lo) {
    unsigned h; asm("cvt.rna.tf32.f32 %0, %1;" : "=r"(h) : "f"(x));
    float hf = __uint_as_float(h);
    unsigned l; asm("cvt.rna.tf32.f32 %0, %1;" : "=r"(l) : "f"(x - hf));
    hi = h; lo = l;
}
__device__ __forceinline__ unsigned to_tf32(float x) {
    unsigned h; asm("cvt.rna.tf32.f32 %0, %1;" : "=r"(h) : "f"(x)); return h;
}
__device__ __forceinline__ void mma8(float* d, const unsigned* a, const unsigned* b) {
    asm volatile(
        "mma.sync.aligned.m16n8k8.row.col.f32.tf32.tf32.f32 "
        "{%0,%1,%2,%3}, {%4,%5,%6,%7}, {%8,%9}, {%0,%1,%2,%3};"
        : "+f"(d[0]), "+f"(d[1]), "+f"(d[2]), "+f"(d[3])
        : "r"(a[0]), "r"(a[1]), "r"(a[2]), "r"(a[3]), "r"(b[0]), "r"(b[1]));
}
__device__ __forceinline__ uint4 ldsm4(unsigned a) {
    uint4 r;
    asm volatile("ldmatrix.sync.aligned.m8n8.x4.shared.b16 {%0,%1,%2,%3}, [%4];"
        : "=r"(r.x), "=r"(r.y), "=r"(r.z), "=r"(r.w) : "r"(a));
    return r;
}
__device__ __forceinline__ unsigned smaddr(const void* p) {
    unsigned a;
    asm("{.reg .u64 u; cvta.to.shared.u64 u, %1; cvt.u32.u64 %0, u;}" : "=r"(a) : "l"(p));
    return a;
}
__device__ __forceinline__ void cp16(unsigned dst, const void* src, bool ok) {
    int sz = ok ? 16 : 0;
    asm volatile("cp.async.cg.shared.global [%0], [%1], 16, %2;\n" :: "r"(dst), "l"(src), "r"(sz));
}
__device__ __forceinline__ void cp_commit() { asm volatile("cp.async.commit_group;"); }
template<int N> __device__ __forceinline__ void cp_wait() {
    asm volatile("cp.async.wait_group %0;" :: "n"(N));
}

// ---------------- prep ----------------
__global__ void prep_kernel(const float* gk, const float* gv, const float* lt) {
    float temp = expf(lt[0]);
    temp = fminf(fmaxf(temp, 0.05f), 1.0f);
    g_scal[0] = (1.0f / 32.0f) / temp;
    g_scal[1] = 1.0f / (1.0f + expf(-gk[0]));
    g_scal[2] = 1.0f / (1.0f + expf(-gv[0]));
}

// ---------------- fp32 -> tf32 hi plane ----------------
__global__ void cvt_kernel(const float* __restrict__ in, unsigned* __restrict__ hi, int n4) {
    int i = blockIdx.x * 256 + threadIdx.x;
    if (i >= n4) return;
    float4 v = ((const float4*)in)[i];
    uint4 h;
    h.x = to_tf32(v.x); h.y = to_tf32(v.y); h.z = to_tf32(v.z); h.w = to_tf32(v.w);
    ((uint4*)hi)[i] = h;
}

// ---------------- transpose + split: in [R][C] -> planes [C][R] ----------------
__global__ void tsplit_kernel(const float* __restrict__ in, int R, int C,
                              unsigned* __restrict__ oh, unsigned* __restrict__ ol)
{
    __shared__ float t[32][33];
    int r0 = blockIdx.y * 32, c0 = blockIdx.x * 32;
    int tx = threadIdx.x, ty = threadIdx.y;
    #pragma unroll
    for (int i = 0; i < 32; i += 8) {
        int r = r0 + ty + i;
        t[ty + i][tx] = (r < R && c0 + tx < C) ? in[(size_t)r * C + c0 + tx] : 0.f;
    }
    __syncthreads();
    #pragma unroll
    for (int i = 0; i < 32; i += 8) {
        int c = c0 + ty + i, r = r0 + tx;
        if (c < C && r < R) {
            unsigned h, l; split_tf32(t[tx][ty + i], h, l);
            oh[(size_t)c * R + r] = h;
            ol[(size_t)c * R + r] = l;
        }
    }
}

// ---------------- GEMM ----------------
static constexpr int WR_F32 = 1, WR_HI = 4;

struct GemmArgs {
    int M, N, K;
    const unsigned *Ah, *Al; int lda; long long sA;
    const unsigned *Bh, *Bl; int ldb; long long sB;   // B is [N][K] (NT)
    float* Cf; unsigned *Chi; int ldc; long long sC;
    const float* bias; const float* gate;
    int accum, wr;
};

// BN=128 (2 CTAs/SM). NPASS=1: BK=32, 3-stage ring. NPASS=3: BK=16, 2-stage.
template<int NPASS>
__global__ void __launch_bounds__(256, 2) gemm_tmpl(GemmArgs g)
{
    constexpr int BK  = (NPASS == 3) ? 16 : 32;
    constexpr int AW  = BK + 4;
    constexpr int ASZ = 128 * AW;
    constexpr int NPL = (NPASS == 3) ? 2 : 1;
    constexpr int NSTG = (NPASS == 3) ? 2 : 3;
    constexpr int STG = NPL * 2 * ASZ;
    constexpr int CPT = BK / 8;
    extern __shared__ unsigned sm[];

    const int tid = threadIdx.x, lane = tid & 31, wid = tid >> 5;
    const int wm = wid >> 2, wn = wid & 3, tg = lane & 3, gid = lane >> 2;
    const int bm = blockIdx.y * 128, bn = blockIdx.x * 128;
    const long long z = blockIdx.z;

    const unsigned* Ap[2];
    Ap[0] = g.Ah + z * g.sA;
    Ap[1] = (NPASS == 3) ? g.Al + z * g.sA : Ap[0];
    const unsigned* Bp[2];
    Bp[0] = g.Bh + z * g.sB;
    Bp[1] = (NPASS == 3) ? g.Bl + z * g.sB : Bp[0];

    const unsigned smbase = smaddr(sm);

    const int am = lane >> 3;
    const int a_row = (am & 1) * 8 + (lane & 7);
    const int a_kw  = (am >> 1) * 4;
    const int b_row = (am >> 1) * 8 + (lane & 7);
    const int b_kw  = (am & 1) * 4;
    unsigned aA[4], bA[2];
    #pragma unroll
    for (int mt = 0; mt < 4; mt++)
        aA[mt] = smbase + (unsigned)((wm*64 + mt*16 + a_row) * AW + a_kw) * 4u;
    #pragma unroll
    for (int pr = 0; pr < 2; pr++)
        bA[pr] = smbase + (unsigned)(NPL * ASZ) * 4u
               + (unsigned)((wn*32 + pr*16 + b_row) * AW + b_kw) * 4u;

    float acc[4][4][4];
    #pragma unroll
    for (int mt = 0; mt < 4; mt++)
        #pragma unroll
        for (int nt = 0; nt < 4; nt++)
            #pragma unroll
            for (int u = 0; u < 4; u++) acc[mt][nt][u] = 0.f;

    auto load_stage = [&](int s, int k0) {
        unsigned base = smbase + (unsigned)(s * STG) * 4u;
        #pragma unroll
        for (int p = 0; p < NPL; p++)
            #pragma unroll
            for (int j = 0; j < CPT; j++) {
                int c = tid + j * 256;
                int row = c / (BK/4), kc = (c % (BK/4)) * 4;
                bool ok = (bm + row) < g.M;
                const unsigned* src = ok ? Ap[p] + (size_t)(bm + row) * g.lda + k0 + kc : Ap[p];
                cp16(base + (unsigned)(p * ASZ + row * AW + kc) * 4u, src, ok);
            }
        unsigned bbase = base + (unsigned)(NPL * ASZ) * 4u;
        #pragma unroll
        for (int p = 0; p < NPL; p++)
            #pragma unroll
            for (int j = 0; j < CPT; j++) {
                int c = tid + j * 256;
                int row = c / (BK/4), kc = (c % (BK/4)) * 4;
                bool ok = (bn + row) < g.N;
                const unsigned* src = ok ? Bp[p] + (size_t)(bn + row) * g.ldb + k0 + kc : Bp[p];
                cp16(bbase + (unsigned)(p * ASZ + row * AW + kc) * 4u, src, ok);
            }
    };

    auto compute = [&](int s) {
        const unsigned so = (unsigned)(s * STG) * 4u;
        #pragma unroll
        for (int kk = 0; kk < BK; kk += 8) {
            const unsigned kb = so + (unsigned)kk * 4u;
            unsigned bh[4][2], bl[4][2];
            #pragma unroll
            for (int pr = 0; pr < 2; pr++) {
                uint4 r = ldsm4(bA[pr] + kb);
                bh[pr*2+0][0] = r.x; bh[pr*2+0][1] = r.y;
                bh[pr*2+1][0] = r.z; bh[pr*2+1][1] = r.w;
                if (NPASS == 3) {
                    uint4 q = ldsm4(bA[pr] + kb + (unsigned)ASZ * 4u);
                    bl[pr*2+0][0] = q.x; bl[pr*2+0][1] = q.y;
                    bl[pr*2+1][0] = q.z; bl[pr*2+1][1] = q.w;
                }
            }
            #pragma unroll
            for (int mt = 0; mt < 4; mt++) {
                uint4 ah4 = ldsm4(aA[mt] + kb);
                uint4 al4 = make_uint4(0,0,0,0);
                if (NPASS == 3) al4 = ldsm4(aA[mt] + kb + (unsigned)ASZ * 4u);
                #pragma unroll
                for (int nt = 0; nt < 4; nt++) {
                    mma8(acc[mt][nt], (const unsigned*)&ah4, bh[nt]);
                    if (NPASS == 3) {
                        mma8(acc[mt][nt], (const unsigned*)&ah4, bl[nt]);
                        mma8(acc[mt][nt], (const unsigned*)&al4, bh[nt]);
                    }
                }
            }
        }
    };

    const int nK = g.K / BK;
    if (NSTG == 3) {
        load_stage(0, 0);
        cp_commit();
        if (nK > 1) load_stage(1, BK);
        cp_commit();
        for (int kt = 0; kt < nK; kt++) {
            cp_wait<1>();
            __syncthreads();
            if (kt + 2 < nK) load_stage((kt + 2) % 3, (kt + 2) * BK);
            cp_commit();
            compute(kt % 3);
        }
    } else {
        load_stage(0, 0);
        cp_commit();
        for (int kt = 0; kt < nK; kt++) {
            if (kt + 1 < nK) {
                load_stage((kt + 1) & 1, (kt + 1) * BK);
                cp_commit();
                cp_wait<1>();
            } else {
                cp_wait<0>();
            }
            __syncthreads();
            compute(kt & 1);
            __syncthreads();
        }
    }

    // ---------------- epilogue ----------------
    const float gt = g.gate ? *g.gate : 1.0f;
    float* Cf = g.Cf + z * g.sC;
    unsigned* Chi = g.Chi + z * g.sC;
    #pragma unroll
    for (int mt = 0; mt < 4; mt++) {
        int r0 = bm + wm * 64 + mt * 16 + gid;
        int r1 = r0 + 8;
        #pragma unroll
        for (int nt = 0; nt < 4; nt++) {
            int col = bn + wn * 32 + nt * 8 + 2 * tg;
            if (col >= g.N) continue;
            float b0 = g.bias ? g.bias[col]     : 0.f;
            float b1 = g.bias ? g.bias[col + 1] : 0.f;
            #pragma unroll
            for (int half = 0; half < 2; half++) {
                int r = half ? r1 : r0;
                if (r >= g.M) continue;
                size_t o = (size_t)r * g.ldc + col;
                float v0 = gt * (acc[mt][nt][half*2+0] + b0);
                float v1 = gt * (acc[mt][nt][half*2+1] + b1);
                if (g.accum) { v0 += Cf[o]; v1 += Cf[o+1]; }
                if (g.wr & WR_F32) *(float2*)(Cf + o) = make_float2(v0, v1);
                if (g.wr & WR_HI) { Chi[o] = to_tf32(v0); Chi[o+1] = to_tf32(v1); }
            }
        }
    }
}

// ---------------- kc (hi plane): kc = sk + sum_r a_r * cbk_r ----------------
__global__ void __launch_bounds__(256) kcvc_k_kernel(const int* __restrict__ catids,
                                                     const float* __restrict__ cat_A)
{
    int blk = blockIdx.x;
    int b = blk / 320, key = blk % 320;
    int v = key >> 5, s = key & 31;
    int cid = catids[b]; if (cid < 0) cid = 0;
    float a[Rx];
    #pragma unroll
    for (int r = 0; r < Rx; r++) a[r] = cat_A[(cid*Sx + v)*Rx + r];
    int c = threadIdx.x * 4;
    float4 ka = *(const float4*)(g_skbf + (size_t)key*Cx + c);
    #pragma unroll
    for (int r = 0; r < Rx; r++) {
        size_t idx = ((size_t)(NKMAX + (v*Rx + r)*SLOTSx + s))*Cx + c;
        float4 kb = *(const float4*)(g_skbf + idx);
        ka.x += a[r]*kb.x; ka.y += a[r]*kb.y; ka.z += a[r]*kb.z; ka.w += a[r]*kb.w;
    }
    size_t o = ((size_t)(b*320 + key))*Cx + c;
    uint4 h;
    h.x = to_tf32(ka.x); h.y = to_tf32(ka.y); h.z = to_tf32(ka.z); h.w = to_tf32(ka.w);
    *(uint4*)(g_kc_h + o) = h;
}

// ---------------- vcT (hi plane) ----------------
__global__ void __launch_bounds__(320) kcvc_v_kernel(const int* __restrict__ catids,
                                                     const float* __restrict__ cat_A)
{
    int c = blockIdx.x, b = blockIdx.y;
    int key = threadIdx.x;
    int cid = catids[b]; if (cid < 0) cid = 0;
    int v = key >> 5, s = key & 31;
    const float* ar = cat_A + (cid*Sx + v)*Rx;
    float acc = g_svbTf[(size_t)c*NKB + key];
    #pragma unroll
    for (int r = 0; r < Rx; r++)
        acc += ar[r] * g_svbTf[(size_t)c*NKB + NKMAX + (v*Rx + r)*SLOTSx + s];
    g_vcT_h[((size_t)b*Cx + c)*NKMAX + key] = to_tf32(acc);
}

// ---------------- alpha constant tables ----------------
__global__ void aconst_kernel(const float* __restrict__ cat_emb,
                              const float* __restrict__ scale_emb,
                              const float* __restrict__ aW1,
                              const float* __restrict__ ab1)
{
    int idx = blockIdx.x, h = threadIdx.x;
    if (idx < NCATx) {
        float acc = 0.f;
        const float* ce = cat_emb + (size_t)idx * Cx;
        for (int c = 0; c < Cx; c++)
            acc += ce[c] * aW1[(size_t)(Cx + c)*AHx + h];
        g_acat[idx*AHx + h] = acc;
    } else {
        int i = idx - NCATx;
        float acc = ab1[h];
        const float* se = scale_emb + (size_t)i * Cx;
        for (int c = 0; c < Cx; c++)
            acc += se[c] * aW1[(size_t)(2*Cx + c)*AHx + h];
        g_ascale[i*AHx + h] = acc;
    }
}

// ---------------- alpha + masked softmax + prescale -> tf32 hi planes ----------------
__global__ void __launch_bounds__(256) softmax_kernel(const int* __restrict__ catids,
                                                      const float* __restrict__ aW2,
                                                      const float* __restrict__ ab2)
{
    int w = threadIdx.x >> 5, lane = threadIdx.x & 31;
    int row = blockIdx.x * 8 + w;
    if (row >= NROW) return;
    int b = row / Lx, l = row % Lx;
    int i = 0;
    #pragma unroll
    for (int u = 1; u < 10; u++) if (l >= c_begin[u]) i = u;
    int nk = (i + 1) * SLOTSx;
    float ls = g_scal[0];

    int cid = catids[b];
    float a = 0.f;
    if (cid >= 0) {
        const float* qhp = g_qhf + (size_t)row*AHx;
        const float* ac  = g_acat + cid*AHx;
        const float* as  = g_ascale + i*AHx;
        float acc = 0.f;
        #pragma unroll
        for (int h = lane; h < AHx; h += 32) {
            float xv = qhp[h] + ac[h] + as[h];
            float ge = 0.5f*xv*(1.0f + erff(xv*0.70710678118654752f));
            acc += ge * aW2[h];
        }
        #pragma unroll
        for (int o = 16; o > 0; o >>= 1) acc += __shfl_xor_sync(0xffffffffu, acc, o);
        a = 1.0f/(1.0f + expf(-(acc + ab2[0])));
    }

    #pragma unroll
    for (int s = 0; s < 2; s++) {
        const float* p = (s ? g_lgcf : g_lgsf) + (size_t)row * NKMAX;
        unsigned* q = (s ? g_lgc_h : g_lgs_h) + (size_t)row * NKMAX;
        float wgt = s ? a : (1.0f - a);
        float v[10];
        int cnt = 0;
        float mx = -3.4e38f;
        for (int j = lane; j < nk; j += 32) { float t = p[j]*ls; v[cnt++] = t; mx = fmaxf(mx, t); }
        #pragma unroll
        for (int o = 16; o > 0; o >>= 1) mx = fmaxf(mx, __shfl_xor_sync(0xffffffffu, mx, o));
        float sum = 0.f;
        for (int c2 = 0; c2 < cnt; c2++) { v[c2] = expf(v[c2] - mx); sum += v[c2]; }
        #pragma unroll
        for (int o = 16; o > 0; o >>= 1) sum += __shfl_xor_sync(0xffffffffu, sum, o);
        float inv = wgt / sum;
        cnt = 0;
        for (int j = lane; j < NKMAX; j += 32)
            q[j] = (j < nk) ? to_tf32(v[cnt++] * inv) : 0u;
    }
}

// ---------------- tail ----------------
__global__ void tail_kernel(float* out, int n2, int total) {
    int idx = n2 + blockIdx.x*blockDim.x + threadIdx.x;
    if (idx < total) out[idx] = 0.f;
}

// ---------------- host helpers ----------------
static void launch_gemm(int npass, int M, int N, int K,
                        const unsigned* Ah, const unsigned* Al, int lda, long long sA,
                        const unsigned* Bh, const unsigned* Bl, int ldb, long long sB,
                        float* Cf, unsigned* Chi, int ldc, long long sC,
                        const float* bias, const float* gate,
                        int accum, int wr, int batches)
{
    GemmArgs g;
    g.M=M; g.N=N; g.K=K;
    g.Ah=Ah; g.Al=Al; g.lda=lda; g.sA=sA;
    g.Bh=Bh; g.Bl=Bl; g.ldb=ldb; g.sB=sB;
    g.Cf=Cf; g.Chi=Chi; g.ldc=ldc; g.sC=sC;
    g.bias=bias; g.gate=gate; g.accum=accum; g.wr=wr;
    dim3 grid((N + 127)/128, (M + 127)/128, batches);
    if (npass == 3) gemm_tmpl<3><<<grid, 256, 81920>>>(g);
    else            gemm_tmpl<1><<<grid, 256, 110592>>>(g);
}

static void launch_tsplit(const float* in, int R, int C, unsigned* oh, unsigned* ol)
{
    dim3 grid((C + 31)/32, (R + 31)/32);
    tsplit_kernel<<<grid, dim3(32, 8)>>>(in, R, C, oh, ol);
}

// ---------------- launch ----------------
extern "C" void kernel_launch(void* const* d_in, const int* in_sizes, int n_in,
                              void* d_out, int out_size) {
    const float* x        = (const float*)d_in[0];
    const int*   catids   = (const int*)  d_in[1];
    const float* shmem    = (const float*)d_in[2];
    const float* cat_A    = (const float*)d_in[3];
    const float* cat_B    = (const float*)d_in[4];
    const float* cat_emb  = (const float*)d_in[5];
    const float* scale_emb= (const float*)d_in[6];
    const float* Wq       = (const float*)d_in[7];
    const float* Wk       = (const float*)d_in[8];
    const float* Wv       = (const float*)d_in[9];
    const float* aW1      = (const float*)d_in[10];
    const float* ab1      = (const float*)d_in[11];
    const float* aW2      = (const float*)d_in[12];
    const float* ab2      = (const float*)d_in[13];
    const float* kW1      = (const float*)d_in[14];
    const float* kb1      = (const float*)d_in[15];
    const float* kW2      = (const float*)d_in[16];
    const float* kb2      = (const float*)d_in[17];
    const float* vW1      = (const float*)d_in[18];
    const float* vb1      = (const float*)d_in[19];
    const float* vW2      = (const float*)d_in[20];
    const float* vb2      = (const float*)d_in[21];
    const float* gk       = (const float*)d_in[22];
    const float* gv       = (const float*)d_in[23];
    const float* lt       = (const float*)d_in[24];

    cudaFuncSetAttribute(gemm_tmpl<3>, cudaFuncAttributeMaxDynamicSharedMemorySize, 81920);
    cudaFuncSetAttribute(gemm_tmpl<1>, cudaFuncAttributeMaxDynamicSharedMemorySize, 110592);

    #define SYM(t, p, s) t p; cudaGetSymbolAddress((void**)&p, s)
    SYM(unsigned*, p_x_h, g_x_h);
    SYM(unsigned*, p_kc2_h, g_kc2_h);
    SYM(unsigned*, p_Wq_rm_h, g_Wq_rm_h);
    SYM(unsigned*, p_FsT_h, g_FsT_h);
    SYM(unsigned*, p_FaT_h, g_FaT_h);
    SYM(unsigned*, p_WkT_h, g_WkT_h); SYM(unsigned*, p_WkT_l, g_WkT_l);
    SYM(unsigned*, p_WvT_h, g_WvT_h); SYM(unsigned*, p_WvT_l, g_WvT_l);
    SYM(unsigned*, p_aW1T_h, g_aW1T_h); SYM(unsigned*, p_aW1T_l, g_aW1T_l);
    SYM(unsigned*, p_w1T_h, g_w1T_h); SYM(unsigned*, p_w1T_l, g_w1T_l);
    SYM(unsigned*, p_kW2T_h, g_kW2T_h); SYM(unsigned*, p_kW2T_l, g_kW2T_l);
    SYM(unsigned*, p_vW2T_h, g_vW2T_h); SYM(unsigned*, p_vW2T_l, g_vW2T_l);
    SYM(unsigned*, p_skb_in_h, g_skb_in_h);
    SYM(float*,    p_skbf, g_skbf);
    SYM(unsigned*, p_skbh, g_skbh);
    SYM(float*,    p_svbTf, g_svbTf);
    SYM(unsigned*, p_svbTh, g_svbTh);
    SYM(unsigned*, p_kc_h, g_kc_h);
    SYM(unsigned*, p_vcT_h, g_vcT_h);
    SYM(float*,    p_lgsf, g_lgsf);   SYM(float*,    p_lgcf, g_lgcf);
    SYM(unsigned*, p_lgs_h, g_lgs_h); SYM(unsigned*, p_lgc_h, g_lgc_h);
    SYM(float*,    p_qhf, g_qhf);
    SYM(float*,    p_memf, g_memf);
    SYM(unsigned*, p_mem_h, g_mem_h);
    SYM(unsigned*, p_t1_h, g_t1_h);
    SYM(float*,    p_scal, g_scal);
    SYM(float*,    p_bias1, g_bias1);
    #undef SYM

    prep_kernel<<<1, 1>>>(gk, gv, lt);

    // -------- operand preparation --------
    cvt_kernel<<<(NQ/4 + 255)/256, 256>>>(x, p_x_h, NQ/4);
    cvt_kernel<<<(NKMAX*Cx/4 + 255)/256, 256>>>(shmem, p_skb_in_h, NKMAX*Cx/4);
    cvt_kernel<<<(2560*Cx/4 + 255)/256, 256>>>(cat_B, p_skb_in_h + NKMAX*Cx, 2560*Cx/4);
    cvt_kernel<<<(Cx*Cx/4 + 255)/256, 256>>>(Wq, p_Wq_rm_h, Cx*Cx/4);
    launch_tsplit(Wk, Cx, Cx, p_WkT_h, p_WkT_l);
    launch_tsplit(Wv, Cx, Cx, p_WvT_h, p_WvT_l);
    launch_tsplit(aW1, Cx, AHx, p_aW1T_h, p_aW1T_l);
    launch_tsplit(kW1, Cx, MRx, p_w1T_h, p_w1T_l);
    launch_tsplit(vW1, Cx, MRx, p_w1T_h + MRx*Cx, p_w1T_l + MRx*Cx);
    launch_tsplit(kW2, MRx, Cx, p_kW2T_h, p_kW2T_l);
    launch_tsplit(vW2, MRx, Cx, p_vW2T_h, p_vW2T_l);
    cudaMemcpyAsync(p_bias1, kb1, MRx*sizeof(float), cudaMemcpyDeviceToDevice);
    cudaMemcpyAsync(p_bias1 + MRx, vb1, MRx*sizeof(float), cudaMemcpyDeviceToDevice);

    // -------- projections (1-pass, BK=32) --------
    // [sk;cbk] = [shm;cat_B] @ Wk
    launch_gemm(1, NKB, Cx, Cx, p_skb_in_h, nullptr, Cx, 0, p_WkT_h, nullptr, Cx, 0,
                p_skbf, p_skbh, Cx, 0, nullptr, nullptr, 0, WR_F32|WR_HI, 1);
    // [svT|cbvT] = WvT @ [shm;cat_B]^T
    launch_gemm(1, Cx, NKB, Cx, p_WvT_h, nullptr, Cx, 0, p_skb_in_h, nullptr, Cx, 0,
                p_svbTf, p_svbTh, NKB, 0, nullptr, nullptr, 0, WR_F32|WR_HI, 1);
    // FsT[j][c] = sum_d sk[j][d] Wq[c][d]
    launch_gemm(1, NKMAX, Cx, Cx, p_skbh, nullptr, Cx, 0, p_Wq_rm_h, nullptr, Cx, 0,
                p_memf, p_FsT_h, Cx, 0, nullptr, nullptr, 0, WR_HI, 1);
    // FaT[h][c] = sum_d aW1[d][h] Wq[c][d]
    launch_gemm(1, AHx, Cx, Cx, p_aW1T_h, nullptr, Cx, 0, p_Wq_rm_h, nullptr, Cx, 0,
                p_memf, p_FaT_h, Cx, 0, nullptr, nullptr, 0, WR_HI, 1);
    // qh = x @ FaT^T
    launch_gemm(1, NROW, AHx, Cx, p_x_h, nullptr, Cx, 0, p_FaT_h, nullptr, Cx, 0,
                p_qhf, p_kc_h, AHx, 0, nullptr, nullptr, 0, WR_F32, 1);

    // per-batch kc / vcT hi planes
    kcvc_k_kernel<<<Bx*NKMAX, 256>>>(catids, cat_A);
    kcvc_v_kernel<<<dim3(Cx, Bx), 320>>>(catids, cat_A);

    // kc2[b][j][c] = sum_d kc[b][j][d] Wq[c][d]   (batched fold)
    launch_gemm(1, NKMAX, Cx, Cx, p_kc_h, nullptr, Cx, (long long)NKMAX*Cx,
                p_Wq_rm_h, nullptr, Cx, 0,
                p_memf, p_kc2_h, Cx, (long long)NKMAX*Cx, nullptr, nullptr, 0, WR_HI, Bx);

    // alpha constants
    aconst_kernel<<<NCATx + Sx, AHx>>>(cat_emb, scale_emb, aW1, ab1);

    // -------- logits directly from x --------
    launch_gemm(1, NROW, NKMAX, Cx, p_x_h, nullptr, Cx, 0, p_FsT_h, nullptr, Cx, 0,
                p_lgsf, p_lgs_h, NKMAX, 0, nullptr, nullptr, 0, WR_F32, 1);
    launch_gemm(1, Lx, NKMAX, Cx, p_x_h, nullptr, Cx, (long long)Lx*Cx,
                p_kc2_h, nullptr, Cx, (long long)NKMAX*Cx,
                p_lgcf, p_lgs_h, NKMAX, (long long)Lx*NKMAX, nullptr, nullptr, 0, WR_F32, Bx);

    // alpha + masked softmax -> tf32 hi planes (prescaled by (1-a)/a)
    softmax_kernel<<<(NROW + 7)/8, 256>>>(catids, aW2, ab2);

    // -------- PV (1-pass) --------
    launch_gemm(1, NROW, Cx, NKMAX, p_lgs_h, nullptr, NKMAX, 0, p_svbTh, nullptr, NKB, 0,
                p_memf, p_mem_h, Cx, 0, nullptr, nullptr, 0, WR_F32, 1);
    launch_gemm(1, Lx, Cx, NKMAX, p_lgc_h, nullptr, NKMAX, (long long)Lx*NKMAX,
                p_vcT_h, nullptr, NKMAX, (long long)Cx*NKMAX,
                p_memf, p_mem_h, Cx, (long long)Lx*Cx, nullptr, nullptr, 1, WR_HI, Bx);

    // -------- heads (1-pass) --------
    launch_gemm(1, NROW, 2*MRx, Cx, p_mem_h, nullptr, Cx, 0, p_w1T_h, nullptr, Cx, 0,
                p_memf, p_t1_h, 2*MRx, 0, p_bias1, nullptr, 0, WR_HI, 1);
    float* outk = (float*)d_out;
    float* outv = (float*)d_out + (size_t)NROW * Cx;
    launch_gemm(1, NROW, Cx, MRx, p_t1_h, nullptr, 2*MRx, 0, p_kW2T_h, nullptr, MRx, 0,
                outk, p_mem_h, Cx, 0, kb2, p_scal + 1, 0, WR_F32, 1);
    launch_gemm(1, NROW, Cx, MRx, p_t1_h + MRx, nullptr, 2*MRx, 0, p_vW2T_h, nullptr, MRx, 0,
                outv, p_mem_h, Cx, 0, vb2, p_scal + 2, 0, WR_F32, 1);

    tail_kernel<<<1, 256>>>((float*)d_out, 2 * NROW * Cx, out_size);
}

// round 13
// speedup vs baseline: 1.9627x; 1.1285x over previous
#include <cuda_runtime.h>
#include <math.h>

// ---------------- problem constants ----------------
static constexpr int Bx = 32, Lx = 680, Cx = 1024;
static constexpr int Sx = 10, SLOTSx = 32, Rx = 8, NCATx = 22;
static constexpr int MRx = 64, AHx = 128;
static constexpr int NROW = Bx * Lx;            // 21760
static constexpr int NKMAX = Sx * SLOTSx;       // 320
static constexpr int NQ = NROW * Cx;            // 22282240
static constexpr int NKB = NKMAX + 2560;        // 2880

__constant__ int c_begin[10] = {0,1,5,14,30,55,91,155,255,424};

// ---------------- device scratch ----------------
__device__ unsigned g_x_h[NQ];
__device__ unsigned g_kc2_h[Bx*NKMAX*Cx];          // folded per-batch logit weights
__device__ unsigned g_Wq_rm_h[Cx*Cx];              // Wq row-major hi plane
__device__ unsigned g_FaT_h[AHx*Cx];               // (Wq @ aW1)^T [128][1024]
__device__ unsigned g_WkT_h[Cx*Cx], g_WkT_l[Cx*Cx];
__device__ unsigned g_WvT_h[Cx*Cx], g_WvT_l[Cx*Cx];
__device__ unsigned g_aW1T_h[AHx*Cx], g_aW1T_l[AHx*Cx];
__device__ unsigned g_w1T_h[(2*MRx)*Cx], g_w1T_l[(2*MRx)*Cx];
__device__ unsigned g_kW2T_h[Cx*MRx], g_kW2T_l[Cx*MRx];
__device__ unsigned g_vW2T_h[Cx*MRx], g_vW2T_l[Cx*MRx];
__device__ unsigned g_skb_in_h[NKB*Cx];            // [shm ; cat_B] hi plane

__device__ unsigned g_skbh[NKB*Cx];                // [sk ; cbk] hi
__device__ float    g_skb2f[NKB*Cx];               // [sk;cbk] @ Wq^T  f32
__device__ unsigned g_skb2h[NKB*Cx];               // hi (rows 0..319 = FsT)
__device__ float    g_svbTf[Cx*NKB];               // [svT | cbvT] f32
__device__ unsigned g_svbTh[Cx*NKB];               // hi
__device__ unsigned g_vcT_h[Bx*Cx*NKMAX];
__device__ float    g_lgsf[NROW*NKMAX], g_lgcf[NROW*NKMAX];
__device__ unsigned g_lgs_h[NROW*NKMAX], g_lgc_h[NROW*NKMAX];
__device__ float    g_qhf[NROW*AHx];
__device__ float    g_memf[NQ];
__device__ unsigned g_mem_h[NQ];
__device__ unsigned g_t1_h[NROW*(2*MRx)];
__device__ float    g_acat[NCATx*AHx];
__device__ float    g_ascale[Sx*AHx];
__device__ float    g_scal[4];
__device__ float    g_bias1[2*MRx];

// ---------------- helpers ----------------
__device__ __forceinline__ void split_tf32(float x, unsigned& hi, unsigned& lo) {
    unsigned h; asm("cvt.rna.tf32.f32 %0, %1;" : "=r"(h) : "f"(x));
    float hf = __uint_as_float(h);
    unsigned l; asm("cvt.rna.tf32.f32 %0, %1;" : "=r"(l) : "f"(x - hf));
    hi = h; lo = l;
}
__device__ __forceinline__ unsigned to_tf32(float x) {
    unsigned h; asm("cvt.rna.tf32.f32 %0, %1;" : "=r"(h) : "f"(x)); return h;
}
__device__ __forceinline__ void mma8(float* d, const unsigned* a, const unsigned* b) {
    asm volatile(
        "mma.sync.aligned.m16n8k8.row.col.f32.tf32.tf32.f32 "
        "{%0,%1,%2,%3}, {%4,%5,%6,%7}, {%8,%9}, {%0,%1,%2,%3};"
        : "+f"(d[0]), "+f"(d[1]), "+f"(d[2]), "+f"(d[3])
        : "r"(a[0]), "r"(a[1]), "r"(a[2]), "r"(a[3]), "r"(b[0]), "r"(b[1]));
}
__device__ __forceinline__ uint4 ldsm4(unsigned a) {
    uint4 r;
    asm volatile("ldmatrix.sync.aligned.m8n8.x4.shared.b16 {%0,%1,%2,%3}, [%4];"
        : "=r"(r.x), "=r"(r.y), "=r"(r.z), "=r"(r.w) : "r"(a));
    return r;
}
__device__ __forceinline__ unsigned smaddr(const void* p) {
    unsigned a;
    asm("{.reg .u64 u; cvta.to.shared.u64 u, %1; cvt.u32.u64 %0, u;}" : "=r"(a) : "l"(p));
    return a;
}
__device__ __forceinline__ void cp16(unsigned dst, const void* src, bool ok) {
    int sz = ok ? 16 : 0;
    asm volatile("cp.async.cg.shared.global [%0], [%1], 16, %2;\n" :: "r"(dst), "l"(src), "r"(sz));
}
__device__ __forceinline__ void cp_commit() { asm volatile("cp.async.commit_group;"); }
template<int N> __device__ __forceinline__ void cp_wait() {
    asm volatile("cp.async.wait_group %0;" :: "n"(N));
}

// ---------------- prep ----------------
__global__ void prep_kernel(const float* gk, const float* gv, const float* lt) {
    float temp = expf(lt[0]);
    temp = fminf(fmaxf(temp, 0.05f), 1.0f);
    g_scal[0] = (1.0f / 32.0f) / temp;
    g_scal[1] = 1.0f / (1.0f + expf(-gk[0]));
    g_scal[2] = 1.0f / (1.0f + expf(-gv[0]));
}

// ---------------- fp32 -> tf32 hi plane ----------------
__global__ void cvt_kernel(const float* __restrict__ in, unsigned* __restrict__ hi, int n4) {
    int i = blockIdx.x * 256 + threadIdx.x;
    if (i >= n4) return;
    float4 v = ((const float4*)in)[i];
    uint4 h;
    h.x = to_tf32(v.x); h.y = to_tf32(v.y); h.z = to_tf32(v.z); h.w = to_tf32(v.w);
    ((uint4*)hi)[i] = h;
}

// ---------------- transpose + split: in [R][C] -> planes [C][R] ----------------
__global__ void tsplit_kernel(const float* __restrict__ in, int R, int C,
                              unsigned* __restrict__ oh, unsigned* __restrict__ ol)
{
    __shared__ float t[32][33];
    int r0 = blockIdx.y * 32, c0 = blockIdx.x * 32;
    int tx = threadIdx.x, ty = threadIdx.y;
    #pragma unroll
    for (int i = 0; i < 32; i += 8) {
        int r = r0 + ty + i;
        t[ty + i][tx] = (r < R && c0 + tx < C) ? in[(size_t)r * C + c0 + tx] : 0.f;
    }
    __syncthreads();
    #pragma unroll
    for (int i = 0; i < 32; i += 8) {
        int c = c0 + ty + i, r = r0 + tx;
        if (c < C && r < R) {
            unsigned h, l; split_tf32(t[tx][ty + i], h, l);
            oh[(size_t)c * R + r] = h;
            ol[(size_t)c * R + r] = l;
        }
    }
}

// ---------------- GEMM ----------------
static constexpr int WR_F32 = 1, WR_HI = 4;

struct GemmArgs {
    int M, N, K;
    const unsigned *Ah, *Al; int lda; long long sA;
    const unsigned *Bh, *Bl; int ldb; long long sB;   // B is [N][K] (NT)
    float* Cf; unsigned *Chi; int ldc; long long sC;
    const float* bias; const float* gate;
    int accum, wr;
};

// BN=128 (2 CTAs/SM). NPASS=1: BK=32, 3-stage ring. NPASS=3: BK=16, 2-stage.
template<int NPASS>
__global__ void __launch_bounds__(256, 2) gemm_tmpl(GemmArgs g)
{
    constexpr int BK  = (NPASS == 3) ? 16 : 32;
    constexpr int AW  = BK + 4;
    constexpr int ASZ = 128 * AW;
    constexpr int NPL = (NPASS == 3) ? 2 : 1;
    constexpr int NSTG = (NPASS == 3) ? 2 : 3;
    constexpr int STG = NPL * 2 * ASZ;
    constexpr int CPT = BK / 8;
    extern __shared__ unsigned sm[];

    const int tid = threadIdx.x, lane = tid & 31, wid = tid >> 5;
    const int wm = wid >> 2, wn = wid & 3, tg = lane & 3, gid = lane >> 2;
    const int bm = blockIdx.y * 128, bn = blockIdx.x * 128;
    const long long z = blockIdx.z;

    const unsigned* Ap[2];
    Ap[0] = g.Ah + z * g.sA;
    Ap[1] = (NPASS == 3) ? g.Al + z * g.sA : Ap[0];
    const unsigned* Bp[2];
    Bp[0] = g.Bh + z * g.sB;
    Bp[1] = (NPASS == 3) ? g.Bl + z * g.sB : Bp[0];

    const unsigned smbase = smaddr(sm);

    const int am = lane >> 3;
    const int a_row = (am & 1) * 8 + (lane & 7);
    const int a_kw  = (am >> 1) * 4;
    const int b_row = (am >> 1) * 8 + (lane & 7);
    const int b_kw  = (am & 1) * 4;
    unsigned aA[4], bA[2];
    #pragma unroll
    for (int mt = 0; mt < 4; mt++)
        aA[mt] = smbase + (unsigned)((wm*64 + mt*16 + a_row) * AW + a_kw) * 4u;
    #pragma unroll
    for (int pr = 0; pr < 2; pr++)
        bA[pr] = smbase + (unsigned)(NPL * ASZ) * 4u
               + (unsigned)((wn*32 + pr*16 + b_row) * AW + b_kw) * 4u;

    float acc[4][4][4];
    #pragma unroll
    for (int mt = 0; mt < 4; mt++)
        #pragma unroll
        for (int nt = 0; nt < 4; nt++)
            #pragma unroll
            for (int u = 0; u < 4; u++) acc[mt][nt][u] = 0.f;

    auto load_stage = [&](int s, int k0) {
        unsigned base = smbase + (unsigned)(s * STG) * 4u;
        #pragma unroll
        for (int p = 0; p < NPL; p++)
            #pragma unroll
            for (int j = 0; j < CPT; j++) {
                int c = tid + j * 256;
                int row = c / (BK/4), kc = (c % (BK/4)) * 4;
                bool ok = (bm + row) < g.M;
                const unsigned* src = ok ? Ap[p] + (size_t)(bm + row) * g.lda + k0 + kc : Ap[p];
                cp16(base + (unsigned)(p * ASZ + row * AW + kc) * 4u, src, ok);
            }
        unsigned bbase = base + (unsigned)(NPL * ASZ) * 4u;
        #pragma unroll
        for (int p = 0; p < NPL; p++)
            #pragma unroll
            for (int j = 0; j < CPT; j++) {
                int c = tid + j * 256;
                int row = c / (BK/4), kc = (c % (BK/4)) * 4;
                bool ok = (bn + row) < g.N;
                const unsigned* src = ok ? Bp[p] + (size_t)(bn + row) * g.ldb + k0 + kc : Bp[p];
                cp16(bbase + (unsigned)(p * ASZ + row * AW + kc) * 4u, src, ok);
            }
    };

    auto compute = [&](int s) {
        const unsigned so = (unsigned)(s * STG) * 4u;
        #pragma unroll
        for (int kk = 0; kk < BK; kk += 8) {
            const unsigned kb = so + (unsigned)kk * 4u;
            unsigned bh[4][2], bl[4][2];
            #pragma unroll
            for (int pr = 0; pr < 2; pr++) {
                uint4 r = ldsm4(bA[pr] + kb);
                bh[pr*2+0][0] = r.x; bh[pr*2+0][1] = r.y;
                bh[pr*2+1][0] = r.z; bh[pr*2+1][1] = r.w;
                if (NPASS == 3) {
                    uint4 q = ldsm4(bA[pr] + kb + (unsigned)ASZ * 4u);
                    bl[pr*2+0][0] = q.x; bl[pr*2+0][1] = q.y;
                    bl[pr*2+1][0] = q.z; bl[pr*2+1][1] = q.w;
                }
            }
            #pragma unroll
            for (int mt = 0; mt < 4; mt++) {
                uint4 ah4 = ldsm4(aA[mt] + kb);
                uint4 al4 = make_uint4(0,0,0,0);
                if (NPASS == 3) al4 = ldsm4(aA[mt] + kb + (unsigned)ASZ * 4u);
                #pragma unroll
                for (int nt = 0; nt < 4; nt++) {
                    mma8(acc[mt][nt], (const unsigned*)&ah4, bh[nt]);
                    if (NPASS == 3) {
                        mma8(acc[mt][nt], (const unsigned*)&ah4, bl[nt]);
                        mma8(acc[mt][nt], (const unsigned*)&al4, bh[nt]);
                    }
                }
            }
        }
    };

    const int nK = g.K / BK;
    if (NSTG == 3) {
        load_stage(0, 0);
        cp_commit();
        if (nK > 1) load_stage(1, BK);
        cp_commit();
        for (int kt = 0; kt < nK; kt++) {
            cp_wait<1>();
            __syncthreads();
            if (kt + 2 < nK) load_stage((kt + 2) % 3, (kt + 2) * BK);
            cp_commit();
            compute(kt % 3);
        }
    } else {
        load_stage(0, 0);
        cp_commit();
        for (int kt = 0; kt < nK; kt++) {
            if (kt + 1 < nK) {
                load_stage((kt + 1) & 1, (kt + 1) * BK);
                cp_commit();
                cp_wait<1>();
            } else {
                cp_wait<0>();
            }
            __syncthreads();
            compute(kt & 1);
            __syncthreads();
        }
    }

    // ---------------- epilogue ----------------
    const float gt = g.gate ? *g.gate : 1.0f;
    float* Cf = g.Cf + z * g.sC;
    unsigned* Chi = g.Chi + z * g.sC;
    #pragma unroll
    for (int mt = 0; mt < 4; mt++) {
        int r0 = bm + wm * 64 + mt * 16 + gid;
        int r1 = r0 + 8;
        #pragma unroll
        for (int nt = 0; nt < 4; nt++) {
            int col = bn + wn * 32 + nt * 8 + 2 * tg;
            if (col >= g.N) continue;
            float b0 = g.bias ? g.bias[col]     : 0.f;
            float b1 = g.bias ? g.bias[col + 1] : 0.f;
            #pragma unroll
            for (int half = 0; half < 2; half++) {
                int r = half ? r1 : r0;
                if (r >= g.M) continue;
                size_t o = (size_t)r * g.ldc + col;
                float v0 = gt * (acc[mt][nt][half*2+0] + b0);
                float v1 = gt * (acc[mt][nt][half*2+1] + b1);
                if (g.accum) { v0 += Cf[o]; v1 += Cf[o+1]; }
                if (g.wr & WR_F32) *(float2*)(Cf + o) = make_float2(v0, v1);
                if (g.wr & WR_HI) { Chi[o] = to_tf32(v0); Chi[o+1] = to_tf32(v1); }
            }
        }
    }
}

// ---------------- kc2 broadcast: kc2[b][key] = skb2[key] + sum_r a_r * skb2[320+...] ----------------
__global__ void __launch_bounds__(256) kc2b_kernel(const int* __restrict__ catids,
                                                   const float* __restrict__ cat_A)
{
    __shared__ float rows[9][Cx];   // 36 KB
    int key = blockIdx.x;           // 0..319
    int v = key >> 5, s = key & 31;
    for (int u = threadIdx.x; u < 9*256; u += 256) {
        int rr = u >> 8, c4 = (u & 255) * 4;
        int srow = (rr == 0) ? key : NKMAX + (v*Rx + (rr-1))*SLOTSx + s;
        *(float4*)&rows[rr][c4] = *(const float4*)(g_skb2f + (size_t)srow*Cx + c4);
    }
    __syncthreads();
    int c = threadIdx.x * 4;
    float4 base = *(float4*)&rows[0][c];
    float4 w[Rx];
    #pragma unroll
    for (int r = 0; r < Rx; r++) w[r] = *(float4*)&rows[r+1][c];
    for (int b = 0; b < Bx; b++) {
        int cid = catids[b]; if (cid < 0) cid = 0;
        const float* ar = cat_A + (cid*Sx + v)*Rx;
        float4 o = base;
        #pragma unroll
        for (int r = 0; r < Rx; r++) {
            float a = ar[r];
            o.x += a*w[r].x; o.y += a*w[r].y; o.z += a*w[r].z; o.w += a*w[r].w;
        }
        uint4 h;
        h.x = to_tf32(o.x); h.y = to_tf32(o.y); h.z = to_tf32(o.z); h.w = to_tf32(o.w);
        *(uint4*)(g_kc2_h + ((size_t)(b*NKMAX + key))*Cx + c) = h;
    }
}

// ---------------- vcT broadcast (block per channel, smem-cached rows) ----------------
__global__ void __launch_bounds__(320) vct_kernel(const int* __restrict__ catids,
                                                  const float* __restrict__ cat_A)
{
    __shared__ float sv[NKMAX];
    __shared__ float cbv[2560];
    int c = blockIdx.x;             // 0..1023
    const float* src = g_svbTf + (size_t)c*NKB;
    for (int u = threadIdx.x; u < NKB; u += 320) {
        float vle = src[u];
        if (u < NKMAX) sv[u] = vle; else cbv[u - NKMAX] = vle;
    }
    __syncthreads();
    int key = threadIdx.x;
    int v = key >> 5, s = key & 31;
    float base = sv[key];
    float w[Rx];
    #pragma unroll
    for (int r = 0; r < Rx; r++) w[r] = cbv[(v*Rx + r)*SLOTSx + s];
    for (int b = 0; b < Bx; b++) {
        int cid = catids[b]; if (cid < 0) cid = 0;
        const float* ar = cat_A + (cid*Sx + v)*Rx;
        float acc = base;
        #pragma unroll
        for (int r = 0; r < Rx; r++) acc += ar[r] * w[r];
        g_vcT_h[((size_t)b*Cx + c)*NKMAX + key] = to_tf32(acc);
    }
}

// ---------------- alpha constant tables ----------------
__global__ void aconst_kernel(const float* __restrict__ cat_emb,
                              const float* __restrict__ scale_emb,
                              const float* __restrict__ aW1,
                              const float* __restrict__ ab1)
{
    int idx = blockIdx.x, h = threadIdx.x;
    if (idx < NCATx) {
        float acc = 0.f;
        const float* ce = cat_emb + (size_t)idx * Cx;
        for (int c = 0; c < Cx; c++)
            acc += ce[c] * aW1[(size_t)(Cx + c)*AHx + h];
        g_acat[idx*AHx + h] = acc;
    } else {
        int i = idx - NCATx;
        float acc = ab1[h];
        const float* se = scale_emb + (size_t)i * Cx;
        for (int c = 0; c < Cx; c++)
            acc += se[c] * aW1[(size_t)(2*Cx + c)*AHx + h];
        g_ascale[i*AHx + h] = acc;
    }
}

// ---------------- alpha + masked softmax + prescale -> tf32 hi planes ----------------
__global__ void __launch_bounds__(256) softmax_kernel(const int* __restrict__ catids,
                                                      const float* __restrict__ aW2,
                                                      const float* __restrict__ ab2)
{
    int w = threadIdx.x >> 5, lane = threadIdx.x & 31;
    int row = blockIdx.x * 8 + w;
    if (row >= NROW) return;
    int b = row / Lx, l = row % Lx;
    int i = 0;
    #pragma unroll
    for (int u = 1; u < 10; u++) if (l >= c_begin[u]) i = u;
    int nk = (i + 1) * SLOTSx;
    float ls = g_scal[0];

    int cid = catids[b];
    float a = 0.f;
    if (cid >= 0) {
        const float* qhp = g_qhf + (size_t)row*AHx;
        const float* ac  = g_acat + cid*AHx;
        const float* as  = g_ascale + i*AHx;
        float acc = 0.f;
        #pragma unroll
        for (int h = lane; h < AHx; h += 32) {
            float xv = qhp[h] + ac[h] + as[h];
            float ge = 0.5f*xv*(1.0f + erff(xv*0.70710678118654752f));
            acc += ge * aW2[h];
        }
        #pragma unroll
        for (int o = 16; o > 0; o >>= 1) acc += __shfl_xor_sync(0xffffffffu, acc, o);
        a = 1.0f/(1.0f + expf(-(acc + ab2[0])));
    }

    #pragma unroll
    for (int s = 0; s < 2; s++) {
        const float* p = (s ? g_lgcf : g_lgsf) + (size_t)row * NKMAX;
        unsigned* q = (s ? g_lgc_h : g_lgs_h) + (size_t)row * NKMAX;
        float wgt = s ? a : (1.0f - a);
        float v[10];
        int cnt = 0;
        float mx = -3.4e38f;
        for (int j = lane; j < nk; j += 32) { float t = p[j]*ls; v[cnt++] = t; mx = fmaxf(mx, t); }
        #pragma unroll
        for (int o = 16; o > 0; o >>= 1) mx = fmaxf(mx, __shfl_xor_sync(0xffffffffu, mx, o));
        float sum = 0.f;
        for (int c2 = 0; c2 < cnt; c2++) { v[c2] = expf(v[c2] - mx); sum += v[c2]; }
        #pragma unroll
        for (int o = 16; o > 0; o >>= 1) sum += __shfl_xor_sync(0xffffffffu, sum, o);
        float inv = wgt / sum;
        cnt = 0;
        for (int j = lane; j < NKMAX; j += 32)
            q[j] = (j < nk) ? to_tf32(v[cnt++] * inv) : 0u;
    }
}

// ---------------- tail ----------------
__global__ void tail_kernel(float* out, int n2, int total) {
    int idx = n2 + blockIdx.x*blockDim.x + threadIdx.x;
    if (idx < total) out[idx] = 0.f;
}

// ---------------- host helpers ----------------
static void launch_gemm(int npass, int M, int N, int K,
                        const unsigned* Ah, const unsigned* Al, int lda, long long sA,
                        const unsigned* Bh, const unsigned* Bl, int ldb, long long sB,
                        float* Cf, unsigned* Chi, int ldc, long long sC,
                        const float* bias, const float* gate,
                        int accum, int wr, int batches)
{
    GemmArgs g;
    g.M=M; g.N=N; g.K=K;
    g.Ah=Ah; g.Al=Al; g.lda=lda; g.sA=sA;
    g.Bh=Bh; g.Bl=Bl; g.ldb=ldb; g.sB=sB;
    g.Cf=Cf; g.Chi=Chi; g.ldc=ldc; g.sC=sC;
    g.bias=bias; g.gate=gate; g.accum=accum; g.wr=wr;
    dim3 grid((N + 127)/128, (M + 127)/128, batches);
    if (npass == 3) gemm_tmpl<3><<<grid, 256, 81920>>>(g);
    else            gemm_tmpl<1><<<grid, 256, 110592>>>(g);
}

static void launch_tsplit(const float* in, int R, int C, unsigned* oh, unsigned* ol)
{
    dim3 grid((C + 31)/32, (R + 31)/32);
    tsplit_kernel<<<grid, dim3(32, 8)>>>(in, R, C, oh, ol);
}

// ---------------- launch ----------------
extern "C" void kernel_launch(void* const* d_in, const int* in_sizes, int n_in,
                              void* d_out, int out_size) {
    const float* x        = (const float*)d_in[0];
    const int*   catids   = (const int*)  d_in[1];
    const float* shmem    = (const float*)d_in[2];
    const float* cat_A    = (const float*)d_in[3];
    const float* cat_B    = (const float*)d_in[4];
    const float* cat_emb  = (const float*)d_in[5];
    const float* scale_emb= (const float*)d_in[6];
    const float* Wq       = (const float*)d_in[7];
    const float* Wk       = (const float*)d_in[8];
    const float* Wv       = (const float*)d_in[9];
    const float* aW1      = (const float*)d_in[10];
    const float* ab1      = (const float*)d_in[11];
    const float* aW2      = (const float*)d_in[12];
    const float* ab2      = (const float*)d_in[13];
    const float* kW1      = (const float*)d_in[14];
    const float* kb1      = (const float*)d_in[15];
    const float* kW2      = (const float*)d_in[16];
    const float* kb2      = (const float*)d_in[17];
    const float* vW1      = (const float*)d_in[18];
    const float* vb1      = (const float*)d_in[19];
    const float* vW2      = (const float*)d_in[20];
    const float* vb2      = (const float*)d_in[21];
    const float* gk       = (const float*)d_in[22];
    const float* gv       = (const float*)d_in[23];
    const float* lt       = (const float*)d_in[24];

    cudaFuncSetAttribute(gemm_tmpl<3>, cudaFuncAttributeMaxDynamicSharedMemorySize, 81920);
    cudaFuncSetAttribute(gemm_tmpl<1>, cudaFuncAttributeMaxDynamicSharedMemorySize, 110592);

    #define SYM(t, p, s) t p; cudaGetSymbolAddress((void**)&p, s)
    SYM(unsigned*, p_x_h, g_x_h);
    SYM(unsigned*, p_kc2_h, g_kc2_h);
    SYM(unsigned*, p_Wq_rm_h, g_Wq_rm_h);
    SYM(unsigned*, p_FaT_h, g_FaT_h);
    SYM(unsigned*, p_WkT_h, g_WkT_h); SYM(unsigned*, p_WkT_l, g_WkT_l);
    SYM(unsigned*, p_WvT_h, g_WvT_h); SYM(unsigned*, p_WvT_l, g_WvT_l);
    SYM(unsigned*, p_aW1T_h, g_aW1T_h); SYM(unsigned*, p_aW1T_l, g_aW1T_l);
    SYM(unsigned*, p_w1T_h, g_w1T_h); SYM(unsigned*, p_w1T_l, g_w1T_l);
    SYM(unsigned*, p_kW2T_h, g_kW2T_h); SYM(unsigned*, p_kW2T_l, g_kW2T_l);
    SYM(unsigned*, p_vW2T_h, g_vW2T_h); SYM(unsigned*, p_vW2T_l, g_vW2T_l);
    SYM(unsigned*, p_skb_in_h, g_skb_in_h);
    SYM(unsigned*, p_skbh, g_skbh);
    SYM(float*,    p_skb2f, g_skb2f);
    SYM(unsigned*, p_skb2h, g_skb2h);
    SYM(float*,    p_svbTf, g_svbTf);
    SYM(unsigned*, p_svbTh, g_svbTh);
    SYM(unsigned*, p_vcT_h, g_vcT_h);
    SYM(float*,    p_lgsf, g_lgsf);   SYM(float*,    p_lgcf, g_lgcf);
    SYM(unsigned*, p_lgs_h, g_lgs_h); SYM(unsigned*, p_lgc_h, g_lgc_h);
    SYM(float*,    p_qhf, g_qhf);
    SYM(float*,    p_memf, g_memf);
    SYM(unsigned*, p_mem_h, g_mem_h);
    SYM(unsigned*, p_t1_h, g_t1_h);
    SYM(float*,    p_scal, g_scal);
    SYM(float*,    p_bias1, g_bias1);
    #undef SYM

    prep_kernel<<<1, 1>>>(gk, gv, lt);

    // -------- operand preparation --------
    cvt_kernel<<<(NQ/4 + 255)/256, 256>>>(x, p_x_h, NQ/4);
    cvt_kernel<<<(NKMAX*Cx/4 + 255)/256, 256>>>(shmem, p_skb_in_h, NKMAX*Cx/4);
    cvt_kernel<<<(2560*Cx/4 + 255)/256, 256>>>(cat_B, p_skb_in_h + NKMAX*Cx, 2560*Cx/4);
    cvt_kernel<<<(Cx*Cx/4 + 255)/256, 256>>>(Wq, p_Wq_rm_h, Cx*Cx/4);
    launch_tsplit(Wk, Cx, Cx, p_WkT_h, p_WkT_l);
    launch_tsplit(Wv, Cx, Cx, p_WvT_h, p_WvT_l);
    launch_tsplit(aW1, Cx, AHx, p_aW1T_h, p_aW1T_l);
    launch_tsplit(kW1, Cx, MRx, p_w1T_h, p_w1T_l);
    launch_tsplit(vW1, Cx, MRx, p_w1T_h + MRx*Cx, p_w1T_l + MRx*Cx);
    launch_tsplit(kW2, MRx, Cx, p_kW2T_h, p_kW2T_l);
    launch_tsplit(vW2, MRx, Cx, p_vW2T_h, p_vW2T_l);
    cudaMemcpyAsync(p_bias1, kb1, MRx*sizeof(float), cudaMemcpyDeviceToDevice);
    cudaMemcpyAsync(p_bias1 + MRx, vb1, MRx*sizeof(float), cudaMemcpyDeviceToDevice);

    // -------- projections (1-pass, BK=32) --------
    // [sk;cbk] = [shm;cat_B] @ Wk  (hi only)
    launch_gemm(1, NKB, Cx, Cx, p_skb_in_h, nullptr, Cx, 0, p_WkT_h, nullptr, Cx, 0,
                p_skb2f, p_skbh, Cx, 0, nullptr, nullptr, 0, WR_HI, 1);
    // [svT|cbvT] = WvT @ [shm;cat_B]^T
    launch_gemm(1, Cx, NKB, Cx, p_WvT_h, nullptr, Cx, 0, p_skb_in_h, nullptr, Cx, 0,
                p_svbTf, p_svbTh, NKB, 0, nullptr, nullptr, 0, WR_F32|WR_HI, 1);
    // skb2 = [sk;cbk] @ Wq^T  (rows 0..319 = FsT)
    launch_gemm(1, NKB, Cx, Cx, p_skbh, nullptr, Cx, 0, p_Wq_rm_h, nullptr, Cx, 0,
                p_skb2f, p_skb2h, Cx, 0, nullptr, nullptr, 0, WR_F32|WR_HI, 1);
    // FaT[h][c] = sum_d aW1[d][h] Wq[c][d]
    launch_gemm(1, AHx, Cx, Cx, p_aW1T_h, nullptr, Cx, 0, p_Wq_rm_h, nullptr, Cx, 0,
                p_memf, p_FaT_h, Cx, 0, nullptr, nullptr, 0, WR_HI, 1);
    // qh = x @ FaT^T
    launch_gemm(1, NROW, AHx, Cx, p_x_h, nullptr, Cx, 0, p_FaT_h, nullptr, Cx, 0,
                p_qhf, p_t1_h, AHx, 0, nullptr, nullptr, 0, WR_F32, 1);

    // per-batch folded kc2 / vcT hi planes (broadcast kernels)
    kc2b_kernel<<<NKMAX, 256>>>(catids, cat_A);
    vct_kernel<<<Cx, 320>>>(catids, cat_A);

    // alpha constants
    aconst_kernel<<<NCATx + Sx, AHx>>>(cat_emb, scale_emb, aW1, ab1);

    // -------- logits directly from x --------
    launch_gemm(1, NROW, NKMAX, Cx, p_x_h, nullptr, Cx, 0, p_skb2h, nullptr, Cx, 0,
                p_lgsf, p_lgs_h, NKMAX, 0, nullptr, nullptr, 0, WR_F32, 1);
    launch_gemm(1, Lx, NKMAX, Cx, p_x_h, nullptr, Cx, (long long)Lx*Cx,
                p_kc2_h, nullptr, Cx, (long long)NKMAX*Cx,
                p_lgcf, p_lgs_h, NKMAX, (long long)Lx*NKMAX, nullptr, nullptr, 0, WR_F32, Bx);

    // alpha + masked softmax -> tf32 hi planes (prescaled by (1-a)/a)
    softmax_kernel<<<(NROW + 7)/8, 256>>>(catids, aW2, ab2);

    // -------- PV (1-pass) --------
    launch_gemm(1, NROW, Cx, NKMAX, p_lgs_h, nullptr, NKMAX, 0, p_svbTh, nullptr, NKB, 0,
                p_memf, p_mem_h, Cx, 0, nullptr, nullptr, 0, WR_F32, 1);
    launch_gemm(1, Lx, Cx, NKMAX, p_lgc_h, nullptr, NKMAX, (long long)Lx*NKMAX,
                p_vcT_h, nullptr, NKMAX, (long long)Cx*NKMAX,
                p_memf, p_mem_h, Cx, (long long)Lx*Cx, nullptr, nullptr, 1, WR_HI, Bx);

    // -------- heads (1-pass) --------
    launch_gemm(1, NROW, 2*MRx, Cx, p_mem_h, nullptr, Cx, 0, p_w1T_h, nullptr, Cx, 0,
                p_memf, p_t1_h, 2*MRx, 0, p_bias1, nullptr, 0, WR_HI, 1);
    float* outk = (float*)d_out;
    float* outv = (float*)d_out + (size_t)NROW * Cx;
    launch_gemm(1, NROW, Cx, MRx, p_t1_h, nullptr, 2*MRx, 0, p_kW2T_h, nullptr, MRx, 0,
                outk, p_mem_h, Cx, 0, kb2, p_scal + 1, 0, WR_F32, 1);
    launch_gemm(1, NROW, Cx, MRx, p_t1_h + MRx, nullptr, 2*MRx, 0, p_vW2T_h, nullptr, MRx, 0,
                outv, p_mem_h, Cx, 0, vb2, p_scal + 2, 0, WR_F32, 1);

    tail_kernel<<<1, 256>>>((float*)d_out, 2 * NROW * Cx, out_size);
}

// round 14
// speedup vs baseline: 2.1690x; 1.1051x over previous
#include <cuda_runtime.h>
#include <math.h>

// ---------------- problem constants ----------------
static constexpr int Bx = 32, Lx = 680, Cx = 1024;
static constexpr int Sx = 10, SLOTSx = 32, Rx = 8, NCATx = 22;
static constexpr int MRx = 64, AHx = 128;
static constexpr int NROW = Bx * Lx;            // 21760
static constexpr int NKMAX = Sx * SLOTSx;       // 320
static constexpr int NQ = NROW * Cx;            // 22282240
static constexpr int NKB = NKMAX + 2560;        // 2880
static constexpr int NQL = AHx + NKMAX;         // 448
static constexpr int NK2 = 2 * NKMAX;           // 640

__constant__ int c_begin[10] = {0,1,5,14,30,55,91,155,255,424};

// ---------------- device scratch ----------------
__device__ unsigned g_x_h[NQ];
__device__ unsigned g_kc2_h[Bx*NKMAX*Cx];
__device__ unsigned g_Wq_rm_h[Cx*Cx];
__device__ unsigned g_Wk_rm_h[Cx*Cx];
__device__ unsigned g_G_h[Cx*Cx];                  // G[c][e] = sum_d Wq[c][d] Wk[e][d]
__device__ unsigned g_BQ_h[NQL*Cx];                // [FaT(128) ; FsT(320)]
__device__ unsigned g_WvT_h[Cx*Cx], g_WvT_l[Cx*Cx];
__device__ unsigned g_aW1T_h[AHx*Cx], g_aW1T_l[AHx*Cx];
__device__ unsigned g_w1T_h[(2*MRx)*Cx], g_w1T_l[(2*MRx)*Cx];
__device__ unsigned g_W2gT_h[2*Cx*MRx], g_W2gT_l[2*Cx*MRx];
__device__ unsigned g_skb_in_h[NKB*Cx];

__device__ float    g_skb2f[NKB*Cx];
__device__ unsigned g_skb2h[NKB*Cx];
__device__ float    g_svbTf[Cx*NKB];
__device__ unsigned g_vT_h[(size_t)Bx*Cx*NK2];     // stacked [svT ; vcT] per batch
__device__ float    g_qlgf[NROW*NQL];              // qh | lgs
__device__ float    g_lgcf[NROW*NKMAX];
__device__ unsigned g_P_h[NROW*NK2];               // stacked [Ps | Pc]
__device__ float    g_memf[NQ];
__device__ unsigned g_mem_h[NQ];
__device__ unsigned g_t1_h[NROW*(2*MRx)];
__device__ float    g_acat[NCATx*AHx];
__device__ float    g_ascale[Sx*AHx];
__device__ float    g_scal[4];
__device__ float    g_bias1[2*MRx];
__device__ float    g_bias2[2*Cx];

// ---------------- helpers ----------------
__device__ __forceinline__ void split_tf32(float x, unsigned& hi, unsigned& lo) {
    unsigned h; asm("cvt.rna.tf32.f32 %0, %1;" : "=r"(h) : "f"(x));
    float hf = __uint_as_float(h);
    unsigned l; asm("cvt.rna.tf32.f32 %0, %1;" : "=r"(l) : "f"(x - hf));
    hi = h; lo = l;
}
__device__ __forceinline__ unsigned to_tf32(float x) {
    unsigned h; asm("cvt.rna.tf32.f32 %0, %1;" : "=r"(h) : "f"(x)); return h;
}
__device__ __forceinline__ void mma8(float* d, const unsigned* a, const unsigned* b) {
    asm volatile(
        "mma.sync.aligned.m16n8k8.row.col.f32.tf32.tf32.f32 "
        "{%0,%1,%2,%3}, {%4,%5,%6,%7}, {%8,%9}, {%0,%1,%2,%3};"
        : "+f"(d[0]), "+f"(d[1]), "+f"(d[2]), "+f"(d[3])
        : "r"(a[0]), "r"(a[1]), "r"(a[2]), "r"(a[3]), "r"(b[0]), "r"(b[1]));
}
__device__ __forceinline__ uint4 ldsm4(unsigned a) {
    uint4 r;
    asm volatile("ldmatrix.sync.aligned.m8n8.x4.shared.b16 {%0,%1,%2,%3}, [%4];"
        : "=r"(r.x), "=r"(r.y), "=r"(r.z), "=r"(r.w) : "r"(a));
    return r;
}
__device__ __forceinline__ unsigned smaddr(const void* p) {
    unsigned a;
    asm("{.reg .u64 u; cvta.to.shared.u64 u, %1; cvt.u32.u64 %0, u;}" : "=r"(a) : "l"(p));
    return a;
}
__device__ __forceinline__ void cp16(unsigned dst, const void* src, bool ok) {
    int sz = ok ? 16 : 0;
    asm volatile("cp.async.cg.shared.global [%0], [%1], 16, %2;\n" :: "r"(dst), "l"(src), "r"(sz));
}
__device__ __forceinline__ void cp_commit() { asm volatile("cp.async.commit_group;"); }
template<int N> __device__ __forceinline__ void cp_wait() {
    asm volatile("cp.async.wait_group %0;" :: "n"(N));
}

// ---------------- prep ----------------
__global__ void prep_kernel(const float* gk, const float* gv, const float* lt) {
    float temp = expf(lt[0]);
    temp = fminf(fmaxf(temp, 0.05f), 1.0f);
    g_scal[0] = (1.0f / 32.0f) / temp;
    g_scal[1] = 1.0f / (1.0f + expf(-gk[0]));
    g_scal[2] = 1.0f / (1.0f + expf(-gv[0]));
}
__global__ void bias2_kernel(const float* kb2, const float* vb2) {
    int c = blockIdx.x * 256 + threadIdx.x;
    if (c < Cx) {
        g_bias2[c]      = g_scal[1] * kb2[c];
        g_bias2[Cx + c] = g_scal[2] * vb2[c];
    }
}

// ---------------- fp32 -> tf32 hi plane ----------------
__global__ void cvt_kernel(const float* __restrict__ in, unsigned* __restrict__ hi, int n4) {
    int i = blockIdx.x * 256 + threadIdx.x;
    if (i >= n4) return;
    float4 v = ((const float4*)in)[i];
    uint4 h;
    h.x = to_tf32(v.x); h.y = to_tf32(v.y); h.z = to_tf32(v.z); h.w = to_tf32(v.w);
    ((uint4*)hi)[i] = h;
}
__global__ void copyu_kernel(const unsigned* __restrict__ src, unsigned* __restrict__ dst, int n4) {
    int i = blockIdx.x * 256 + threadIdx.x;
    if (i < n4) ((uint4*)dst)[i] = ((const uint4*)src)[i];
}

// ---------------- transpose + split (optional gate): [R][C] -> planes [C][R] ----------------
__global__ void tsplit_kernel(const float* __restrict__ in, int R, int C,
                              unsigned* __restrict__ oh, unsigned* __restrict__ ol,
                              const float* __restrict__ gate)
{
    __shared__ float t[32][33];
    int r0 = blockIdx.y * 32, c0 = blockIdx.x * 32;
    int tx = threadIdx.x, ty = threadIdx.y;
    float gt = gate ? *gate : 1.0f;
    #pragma unroll
    for (int i = 0; i < 32; i += 8) {
        int r = r0 + ty + i;
        t[ty + i][tx] = (r < R && c0 + tx < C) ? gt * in[(size_t)r * C + c0 + tx] : 0.f;
    }
    __syncthreads();
    #pragma unroll
    for (int i = 0; i < 32; i += 8) {
        int c = c0 + ty + i, r = r0 + tx;
        if (c < C && r < R) {
            unsigned h, l; split_tf32(t[tx][ty + i], h, l);
            oh[(size_t)c * R + r] = h;
            ol[(size_t)c * R + r] = l;
        }
    }
}

// ---------------- GEMM ----------------
static constexpr int WR_F32 = 1, WR_HI = 4;

struct GemmArgs {
    int M, N, K;
    const unsigned *Ah; int lda; long long sA;
    const unsigned *Bh; int ldb; long long sB;   // B is [N][K] (NT)
    float* Cf; unsigned *Chi; int ldc; long long sC;
    const float* bias; long long sBias;
    const float* gate;
    int accum, wr;
};

// BN=128, 2 CTAs/SM, BK=32, 3-stage ring, 1-pass tf32.
__global__ void __launch_bounds__(256, 2) gemm1(GemmArgs g)
{
    constexpr int BK = 32, AW = 36, ASZ = 128 * AW, STG = 2 * ASZ, CPT = 4;
    extern __shared__ unsigned sm[];

    const int tid = threadIdx.x, lane = tid & 31, wid = tid >> 5;
    const int wm = wid >> 2, wn = wid & 3, tg = lane & 3, gid = lane >> 2;
    const int bm = blockIdx.y * 128, bn = blockIdx.x * 128;
    const long long z = blockIdx.z;

    const unsigned* Ap = g.Ah + z * g.sA;
    const unsigned* Bp = g.Bh + z * g.sB;
    const unsigned smbase = smaddr(sm);

    const int am = lane >> 3;
    const int a_row = (am & 1) * 8 + (lane & 7);
    const int a_kw  = (am >> 1) * 4;
    const int b_row = (am >> 1) * 8 + (lane & 7);
    const int b_kw  = (am & 1) * 4;
    unsigned aA[4], bA[2];
    #pragma unroll
    for (int mt = 0; mt < 4; mt++)
        aA[mt] = smbase + (unsigned)((wm*64 + mt*16 + a_row) * AW + a_kw) * 4u;
    #pragma unroll
    for (int pr = 0; pr < 2; pr++)
        bA[pr] = smbase + (unsigned)ASZ * 4u
               + (unsigned)((wn*32 + pr*16 + b_row) * AW + b_kw) * 4u;

    float acc[4][4][4];
    #pragma unroll
    for (int mt = 0; mt < 4; mt++)
        #pragma unroll
        for (int nt = 0; nt < 4; nt++)
            #pragma unroll
            for (int u = 0; u < 4; u++) acc[mt][nt][u] = 0.f;

    auto load_stage = [&](int s, int k0) {
        unsigned base = smbase + (unsigned)(s * STG) * 4u;
        #pragma unroll
        for (int j = 0; j < CPT; j++) {
            int c = tid + j * 256;
            int row = c >> 3, kc = (c & 7) * 4;
            bool ok = (bm + row) < g.M;
            const unsigned* src = ok ? Ap + (size_t)(bm + row) * g.lda + k0 + kc : Ap;
            cp16(base + (unsigned)(row * AW + kc) * 4u, src, ok);
        }
        unsigned bbase = base + (unsigned)ASZ * 4u;
        #pragma unroll
        for (int j = 0; j < CPT; j++) {
            int c = tid + j * 256;
            int row = c >> 3, kc = (c & 7) * 4;
            bool ok = (bn + row) < g.N;
            const unsigned* src = ok ? Bp + (size_t)(bn + row) * g.ldb + k0 + kc : Bp;
            cp16(bbase + (unsigned)(row * AW + kc) * 4u, src, ok);
        }
    };

    auto compute = [&](int s) {
        const unsigned so = (unsigned)(s * STG) * 4u;
        #pragma unroll
        for (int kk = 0; kk < BK; kk += 8) {
            const unsigned kb = so + (unsigned)kk * 4u;
            unsigned bh[4][2];
            #pragma unroll
            for (int pr = 0; pr < 2; pr++) {
                uint4 r = ldsm4(bA[pr] + kb);
                bh[pr*2+0][0] = r.x; bh[pr*2+0][1] = r.y;
                bh[pr*2+1][0] = r.z; bh[pr*2+1][1] = r.w;
            }
            #pragma unroll
            for (int mt = 0; mt < 4; mt++) {
                uint4 ah4 = ldsm4(aA[mt] + kb);
                #pragma unroll
                for (int nt = 0; nt < 4; nt++)
                    mma8(acc[mt][nt], (const unsigned*)&ah4, bh[nt]);
            }
        }
    };

    const int nK = g.K / BK;
    load_stage(0, 0);
    cp_commit();
    if (nK > 1) load_stage(1, BK);
    cp_commit();
    for (int kt = 0; kt < nK; kt++) {
        cp_wait<1>();
        __syncthreads();
        if (kt + 2 < nK) load_stage((kt + 2) % 3, (kt + 2) * BK);
        cp_commit();
        compute(kt % 3);
    }

    const float gt = g.gate ? *g.gate : 1.0f;
    float* Cf = g.Cf + z * g.sC;
    unsigned* Chi = g.Chi + z * g.sC;
    const float* bs = g.bias ? g.bias + z * g.sBias : nullptr;
    #pragma unroll
    for (int mt = 0; mt < 4; mt++) {
        int r0 = bm + wm * 64 + mt * 16 + gid;
        int r1 = r0 + 8;
        #pragma unroll
        for (int nt = 0; nt < 4; nt++) {
            int col = bn + wn * 32 + nt * 8 + 2 * tg;
            if (col >= g.N) continue;
            float b0 = bs ? bs[col]     : 0.f;
            float b1 = bs ? bs[col + 1] : 0.f;
            #pragma unroll
            for (int half = 0; half < 2; half++) {
                int r = half ? r1 : r0;
                if (r >= g.M) continue;
                size_t o = (size_t)r * g.ldc + col;
                float v0 = gt * (acc[mt][nt][half*2+0] + b0);
                float v1 = gt * (acc[mt][nt][half*2+1] + b1);
                if (g.accum) { v0 += Cf[o]; v1 += Cf[o+1]; }
                if (g.wr & WR_F32) *(float2*)(Cf + o) = make_float2(v0, v1);
                if (g.wr & WR_HI) { Chi[o] = to_tf32(v0); Chi[o+1] = to_tf32(v1); }
            }
        }
    }
}

// ---------------- kc2 broadcast ----------------
__global__ void __launch_bounds__(256) kc2b_kernel(const int* __restrict__ catids,
                                                   const float* __restrict__ cat_A)
{
    __shared__ float rows[9][Cx];
    int key = blockIdx.x;
    int v = key >> 5, s = key & 31;
    for (int u = threadIdx.x; u < 9*256; u += 256) {
        int rr = u >> 8, c4 = (u & 255) * 4;
        int srow = (rr == 0) ? key : NKMAX + (v*Rx + (rr-1))*SLOTSx + s;
        *(float4*)&rows[rr][c4] = *(const float4*)(g_skb2f + (size_t)srow*Cx + c4);
    }
    __syncthreads();
    int c = threadIdx.x * 4;
    float4 base = *(float4*)&rows[0][c];
    float4 w[Rx];
    #pragma unroll
    for (int r = 0; r < Rx; r++) w[r] = *(float4*)&rows[r+1][c];
    for (int b = 0; b < Bx; b++) {
        int cid = catids[b]; if (cid < 0) cid = 0;
        const float* ar = cat_A + (cid*Sx + v)*Rx;
        float4 o = base;
        #pragma unroll
        for (int r = 0; r < Rx; r++) {
            float a = ar[r];
            o.x += a*w[r].x; o.y += a*w[r].y; o.z += a*w[r].z; o.w += a*w[r].w;
        }
        uint4 h;
        h.x = to_tf32(o.x); h.y = to_tf32(o.y); h.z = to_tf32(o.z); h.w = to_tf32(o.w);
        *(uint4*)(g_kc2_h + ((size_t)(b*NKMAX + key))*Cx + c) = h;
    }
}

// ---------------- vT stacked broadcast: vT[b][c] = [svT(c) | vcT(b,c)] ----------------
__global__ void __launch_bounds__(320) vct_kernel(const int* __restrict__ catids,
                                                  const float* __restrict__ cat_A)
{
    __shared__ float sv[NKMAX];
    __shared__ float cbv[2560];
    int c = blockIdx.x;
    const float* src = g_svbTf + (size_t)c*NKB;
    for (int u = threadIdx.x; u < NKB; u += 320) {
        float vle = src[u];
        if (u < NKMAX) sv[u] = vle; else cbv[u - NKMAX] = vle;
    }
    __syncthreads();
    int key = threadIdx.x;
    int v = key >> 5, s = key & 31;
    float base = sv[key];
    unsigned base_h = to_tf32(base);
    float w[Rx];
    #pragma unroll
    for (int r = 0; r < Rx; r++) w[r] = cbv[(v*Rx + r)*SLOTSx + s];
    for (int b = 0; b < Bx; b++) {
        int cid = catids[b]; if (cid < 0) cid = 0;
        const float* ar = cat_A + (cid*Sx + v)*Rx;
        float acc = base;
        #pragma unroll
        for (int r = 0; r < Rx; r++) acc += ar[r] * w[r];
        size_t o = ((size_t)b*Cx + c)*NK2;
        g_vT_h[o + key] = base_h;
        g_vT_h[o + NKMAX + key] = to_tf32(acc);
    }
}

// ---------------- alpha constant tables ----------------
__global__ void aconst_kernel(const float* __restrict__ cat_emb,
                              const float* __restrict__ scale_emb,
                              const float* __restrict__ aW1,
                              const float* __restrict__ ab1)
{
    int idx = blockIdx.x, h = threadIdx.x;
    if (idx < NCATx) {
        float acc = 0.f;
        const float* ce = cat_emb + (size_t)idx * Cx;
        for (int c = 0; c < Cx; c++)
            acc += ce[c] * aW1[(size_t)(Cx + c)*AHx + h];
        g_acat[idx*AHx + h] = acc;
    } else {
        int i = idx - NCATx;
        float acc = ab1[h];
        const float* se = scale_emb + (size_t)i * Cx;
        for (int c = 0; c < Cx; c++)
            acc += se[c] * aW1[(size_t)(2*Cx + c)*AHx + h];
        g_ascale[i*AHx + h] = acc;
    }
}

// ---------------- alpha + masked softmax -> stacked P hi planes ----------------
__global__ void __launch_bounds__(256) softmax_kernel(const int* __restrict__ catids,
                                                      const float* __restrict__ aW2,
                                                      const float* __restrict__ ab2)
{
    int w = threadIdx.x >> 5, lane = threadIdx.x & 31;
    int row = blockIdx.x * 8 + w;
    if (row >= NROW) return;
    int b = row / Lx, l = row % Lx;
    int i = 0;
    #pragma unroll
    for (int u = 1; u < 10; u++) if (l >= c_begin[u]) i = u;
    int nk = (i + 1) * SLOTSx;
    float ls = g_scal[0];

    int cid = catids[b];
    float a = 0.f;
    if (cid >= 0) {
        const float* qhp = g_qlgf + (size_t)row*NQL;
        const float* ac  = g_acat + cid*AHx;
        const float* as  = g_ascale + i*AHx;
        float acc = 0.f;
        #pragma unroll
        for (int h = lane; h < AHx; h += 32) {
            float xv = qhp[h] + ac[h] + as[h];
            float ge = 0.5f*xv*(1.0f + erff(xv*0.70710678118654752f));
            acc += ge * aW2[h];
        }
        #pragma unroll
        for (int o = 16; o > 0; o >>= 1) acc += __shfl_xor_sync(0xffffffffu, acc, o);
        a = 1.0f/(1.0f + expf(-(acc + ab2[0])));
    }

    #pragma unroll
    for (int s = 0; s < 2; s++) {
        const float* p = s ? (g_lgcf + (size_t)row * NKMAX)
                           : (g_qlgf + (size_t)row * NQL + AHx);
        unsigned* q = g_P_h + (size_t)row * NK2 + s * NKMAX;
        float wgt = s ? a : (1.0f - a);
        float v[10];
        int cnt = 0;
        float mx = -3.4e38f;
        for (int j = lane; j < nk; j += 32) { float t = p[j]*ls; v[cnt++] = t; mx = fmaxf(mx, t); }
        #pragma unroll
        for (int o = 16; o > 0; o >>= 1) mx = fmaxf(mx, __shfl_xor_sync(0xffffffffu, mx, o));
        float sum = 0.f;
        for (int c2 = 0; c2 < cnt; c2++) { v[c2] = expf(v[c2] - mx); sum += v[c2]; }
        #pragma unroll
        for (int o = 16; o > 0; o >>= 1) sum += __shfl_xor_sync(0xffffffffu, sum, o);
        float inv = wgt / sum;
        cnt = 0;
        for (int j = lane; j < NKMAX; j += 32)
            q[j] = (j < nk) ? to_tf32(v[cnt++] * inv) : 0u;
    }
}

// ---------------- tail ----------------
__global__ void tail_kernel(float* out, int n2, int total) {
    int idx = n2 + blockIdx.x*blockDim.x + threadIdx.x;
    if (idx < total) out[idx] = 0.f;
}

// ---------------- host helpers ----------------
static void launch_gemm(int M, int N, int K,
                        const unsigned* Ah, int lda, long long sA,
                        const unsigned* Bh, int ldb, long long sB,
                        float* Cf, unsigned* Chi, int ldc, long long sC,
                        const float* bias, long long sBias, const float* gate,
                        int accum, int wr, int batches)
{
    GemmArgs g;
    g.M=M; g.N=N; g.K=K;
    g.Ah=Ah; g.lda=lda; g.sA=sA;
    g.Bh=Bh; g.ldb=ldb; g.sB=sB;
    g.Cf=Cf; g.Chi=Chi; g.ldc=ldc; g.sC=sC;
    g.bias=bias; g.sBias=sBias; g.gate=gate; g.accum=accum; g.wr=wr;
    dim3 grid((N + 127)/128, (M + 127)/128, batches);
    gemm1<<<grid, 256, 110592>>>(g);
}

static void launch_tsplit(const float* in, int R, int C, unsigned* oh, unsigned* ol,
                          const float* gate)
{
    dim3 grid((C + 31)/32, (R + 31)/32);
    tsplit_kernel<<<grid, dim3(32, 8)>>>(in, R, C, oh, ol, gate);
}

// ---------------- launch ----------------
extern "C" void kernel_launch(void* const* d_in, const int* in_sizes, int n_in,
                              void* d_out, int out_size) {
    const float* x        = (const float*)d_in[0];
    const int*   catids   = (const int*)  d_in[1];
    const float* shmem    = (const float*)d_in[2];
    const float* cat_A    = (const float*)d_in[3];
    const float* cat_B    = (const float*)d_in[4];
    const float* cat_emb  = (const float*)d_in[5];
    const float* scale_emb= (const float*)d_in[6];
    const float* Wq       = (const float*)d_in[7];
    const float* Wk       = (const float*)d_in[8];
    const float* Wv       = (const float*)d_in[9];
    const float* aW1      = (const float*)d_in[10];
    const float* ab1      = (const float*)d_in[11];
    const float* aW2      = (const float*)d_in[12];
    const float* ab2      = (const float*)d_in[13];
    const float* kW1      = (const float*)d_in[14];
    const float* kb1      = (const float*)d_in[15];
    const float* kW2      = (const float*)d_in[16];
    const float* kb2      = (const float*)d_in[17];
    const float* vW1      = (const float*)d_in[18];
    const float* vb1      = (const float*)d_in[19];
    const float* vW2      = (const float*)d_in[20];
    const float* vb2      = (const float*)d_in[21];
    const float* gk       = (const float*)d_in[22];
    const float* gv       = (const float*)d_in[23];
    const float* lt       = (const float*)d_in[24];

    cudaFuncSetAttribute(gemm1, cudaFuncAttributeMaxDynamicSharedMemorySize, 110592);

    #define SYM(t, p, s) t p; cudaGetSymbolAddress((void**)&p, s)
    SYM(unsigned*, p_x_h, g_x_h);
    SYM(unsigned*, p_kc2_h, g_kc2_h);
    SYM(unsigned*, p_Wq_rm, g_Wq_rm_h);
    SYM(unsigned*, p_Wk_rm, g_Wk_rm_h);
    SYM(unsigned*, p_G_h, g_G_h);
    SYM(unsigned*, p_BQ_h, g_BQ_h);
    SYM(unsigned*, p_WvT_h, g_WvT_h); SYM(unsigned*, p_WvT_l, g_WvT_l);
    SYM(unsigned*, p_aW1T_h, g_aW1T_h); SYM(unsigned*, p_aW1T_l, g_aW1T_l);
    SYM(unsigned*, p_w1T_h, g_w1T_h); SYM(unsigned*, p_w1T_l, g_w1T_l);
    SYM(unsigned*, p_W2gT_h, g_W2gT_h); SYM(unsigned*, p_W2gT_l, g_W2gT_l);
    SYM(unsigned*, p_skb_in, g_skb_in_h);
    SYM(float*,    p_skb2f, g_skb2f);
    SYM(unsigned*, p_skb2h, g_skb2h);
    SYM(float*,    p_svbTf, g_svbTf);
    SYM(unsigned*, p_vT_h, g_vT_h);
    SYM(float*,    p_qlgf, g_qlgf);
    SYM(float*,    p_lgcf, g_lgcf);
    SYM(unsigned*, p_P_h, g_P_h);
    SYM(float*,    p_memf, g_memf);
    SYM(unsigned*, p_mem_h, g_mem_h);
    SYM(unsigned*, p_t1_h, g_t1_h);
    SYM(float*,    p_scal, g_scal);
    SYM(float*,    p_bias1, g_bias1);
    SYM(float*,    p_bias2, g_bias2);
    #undef SYM

    prep_kernel<<<1, 1>>>(gk, gv, lt);
    bias2_kernel<<<4, 256>>>(kb2, vb2);

    // -------- operand preparation --------
    cvt_kernel<<<(NQ/4 + 255)/256, 256>>>(x, p_x_h, NQ/4);
    cvt_kernel<<<(NKMAX*Cx/4 + 255)/256, 256>>>(shmem, p_skb_in, NKMAX*Cx/4);
    cvt_kernel<<<(2560*Cx/4 + 255)/256, 256>>>(cat_B, p_skb_in + NKMAX*Cx, 2560*Cx/4);
    cvt_kernel<<<(Cx*Cx/4 + 255)/256, 256>>>(Wq, p_Wq_rm, Cx*Cx/4);
    cvt_kernel<<<(Cx*Cx/4 + 255)/256, 256>>>(Wk, p_Wk_rm, Cx*Cx/4);
    launch_tsplit(Wv, Cx, Cx, p_WvT_h, p_WvT_l, nullptr);
    launch_tsplit(aW1, Cx, AHx, p_aW1T_h, p_aW1T_l, nullptr);
    launch_tsplit(kW1, Cx, MRx, p_w1T_h, p_w1T_l, nullptr);
    launch_tsplit(vW1, Cx, MRx, p_w1T_h + MRx*Cx, p_w1T_l + MRx*Cx, nullptr);
    launch_tsplit(kW2, MRx, Cx, p_W2gT_h, p_W2gT_l, p_scal + 1);
    launch_tsplit(vW2, MRx, Cx, p_W2gT_h + Cx*MRx, p_W2gT_l + Cx*MRx, p_scal + 2);
    cudaMemcpyAsync(p_bias1, kb1, MRx*sizeof(float), cudaMemcpyDeviceToDevice);
    cudaMemcpyAsync(p_bias1 + MRx, vb1, MRx*sizeof(float), cudaMemcpyDeviceToDevice);

    // -------- folded weight GEMMs --------
    // G[c][e] = sum_d Wq[c][d] Wk[e][d]
    launch_gemm(Cx, Cx, Cx, p_Wq_rm, Cx, 0, p_Wk_rm, Cx, 0,
                p_skb2f, p_G_h, Cx, 0, nullptr, 0, nullptr, 0, WR_HI, 1);
    // [svT|cbvT] = WvT @ [shm;cat_B]^T
    launch_gemm(Cx, NKB, Cx, p_WvT_h, Cx, 0, p_skb_in, Cx, 0,
                p_svbTf, p_G_h, NKB, 0, nullptr, 0, nullptr, 0, WR_F32, 1);
    // skb2 = skbin @ G^T  (rows 0..319 = FsT)
    launch_gemm(NKB, Cx, Cx, p_skb_in, Cx, 0, p_G_h, Cx, 0,
                p_skb2f, p_skb2h, Cx, 0, nullptr, 0, nullptr, 0, WR_F32|WR_HI, 1);
    // FaT rows -> BQ[0..127]
    launch_gemm(AHx, Cx, Cx, p_aW1T_h, Cx, 0, p_Wq_rm, Cx, 0,
                p_memf, p_BQ_h, Cx, 0, nullptr, 0, nullptr, 0, WR_HI, 1);
    // FsT rows -> BQ[128..447]
    copyu_kernel<<<(NKMAX*Cx/4 + 255)/256, 256>>>(p_skb2h, p_BQ_h + AHx*Cx, NKMAX*Cx/4);

    // qh|lgs = x @ BQ^T
    launch_gemm(NROW, NQL, Cx, p_x_h, Cx, 0, p_BQ_h, Cx, 0,
                p_qlgf, p_kc2_h, NQL, 0, nullptr, 0, nullptr, 0, WR_F32, 1);

    // per-batch folded kc2 / stacked vT
    kc2b_kernel<<<NKMAX, 256>>>(catids, cat_A);
    vct_kernel<<<Cx, 320>>>(catids, cat_A);
    aconst_kernel<<<NCATx + Sx, AHx>>>(cat_emb, scale_emb, aW1, ab1);

    // lgc = x @ kc2^T (batched)
    launch_gemm(Lx, NKMAX, Cx, p_x_h, Cx, (long long)Lx*Cx,
                p_kc2_h, Cx, (long long)NKMAX*Cx,
                p_lgcf, p_P_h, NKMAX, (long long)Lx*NKMAX, nullptr, 0, nullptr, 0, WR_F32, Bx);

    softmax_kernel<<<(NROW + 7)/8, 256>>>(catids, aW2, ab2);

    // mem = P @ vT^T (batched, K=640)
    launch_gemm(Lx, Cx, NK2, p_P_h, NK2, (long long)Lx*NK2,
                p_vT_h, NK2, (long long)Cx*NK2,
                p_memf, p_mem_h, Cx, (long long)Lx*Cx, nullptr, 0, nullptr, 0, WR_F32|WR_HI, Bx);

    // heads
    launch_gemm(NROW, 2*MRx, Cx, p_mem_h, Cx, 0, p_w1T_h, Cx, 0,
                p_memf, p_t1_h, 2*MRx, 0, p_bias1, 0, nullptr, 0, WR_HI, 1);
    launch_gemm(NROW, Cx, MRx, p_t1_h, 2*MRx, MRx,
                p_W2gT_h, MRx, (long long)Cx*MRx,
                (float*)d_out, p_mem_h, Cx, (long long)NROW*Cx,
                p_bias2, Cx, nullptr, 0, WR_F32, 2);

    tail_kernel<<<1, 256>>>((float*)d_out, 2 * NROW * Cx, out_size);
}

// round 15
// speedup vs baseline: 2.2489x; 1.0368x over previous
#include <cuda_runtime.h>
#include <math.h>

// ---------------- problem constants ----------------
static constexpr int Bx = 32, Lx = 680, Cx = 1024;
static constexpr int Sx = 10, SLOTSx = 32, Rx = 8, NCATx = 22;
static constexpr int MRx = 64, AHx = 128;
static constexpr int NROW = Bx * Lx;            // 21760
static constexpr int NKMAX = Sx * SLOTSx;       // 320
static constexpr int NQ = NROW * Cx;            // 22282240
static constexpr int NKB = NKMAX + 2560;        // 2880
static constexpr int NQL = AHx + NKMAX;         // 448
static constexpr int NBL = NQL + NKMAX;         // 768 (qh|lgs|lgc cols)
static constexpr int NK2 = 2 * NKMAX;           // 640

__constant__ int c_begin[10] = {0,1,5,14,30,55,91,155,255,424};

// ---------------- device scratch ----------------
__device__ unsigned g_x_h[NQ];
__device__ unsigned g_Wq_rm_h[Cx*Cx];
__device__ unsigned g_Wk_rm_h[Cx*Cx];
__device__ unsigned g_G_h[Cx*Cx];                  // G[c][e] = sum_d Wq[c][d] Wk[e][d]
__device__ unsigned g_BQ_h[NQL*Cx];                // [FaT(128) ; FsT(320)]
__device__ unsigned g_Ball_h[(size_t)Bx*NBL*Cx];   // per-batch [BQ ; kc2[b]]
__device__ unsigned g_WvT_h[Cx*Cx], g_WvT_l[Cx*Cx];
__device__ unsigned g_aW1T_h[AHx*Cx], g_aW1T_l[AHx*Cx];
__device__ unsigned g_w1T_h[(2*MRx)*Cx], g_w1T_l[(2*MRx)*Cx];
__device__ unsigned g_W2gT_h[2*Cx*MRx], g_W2gT_l[2*Cx*MRx];
__device__ unsigned g_skb_in_h[NKB*Cx];

__device__ float    g_skb2f[NKB*Cx];
__device__ unsigned g_skb2h[NKB*Cx];
__device__ float    g_svbTf[Cx*NKB];
__device__ unsigned g_vT_h[(size_t)Bx*Cx*NK2];     // stacked [svT ; vcT] per batch
__device__ float    g_qlgf[(size_t)NROW*NBL];      // qh | lgs | lgc
__device__ unsigned g_P_h[NROW*NK2];               // stacked [Ps | Pc]
__device__ float    g_memf[NQ];
__device__ unsigned g_mem_h[NQ];
__device__ unsigned g_t1_h[NROW*(2*MRx)];
__device__ float    g_acat[NCATx*AHx];
__device__ float    g_ascale[Sx*AHx];
__device__ float    g_scal[4];
__device__ float    g_bias1[2*MRx];
__device__ float    g_bias2[2*Cx];

// ---------------- helpers ----------------
__device__ __forceinline__ void split_tf32(float x, unsigned& hi, unsigned& lo) {
    unsigned h; asm("cvt.rna.tf32.f32 %0, %1;" : "=r"(h) : "f"(x));
    float hf = __uint_as_float(h);
    unsigned l; asm("cvt.rna.tf32.f32 %0, %1;" : "=r"(l) : "f"(x - hf));
    hi = h; lo = l;
}
__device__ __forceinline__ unsigned to_tf32(float x) {
    unsigned h; asm("cvt.rna.tf32.f32 %0, %1;" : "=r"(h) : "f"(x)); return h;
}
__device__ __forceinline__ void mma8(float* d, const unsigned* a, const unsigned* b) {
    asm volatile(
        "mma.sync.aligned.m16n8k8.row.col.f32.tf32.tf32.f32 "
        "{%0,%1,%2,%3}, {%4,%5,%6,%7}, {%8,%9}, {%0,%1,%2,%3};"
        : "+f"(d[0]), "+f"(d[1]), "+f"(d[2]), "+f"(d[3])
        : "r"(a[0]), "r"(a[1]), "r"(a[2]), "r"(a[3]), "r"(b[0]), "r"(b[1]));
}
__device__ __forceinline__ uint4 ldsm4(unsigned a) {
    uint4 r;
    asm volatile("ldmatrix.sync.aligned.m8n8.x4.shared.b16 {%0,%1,%2,%3}, [%4];"
        : "=r"(r.x), "=r"(r.y), "=r"(r.z), "=r"(r.w) : "r"(a));
    return r;
}
__device__ __forceinline__ unsigned smaddr(const void* p) {
    unsigned a;
    asm("{.reg .u64 u; cvta.to.shared.u64 u, %1; cvt.u32.u64 %0, u;}" : "=r"(a) : "l"(p));
    return a;
}
__device__ __forceinline__ void cp16(unsigned dst, const void* src, bool ok) {
    int sz = ok ? 16 : 0;
    asm volatile("cp.async.cg.shared.global [%0], [%1], 16, %2;\n" :: "r"(dst), "l"(src), "r"(sz));
}
__device__ __forceinline__ void cp_commit() { asm volatile("cp.async.commit_group;"); }
template<int N> __device__ __forceinline__ void cp_wait() {
    asm volatile("cp.async.wait_group %0;" :: "n"(N));
}

// ---------------- prep ----------------
__global__ void prep_kernel(const float* gk, const float* gv, const float* lt) {
    float temp = expf(lt[0]);
    temp = fminf(fmaxf(temp, 0.05f), 1.0f);
    g_scal[0] = (1.0f / 32.0f) / temp;
    g_scal[1] = 1.0f / (1.0f + expf(-gk[0]));
    g_scal[2] = 1.0f / (1.0f + expf(-gv[0]));
}
__global__ void bias2_kernel(const float* kb2, const float* vb2) {
    int c = blockIdx.x * 256 + threadIdx.x;
    if (c < Cx) {
        g_bias2[c]      = g_scal[1] * kb2[c];
        g_bias2[Cx + c] = g_scal[2] * vb2[c];
    }
}

// ---------------- fp32 -> tf32 hi plane ----------------
__global__ void cvt_kernel(const float* __restrict__ in, unsigned* __restrict__ hi, int n4) {
    int i = blockIdx.x * 256 + threadIdx.x;
    if (i >= n4) return;
    float4 v = ((const float4*)in)[i];
    uint4 h;
    h.x = to_tf32(v.x); h.y = to_tf32(v.y); h.z = to_tf32(v.z); h.w = to_tf32(v.w);
    ((uint4*)hi)[i] = h;
}
__global__ void copyu_kernel(const unsigned* __restrict__ src, unsigned* __restrict__ dst, int n4) {
    int i = blockIdx.x * 256 + threadIdx.x;
    if (i < n4) ((uint4*)dst)[i] = ((const uint4*)src)[i];
}
// broadcast BQ (448x1024) into each batch's Ball rows 0..447
__global__ void bqbc_kernel() {
    int i = blockIdx.x * 256 + threadIdx.x;     // uint4 index within BQ
    int b = blockIdx.y;
    if (i < NQL*Cx/4)
        ((uint4*)(g_Ball_h + (size_t)b*NBL*Cx))[i] = ((const uint4*)g_BQ_h)[i];
}

// ---------------- transpose + split (optional gate): [R][C] -> planes [C][R] ----------------
__global__ void tsplit_kernel(const float* __restrict__ in, int R, int C,
                              unsigned* __restrict__ oh, unsigned* __restrict__ ol,
                              const float* __restrict__ gate)
{
    __shared__ float t[32][33];
    int r0 = blockIdx.y * 32, c0 = blockIdx.x * 32;
    int tx = threadIdx.x, ty = threadIdx.y;
    float gt = gate ? *gate : 1.0f;
    #pragma unroll
    for (int i = 0; i < 32; i += 8) {
        int r = r0 + ty + i;
        t[ty + i][tx] = (r < R && c0 + tx < C) ? gt * in[(size_t)r * C + c0 + tx] : 0.f;
    }
    __syncthreads();
    #pragma unroll
    for (int i = 0; i < 32; i += 8) {
        int c = c0 + ty + i, r = r0 + tx;
        if (c < C && r < R) {
            unsigned h, l; split_tf32(t[tx][ty + i], h, l);
            oh[(size_t)c * R + r] = h;
            ol[(size_t)c * R + r] = l;
        }
    }
}

// ---------------- GEMM ----------------
static constexpr int WR_F32 = 1, WR_HI = 4;

struct GemmArgs {
    int M, N, K;
    const unsigned *Ah; int lda; long long sA;
    const unsigned *Bh; int ldb; long long sB;   // B is [N][K] (NT)
    float* Cf; unsigned *Chi; int ldc; long long sC;
    const float* bias; long long sBias;
    int accum, wr;
};

// BN=128, 2 CTAs/SM, BK=32, 3-stage ring, 1-pass tf32.
__global__ void __launch_bounds__(256, 2) gemm1(GemmArgs g)
{
    constexpr int BK = 32, AW = 36, ASZ = 128 * AW, STG = 2 * ASZ, CPT = 4;
    extern __shared__ unsigned sm[];

    const int tid = threadIdx.x, lane = tid & 31, wid = tid >> 5;
    const int wm = wid >> 2, wn = wid & 3, tg = lane & 3, gid = lane >> 2;
    const int bm = blockIdx.y * 128, bn = blockIdx.x * 128;
    const long long z = blockIdx.z;

    const unsigned* Ap = g.Ah + z * g.sA;
    const unsigned* Bp = g.Bh + z * g.sB;
    const unsigned smbase = smaddr(sm);

    const int am = lane >> 3;
    const int a_row = (am & 1) * 8 + (lane & 7);
    const int a_kw  = (am >> 1) * 4;
    const int b_row = (am >> 1) * 8 + (lane & 7);
    const int b_kw  = (am & 1) * 4;
    unsigned aA[4], bA[2];
    #pragma unroll
    for (int mt = 0; mt < 4; mt++)
        aA[mt] = smbase + (unsigned)((wm*64 + mt*16 + a_row) * AW + a_kw) * 4u;
    #pragma unroll
    for (int pr = 0; pr < 2; pr++)
        bA[pr] = smbase + (unsigned)ASZ * 4u
               + (unsigned)((wn*32 + pr*16 + b_row) * AW + b_kw) * 4u;

    float acc[4][4][4];
    #pragma unroll
    for (int mt = 0; mt < 4; mt++)
        #pragma unroll
        for (int nt = 0; nt < 4; nt++)
            #pragma unroll
            for (int u = 0; u < 4; u++) acc[mt][nt][u] = 0.f;

    auto load_stage = [&](int s, int k0) {
        unsigned base = smbase + (unsigned)(s * STG) * 4u;
        #pragma unroll
        for (int j = 0; j < CPT; j++) {
            int c = tid + j * 256;
            int row = c >> 3, kc = (c & 7) * 4;
            bool ok = (bm + row) < g.M;
            const unsigned* src = ok ? Ap + (size_t)(bm + row) * g.lda + k0 + kc : Ap;
            cp16(base + (unsigned)(row * AW + kc) * 4u, src, ok);
        }
        unsigned bbase = base + (unsigned)ASZ * 4u;
        #pragma unroll
        for (int j = 0; j < CPT; j++) {
            int c = tid + j * 256;
            int row = c >> 3, kc = (c & 7) * 4;
            bool ok = (bn + row) < g.N;
            const unsigned* src = ok ? Bp + (size_t)(bn + row) * g.ldb + k0 + kc : Bp;
            cp16(bbase + (unsigned)(row * AW + kc) * 4u, src, ok);
        }
    };

    auto compute = [&](int s) {
        const unsigned so = (unsigned)(s * STG) * 4u;
        #pragma unroll
        for (int kk = 0; kk < BK; kk += 8) {
            const unsigned kb = so + (unsigned)kk * 4u;
            unsigned bh[4][2];
            #pragma unroll
            for (int pr = 0; pr < 2; pr++) {
                uint4 r = ldsm4(bA[pr] + kb);
                bh[pr*2+0][0] = r.x; bh[pr*2+0][1] = r.y;
                bh[pr*2+1][0] = r.z; bh[pr*2+1][1] = r.w;
            }
            #pragma unroll
            for (int mt = 0; mt < 4; mt++) {
                uint4 ah4 = ldsm4(aA[mt] + kb);
                #pragma unroll
                for (int nt = 0; nt < 4; nt++)
                    mma8(acc[mt][nt], (const unsigned*)&ah4, bh[nt]);
            }
        }
    };

    const int nK = g.K / BK;
    load_stage(0, 0);
    cp_commit();
    if (nK > 1) load_stage(1, BK);
    cp_commit();
    for (int kt = 0; kt < nK; kt++) {
        cp_wait<1>();
        __syncthreads();
        if (kt + 2 < nK) load_stage((kt + 2) % 3, (kt + 2) * BK);
        cp_commit();
        compute(kt % 3);
    }

    float* Cf = g.Cf + z * g.sC;
    unsigned* Chi = g.Chi + z * g.sC;
    const float* bs = g.bias ? g.bias + z * g.sBias : nullptr;
    #pragma unroll
    for (int mt = 0; mt < 4; mt++) {
        int r0 = bm + wm * 64 + mt * 16 + gid;
        int r1 = r0 + 8;
        #pragma unroll
        for (int nt = 0; nt < 4; nt++) {
            int col = bn + wn * 32 + nt * 8 + 2 * tg;
            if (col >= g.N) continue;
            float b0 = bs ? bs[col]     : 0.f;
            float b1 = bs ? bs[col + 1] : 0.f;
            #pragma unroll
            for (int half = 0; half < 2; half++) {
                int r = half ? r1 : r0;
                if (r >= g.M) continue;
                size_t o = (size_t)r * g.ldc + col;
                float v0 = acc[mt][nt][half*2+0] + b0;
                float v1 = acc[mt][nt][half*2+1] + b1;
                if (g.accum) { v0 += Cf[o]; v1 += Cf[o+1]; }
                if (g.wr & WR_F32) *(float2*)(Cf + o) = make_float2(v0, v1);
                if (g.wr & WR_HI) { Chi[o] = to_tf32(v0); Chi[o+1] = to_tf32(v1); }
            }
        }
    }
}

// ---------------- kc2 broadcast -> Ball rows 448.. ----------------
__global__ void __launch_bounds__(256) kc2b_kernel(const int* __restrict__ catids,
                                                   const float* __restrict__ cat_A)
{
    __shared__ float rows[9][Cx];
    int key = blockIdx.x;
    int v = key >> 5, s = key & 31;
    for (int u = threadIdx.x; u < 9*256; u += 256) {
        int rr = u >> 8, c4 = (u & 255) * 4;
        int srow = (rr == 0) ? key : NKMAX + (v*Rx + (rr-1))*SLOTSx + s;
        *(float4*)&rows[rr][c4] = *(const float4*)(g_skb2f + (size_t)srow*Cx + c4);
    }
    __syncthreads();
    int c = threadIdx.x * 4;
    float4 base = *(float4*)&rows[0][c];
    float4 w[Rx];
    #pragma unroll
    for (int r = 0; r < Rx; r++) w[r] = *(float4*)&rows[r+1][c];
    for (int b = 0; b < Bx; b++) {
        int cid = catids[b]; if (cid < 0) cid = 0;
        const float* ar = cat_A + (cid*Sx + v)*Rx;
        float4 o = base;
        #pragma unroll
        for (int r = 0; r < Rx; r++) {
            float a = ar[r];
            o.x += a*w[r].x; o.y += a*w[r].y; o.z += a*w[r].z; o.w += a*w[r].w;
        }
        uint4 h;
        h.x = to_tf32(o.x); h.y = to_tf32(o.y); h.z = to_tf32(o.z); h.w = to_tf32(o.w);
        *(uint4*)(g_Ball_h + ((size_t)b*NBL + NQL + key)*Cx + c) = h;
    }
}

// ---------------- vT stacked broadcast ----------------
__global__ void __launch_bounds__(320) vct_kernel(const int* __restrict__ catids,
                                                  const float* __restrict__ cat_A)
{
    __shared__ float sv[NKMAX];
    __shared__ float cbv[2560];
    int c = blockIdx.x;
    const float* src = g_svbTf + (size_t)c*NKB;
    for (int u = threadIdx.x; u < NKB; u += 320) {
        float vle = src[u];
        if (u < NKMAX) sv[u] = vle; else cbv[u - NKMAX] = vle;
    }
    __syncthreads();
    int key = threadIdx.x;
    int v = key >> 5, s = key & 31;
    float base = sv[key];
    unsigned base_h = to_tf32(base);
    float w[Rx];
    #pragma unroll
    for (int r = 0; r < Rx; r++) w[r] = cbv[(v*Rx + r)*SLOTSx + s];
    for (int b = 0; b < Bx; b++) {
        int cid = catids[b]; if (cid < 0) cid = 0;
        const float* ar = cat_A + (cid*Sx + v)*Rx;
        float acc = base;
        #pragma unroll
        for (int r = 0; r < Rx; r++) acc += ar[r] * w[r];
        size_t o = ((size_t)b*Cx + c)*NK2;
        g_vT_h[o + key] = base_h;
        g_vT_h[o + NKMAX + key] = to_tf32(acc);
    }
}

// ---------------- alpha constant tables ----------------
__global__ void aconst_kernel(const float* __restrict__ cat_emb,
                              const float* __restrict__ scale_emb,
                              const float* __restrict__ aW1,
                              const float* __restrict__ ab1)
{
    int idx = blockIdx.x, h = threadIdx.x;
    if (idx < NCATx) {
        float acc = 0.f;
        const float* ce = cat_emb + (size_t)idx * Cx;
        for (int c = 0; c < Cx; c++)
            acc += ce[c] * aW1[(size_t)(Cx + c)*AHx + h];
        g_acat[idx*AHx + h] = acc;
    } else {
        int i = idx - NCATx;
        float acc = ab1[h];
        const float* se = scale_emb + (size_t)i * Cx;
        for (int c = 0; c < Cx; c++)
            acc += se[c] * aW1[(size_t)(2*Cx + c)*AHx + h];
        g_ascale[i*AHx + h] = acc;
    }
}

// ---------------- alpha + masked softmax -> stacked P hi planes ----------------
__global__ void __launch_bounds__(256) softmax_kernel(const int* __restrict__ catids,
                                                      const float* __restrict__ aW2,
                                                      const float* __restrict__ ab2)
{
    int w = threadIdx.x >> 5, lane = threadIdx.x & 31;
    int row = blockIdx.x * 8 + w;
    if (row >= NROW) return;
    int b = row / Lx, l = row % Lx;
    int i = 0;
    #pragma unroll
    for (int u = 1; u < 10; u++) if (l >= c_begin[u]) i = u;
    int nk = (i + 1) * SLOTSx;
    float ls = g_scal[0];
    const float* qrow = g_qlgf + (size_t)row * NBL;

    int cid = catids[b];
    float a = 0.f;
    if (cid >= 0) {
        const float* ac = g_acat + cid*AHx;
        const float* as = g_ascale + i*AHx;
        float acc = 0.f;
        #pragma unroll
        for (int h = lane; h < AHx; h += 32) {
            float xv = qrow[h] + ac[h] + as[h];
            float ge = 0.5f*xv*(1.0f + erff(xv*0.70710678118654752f));
            acc += ge * aW2[h];
        }
        #pragma unroll
        for (int o = 16; o > 0; o >>= 1) acc += __shfl_xor_sync(0xffffffffu, acc, o);
        a = 1.0f/(1.0f + expf(-(acc + ab2[0])));
    }

    #pragma unroll
    for (int s = 0; s < 2; s++) {
        const float* p = qrow + AHx + s * NKMAX;
        unsigned* q = g_P_h + (size_t)row * NK2 + s * NKMAX;
        float wgt = s ? a : (1.0f - a);
        float v[10];
        int cnt = 0;
        float mx = -3.4e38f;
        for (int j = lane; j < nk; j += 32) { float t = p[j]*ls; v[cnt++] = t; mx = fmaxf(mx, t); }
        #pragma unroll
        for (int o = 16; o > 0; o >>= 1) mx = fmaxf(mx, __shfl_xor_sync(0xffffffffu, mx, o));
        float sum = 0.f;
        for (int c2 = 0; c2 < cnt; c2++) { v[c2] = expf(v[c2] - mx); sum += v[c2]; }
        #pragma unroll
        for (int o = 16; o > 0; o >>= 1) sum += __shfl_xor_sync(0xffffffffu, sum, o);
        float inv = wgt / sum;
        cnt = 0;
        for (int j = lane; j < NKMAX; j += 32)
            q[j] = (j < nk) ? to_tf32(v[cnt++] * inv) : 0u;
    }
}

// ---------------- tail ----------------
__global__ void tail_kernel(float* out, int n2, int total) {
    int idx = n2 + blockIdx.x*blockDim.x + threadIdx.x;
    if (idx < total) out[idx] = 0.f;
}

// ---------------- host helpers ----------------
static void launch_gemm(int M, int N, int K,
                        const unsigned* Ah, int lda, long long sA,
                        const unsigned* Bh, int ldb, long long sB,
                        float* Cf, unsigned* Chi, int ldc, long long sC,
                        const float* bias, long long sBias,
                        int accum, int wr, int batches)
{
    GemmArgs g;
    g.M=M; g.N=N; g.K=K;
    g.Ah=Ah; g.lda=lda; g.sA=sA;
    g.Bh=Bh; g.ldb=ldb; g.sB=sB;
    g.Cf=Cf; g.Chi=Chi; g.ldc=ldc; g.sC=sC;
    g.bias=bias; g.sBias=sBias; g.accum=accum; g.wr=wr;
    dim3 grid((N + 127)/128, (M + 127)/128, batches);
    gemm1<<<grid, 256, 110592>>>(g);
}

static void launch_tsplit(const float* in, int R, int C, unsigned* oh, unsigned* ol,
                          const float* gate)
{
    dim3 grid((C + 31)/32, (R + 31)/32);
    tsplit_kernel<<<grid, dim3(32, 8)>>>(in, R, C, oh, ol, gate);
}

// ---------------- launch ----------------
extern "C" void kernel_launch(void* const* d_in, const int* in_sizes, int n_in,
                              void* d_out, int out_size) {
    const float* x        = (const float*)d_in[0];
    const int*   catids   = (const int*)  d_in[1];
    const float* shmem    = (const float*)d_in[2];
    const float* cat_A    = (const float*)d_in[3];
    const float* cat_B    = (const float*)d_in[4];
    const float* cat_emb  = (const float*)d_in[5];
    const float* scale_emb= (const float*)d_in[6];
    const float* Wq       = (const float*)d_in[7];
    const float* Wk       = (const float*)d_in[8];
    const float* Wv       = (const float*)d_in[9];
    const float* aW1      = (const float*)d_in[10];
    const float* ab1      = (const float*)d_in[11];
    const float* aW2      = (const float*)d_in[12];
    const float* ab2      = (const float*)d_in[13];
    const float* kW1      = (const float*)d_in[14];
    const float* kb1      = (const float*)d_in[15];
    const float* kW2      = (const float*)d_in[16];
    const float* kb2      = (const float*)d_in[17];
    const float* vW1      = (const float*)d_in[18];
    const float* vb1      = (const float*)d_in[19];
    const float* vW2      = (const float*)d_in[20];
    const float* vb2      = (const float*)d_in[21];
    const float* gk       = (const float*)d_in[22];
    const float* gv       = (const float*)d_in[23];
    const float* lt       = (const float*)d_in[24];

    cudaFuncSetAttribute(gemm1, cudaFuncAttributeMaxDynamicSharedMemorySize, 110592);

    #define SYM(t, p, s) t p; cudaGetSymbolAddress((void**)&p, s)
    SYM(unsigned*, p_x_h, g_x_h);
    SYM(unsigned*, p_Wq_rm, g_Wq_rm_h);
    SYM(unsigned*, p_Wk_rm, g_Wk_rm_h);
    SYM(unsigned*, p_G_h, g_G_h);
    SYM(unsigned*, p_BQ_h, g_BQ_h);
    SYM(unsigned*, p_Ball_h, g_Ball_h);
    SYM(unsigned*, p_WvT_h, g_WvT_h); SYM(unsigned*, p_WvT_l, g_WvT_l);
    SYM(unsigned*, p_aW1T_h, g_aW1T_h); SYM(unsigned*, p_aW1T_l, g_aW1T_l);
    SYM(unsigned*, p_w1T_h, g_w1T_h); SYM(unsigned*, p_w1T_l, g_w1T_l);
    SYM(unsigned*, p_W2gT_h, g_W2gT_h); SYM(unsigned*, p_W2gT_l, g_W2gT_l);
    SYM(unsigned*, p_skb_in, g_skb_in_h);
    SYM(float*,    p_skb2f, g_skb2f);
    SYM(unsigned*, p_skb2h, g_skb2h);
    SYM(float*,    p_svbTf, g_svbTf);
    SYM(unsigned*, p_vT_h, g_vT_h);
    SYM(float*,    p_qlgf, g_qlgf);
    SYM(unsigned*, p_P_h, g_P_h);
    SYM(float*,    p_memf, g_memf);
    SYM(unsigned*, p_mem_h, g_mem_h);
    SYM(unsigned*, p_t1_h, g_t1_h);
    SYM(float*,    p_scal, g_scal);
    SYM(float*,    p_bias1, g_bias1);
    SYM(float*,    p_bias2, g_bias2);
    #undef SYM

    prep_kernel<<<1, 1>>>(gk, gv, lt);
    bias2_kernel<<<4, 256>>>(kb2, vb2);

    // -------- operand preparation --------
    cvt_kernel<<<(NQ/4 + 255)/256, 256>>>(x, p_x_h, NQ/4);
    cvt_kernel<<<(NKMAX*Cx/4 + 255)/256, 256>>>(shmem, p_skb_in, NKMAX*Cx/4);
    cvt_kernel<<<(2560*Cx/4 + 255)/256, 256>>>(cat_B, p_skb_in + NKMAX*Cx, 2560*Cx/4);
    cvt_kernel<<<(Cx*Cx/4 + 255)/256, 256>>>(Wq, p_Wq_rm, Cx*Cx/4);
    cvt_kernel<<<(Cx*Cx/4 + 255)/256, 256>>>(Wk, p_Wk_rm, Cx*Cx/4);
    launch_tsplit(Wv, Cx, Cx, p_WvT_h, p_WvT_l, nullptr);
    launch_tsplit(aW1, Cx, AHx, p_aW1T_h, p_aW1T_l, nullptr);
    launch_tsplit(kW1, Cx, MRx, p_w1T_h, p_w1T_l, nullptr);
    launch_tsplit(vW1, Cx, MRx, p_w1T_h + MRx*Cx, p_w1T_l + MRx*Cx, nullptr);
    launch_tsplit(kW2, MRx, Cx, p_W2gT_h, p_W2gT_l, p_scal + 1);
    launch_tsplit(vW2, MRx, Cx, p_W2gT_h + Cx*MRx, p_W2gT_l + Cx*MRx, p_scal + 2);
    cudaMemcpyAsync(p_bias1, kb1, MRx*sizeof(float), cudaMemcpyDeviceToDevice);
    cudaMemcpyAsync(p_bias1 + MRx, vb1, MRx*sizeof(float), cudaMemcpyDeviceToDevice);

    // -------- folded weight GEMMs --------
    // G[c][e] = sum_d Wq[c][d] Wk[e][d]
    launch_gemm(Cx, Cx, Cx, p_Wq_rm, Cx, 0, p_Wk_rm, Cx, 0,
                p_skb2f, p_G_h, Cx, 0, nullptr, 0, 0, WR_HI, 1);
    // [svT|cbvT] = WvT @ [shm;cat_B]^T
    launch_gemm(Cx, NKB, Cx, p_WvT_h, Cx, 0, p_skb_in, Cx, 0,
                p_svbTf, p_G_h, NKB, 0, nullptr, 0, 0, WR_F32, 1);
    // skb2 = skbin @ G^T  (rows 0..319 = FsT)
    launch_gemm(NKB, Cx, Cx, p_skb_in, Cx, 0, p_G_h, Cx, 0,
                p_skb2f, p_skb2h, Cx, 0, nullptr, 0, 0, WR_F32|WR_HI, 1);
    // FaT -> BQ rows 0..127
    launch_gemm(AHx, Cx, Cx, p_aW1T_h, Cx, 0, p_Wq_rm, Cx, 0,
                p_memf, p_BQ_h, Cx, 0, nullptr, 0, 0, WR_HI, 1);
    // FsT -> BQ rows 128..447
    copyu_kernel<<<(NKMAX*Cx/4 + 255)/256, 256>>>(p_skb2h, p_BQ_h + AHx*Cx, NKMAX*Cx/4);

    // broadcast BQ into Ball; kc2 rows into Ball[448..]
    bqbc_kernel<<<dim3((NQL*Cx/4 + 255)/256, Bx), 256>>>();
    kc2b_kernel<<<NKMAX, 256>>>(catids, cat_A);
    vct_kernel<<<Cx, 320>>>(catids, cat_A);
    aconst_kernel<<<NCATx + Sx, AHx>>>(cat_emb, scale_emb, aW1, ab1);

    // qh|lgs|lgc = x @ Ball^T (batched, N=768 exact tiles)
    launch_gemm(Lx, NBL, Cx, p_x_h, Cx, (long long)Lx*Cx,
                p_Ball_h, Cx, (long long)NBL*Cx,
                p_qlgf, p_P_h, NBL, (long long)Lx*NBL, nullptr, 0, 0, WR_F32, Bx);

    softmax_kernel<<<(NROW + 7)/8, 256>>>(catids, aW2, ab2);

    // mem = P @ vT^T (batched, K=640) -> hi plane only
    launch_gemm(Lx, Cx, NK2, p_P_h, NK2, (long long)Lx*NK2,
                p_vT_h, NK2, (long long)Cx*NK2,
                p_memf, p_mem_h, Cx, (long long)Lx*Cx, nullptr, 0, 0, WR_HI, Bx);

    // heads
    launch_gemm(NROW, 2*MRx, Cx, p_mem_h, Cx, 0, p_w1T_h, Cx, 0,
                p_memf, p_t1_h, 2*MRx, 0, p_bias1, 0, 0, WR_HI, 1);
    launch_gemm(NROW, Cx, MRx, p_t1_h, 2*MRx, MRx,
                p_W2gT_h, MRx, (long long)Cx*MRx,
                (float*)d_out, p_mem_h, Cx, (long long)NROW*Cx,
                p_bias2, Cx, 0, WR_F32, 2);

    tail_kernel<<<1, 256>>>((float*)d_out, 2 * NROW * Cx, out_size);
}

// round 16
// speedup vs baseline: 2.2740x; 1.0111x over previous
#include <cuda_runtime.h>
#include <math.h>

// ---------------- problem constants ----------------
static constexpr int Bx = 32, Lx = 680, Cx = 1024;
static constexpr int Sx = 10, SLOTSx = 32, Rx = 8, NCATx = 22;
static constexpr int MRx = 64, AHx = 128;
static constexpr int NROW = Bx * Lx;            // 21760
static constexpr int NKMAX = Sx * SLOTSx;       // 320
static constexpr int NQ = NROW * Cx;            // 22282240
static constexpr int NKB = NKMAX + 2560;        // 2880
static constexpr int NQL = AHx + NKMAX;         // 448
static constexpr int NBL = NQL + NKMAX;         // 768
static constexpr int NK2 = 2 * NKMAX;           // 640
static constexpr int LMAIN = 640;               // 5*128
static constexpr int LTAIL = Lx - LMAIN;        // 40

__constant__ int c_begin[10] = {0,1,5,14,30,55,91,155,255,424};

// ---------------- device scratch ----------------
__device__ unsigned g_x_h[NQ];
__device__ unsigned g_Wq_rm_h[Cx*Cx];
__device__ unsigned g_Wk_rm_h[Cx*Cx];
__device__ unsigned g_G_h[Cx*Cx];
__device__ unsigned g_BQ_h[NQL*Cx];                // [FaT(128) ; FsT(320)]
__device__ unsigned g_kc2_h[(size_t)Bx*NKMAX*Cx];
__device__ unsigned g_WvT_h[Cx*Cx], g_WvT_l[Cx*Cx];
__device__ unsigned g_aW1T_h[AHx*Cx], g_aW1T_l[AHx*Cx];
__device__ unsigned g_w1T_h[(2*MRx)*Cx], g_w1T_l[(2*MRx)*Cx];
__device__ unsigned g_W2gT_h[2*Cx*MRx], g_W2gT_l[2*Cx*MRx];
__device__ unsigned g_skb_in_h[NKB*Cx];

__device__ float    g_skb2f[NKB*Cx];
__device__ unsigned g_skb2h[NKB*Cx];
__device__ float    g_svbTf[Cx*NKB];
__device__ unsigned g_vT_h[(size_t)Bx*Cx*NK2];
__device__ float    g_qlgf[(size_t)NROW*NBL];      // qh | lgs | lgc
__device__ unsigned g_P_h[NROW*NK2];
__device__ float    g_memf[NQ];
__device__ unsigned g_mem_h[NQ];
__device__ unsigned g_t1_h[NROW*(2*MRx)];
__device__ float    g_acat[NCATx*AHx];
__device__ float    g_ascale[Sx*AHx];
__device__ float    g_scal[4];
__device__ float    g_bias1[2*MRx];
__device__ float    g_bias2[2*Cx];

// ---------------- helpers ----------------
__device__ __forceinline__ void split_tf32(float x, unsigned& hi, unsigned& lo) {
    unsigned h; asm("cvt.rna.tf32.f32 %0, %1;" : "=r"(h) : "f"(x));
    float hf = __uint_as_float(h);
    unsigned l; asm("cvt.rna.tf32.f32 %0, %1;" : "=r"(l) : "f"(x - hf));
    hi = h; lo = l;
}
__device__ __forceinline__ unsigned to_tf32(float x) {
    unsigned h; asm("cvt.rna.tf32.f32 %0, %1;" : "=r"(h) : "f"(x)); return h;
}
__device__ __forceinline__ void mma8(float* d, const unsigned* a, const unsigned* b) {
    asm volatile(
        "mma.sync.aligned.m16n8k8.row.col.f32.tf32.tf32.f32 "
        "{%0,%1,%2,%3}, {%4,%5,%6,%7}, {%8,%9}, {%0,%1,%2,%3};"
        : "+f"(d[0]), "+f"(d[1]), "+f"(d[2]), "+f"(d[3])
        : "r"(a[0]), "r"(a[1]), "r"(a[2]), "r"(a[3]), "r"(b[0]), "r"(b[1]));
}
__device__ __forceinline__ uint4 ldsm4(unsigned a) {
    uint4 r;
    asm volatile("ldmatrix.sync.aligned.m8n8.x4.shared.b16 {%0,%1,%2,%3}, [%4];"
        : "=r"(r.x), "=r"(r.y), "=r"(r.z), "=r"(r.w) : "r"(a));
    return r;
}
__device__ __forceinline__ unsigned smaddr(const void* p) {
    unsigned a;
    asm("{.reg .u64 u; cvta.to.shared.u64 u, %1; cvt.u32.u64 %0, u;}" : "=r"(a) : "l"(p));
    return a;
}
__device__ __forceinline__ void cp16(unsigned dst, const void* src, bool ok) {
    int sz = ok ? 16 : 0;
    asm volatile("cp.async.cg.shared.global [%0], [%1], 16, %2;\n" :: "r"(dst), "l"(src), "r"(sz));
}
__device__ __forceinline__ void cp_commit() { asm volatile("cp.async.commit_group;"); }
template<int N> __device__ __forceinline__ void cp_wait() {
    asm volatile("cp.async.wait_group %0;" :: "n"(N));
}

// ---------------- prep ----------------
__global__ void prep_kernel(const float* gk, const float* gv, const float* lt) {
    float temp = expf(lt[0]);
    temp = fminf(fmaxf(temp, 0.05f), 1.0f);
    g_scal[0] = (1.0f / 32.0f) / temp;
    g_scal[1] = 1.0f / (1.0f + expf(-gk[0]));
    g_scal[2] = 1.0f / (1.0f + expf(-gv[0]));
}
__global__ void bias2_kernel(const float* kb2, const float* vb2,
                             const float* kb1, const float* vb1) {
    int c = blockIdx.x * 256 + threadIdx.x;
    if (c < Cx) {
        g_bias2[c]      = g_scal[1] * kb2[c];
        g_bias2[Cx + c] = g_scal[2] * vb2[c];
    }
    if (c < MRx) {
        g_bias1[c] = kb1[c];
        g_bias1[MRx + c] = vb1[c];
    }
}

// ---------------- fp32 -> tf32 hi plane ----------------
__global__ void cvt_kernel(const float* __restrict__ in, unsigned* __restrict__ hi, int n4) {
    int i = blockIdx.x * 256 + threadIdx.x;
    if (i >= n4) return;
    float4 v = ((const float4*)in)[i];
    uint4 h;
    h.x = to_tf32(v.x); h.y = to_tf32(v.y); h.z = to_tf32(v.z); h.w = to_tf32(v.w);
    ((uint4*)hi)[i] = h;
}
__global__ void copyu_kernel(const unsigned* __restrict__ src, unsigned* __restrict__ dst, int n4) {
    int i = blockIdx.x * 256 + threadIdx.x;
    if (i < n4) ((uint4*)dst)[i] = ((const uint4*)src)[i];
}

// ---------------- transpose + split (optional gate) ----------------
__global__ void tsplit_kernel(const float* __restrict__ in, int R, int C,
                              unsigned* __restrict__ oh, unsigned* __restrict__ ol,
                              const float* __restrict__ gate)
{
    __shared__ float t[32][33];
    int r0 = blockIdx.y * 32, c0 = blockIdx.x * 32;
    int tx = threadIdx.x, ty = threadIdx.y;
    float gt = gate ? *gate : 1.0f;
    #pragma unroll
    for (int i = 0; i < 32; i += 8) {
        int r = r0 + ty + i;
        t[ty + i][tx] = (r < R && c0 + tx < C) ? gt * in[(size_t)r * C + c0 + tx] : 0.f;
    }
    __syncthreads();
    #pragma unroll
    for (int i = 0; i < 32; i += 8) {
        int c = c0 + ty + i, r = r0 + tx;
        if (c < C && r < R) {
            unsigned h, l; split_tf32(t[tx][ty + i], h, l);
            oh[(size_t)c * R + r] = h;
            ol[(size_t)c * R + r] = l;
        }
    }
}

// ---------------- GEMM ----------------
static constexpr int WR_F32 = 1, WR_HI = 4;

struct GemmArgs {
    int M, N, K;
    const unsigned *Ah; int lda; long long sA;
    const unsigned *Bh; int nb1;               // B rows [0,nb1) from Bh (shared)
    const unsigned *Bh2; int ldb; long long sB; // B rows [nb1,N) from Bh2 (z-strided)
    float* Cf; unsigned *Chi; int ldc; long long sC;
    const float* bias; long long sBias;
    int wr;
};

// MT=4 -> BM=128, MT=2 -> BM=64. BN=128, BK=32, 3-stage, 1-pass tf32.
template<int MT>
__global__ void __launch_bounds__(256, 2) gemm_t(GemmArgs g)
{
    constexpr int BK = 32, AW = 36;
    constexpr int BM = MT * 32;
    constexpr int ASZ = BM * AW, BSZ = 128 * AW, STG = ASZ + BSZ;
    constexpr int ACPT = BM / 32;
    extern __shared__ unsigned sm[];

    const int tid = threadIdx.x, lane = tid & 31, wid = tid >> 5;
    const int wm = wid >> 2, wn = wid & 3, tg = lane & 3, gid = lane >> 2;
    const int bm = blockIdx.y * BM, bn = blockIdx.x * 128;
    const long long z = blockIdx.z;

    const unsigned* Ap = g.Ah + z * g.sA;
    const unsigned* Bp2 = g.Bh2 + z * g.sB;
    const unsigned smbase = smaddr(sm);

    const int am = lane >> 3;
    const int a_row = (am & 1) * 8 + (lane & 7);
    const int a_kw  = (am >> 1) * 4;
    const int b_row = (am >> 1) * 8 + (lane & 7);
    const int b_kw  = (am & 1) * 4;
    unsigned aA[MT], bA[2];
    #pragma unroll
    for (int mt = 0; mt < MT; mt++)
        aA[mt] = smbase + (unsigned)((wm*(MT*16) + mt*16 + a_row) * AW + a_kw) * 4u;
    #pragma unroll
    for (int pr = 0; pr < 2; pr++)
        bA[pr] = smbase + (unsigned)ASZ * 4u
               + (unsigned)((wn*32 + pr*16 + b_row) * AW + b_kw) * 4u;

    float acc[MT][4][4];
    #pragma unroll
    for (int mt = 0; mt < MT; mt++)
        #pragma unroll
        for (int nt = 0; nt < 4; nt++)
            #pragma unroll
            for (int u = 0; u < 4; u++) acc[mt][nt][u] = 0.f;

    auto load_stage = [&](int s, int k0) {
        unsigned base = smbase + (unsigned)(s * STG) * 4u;
        #pragma unroll
        for (int j = 0; j < ACPT; j++) {
            int c = tid + j * 256;
            int row = c >> 3, kc = (c & 7) * 4;
            bool ok = (bm + row) < g.M;
            const unsigned* src = ok ? Ap + (size_t)(bm + row) * g.lda + k0 + kc : Ap;
            cp16(base + (unsigned)(row * AW + kc) * 4u, src, ok);
        }
        unsigned bbase = base + (unsigned)ASZ * 4u;
        #pragma unroll
        for (int j = 0; j < 4; j++) {
            int c = tid + j * 256;
            int row = c >> 3, kc = (c & 7) * 4;
            int grow = bn + row;
            bool ok = grow < g.N;
            const unsigned* src;
            if (grow < g.nb1) src = g.Bh + (size_t)grow * g.ldb + k0 + kc;
            else              src = Bp2 + (size_t)(grow - g.nb1) * g.ldb + k0 + kc;
            if (!ok) src = Ap;
            cp16(bbase + (unsigned)(row * AW + kc) * 4u, src, ok);
        }
    };

    auto compute = [&](int s) {
        const unsigned so = (unsigned)(s * STG) * 4u;
        #pragma unroll
        for (int kk = 0; kk < BK; kk += 8) {
            const unsigned kb = so + (unsigned)kk * 4u;
            unsigned bh[4][2];
            #pragma unroll
            for (int pr = 0; pr < 2; pr++) {
                uint4 r = ldsm4(bA[pr] + kb);
                bh[pr*2+0][0] = r.x; bh[pr*2+0][1] = r.y;
                bh[pr*2+1][0] = r.z; bh[pr*2+1][1] = r.w;
            }
            #pragma unroll
            for (int mt = 0; mt < MT; mt++) {
                uint4 ah4 = ldsm4(aA[mt] + kb);
                #pragma unroll
                for (int nt = 0; nt < 4; nt++)
                    mma8(acc[mt][nt], (const unsigned*)&ah4, bh[nt]);
            }
        }
    };

    const int nK = g.K / BK;
    load_stage(0, 0);
    cp_commit();
    if (nK > 1) load_stage(1, BK);
    cp_commit();
    for (int kt = 0; kt < nK; kt++) {
        cp_wait<1>();
        __syncthreads();
        if (kt + 2 < nK) load_stage((kt + 2) % 3, (kt + 2) * BK);
        cp_commit();
        compute(kt % 3);
    }

    float* Cf = g.Cf + z * g.sC;
    unsigned* Chi = g.Chi + z * g.sC;
    const float* bs = g.bias ? g.bias + z * g.sBias : nullptr;
    #pragma unroll
    for (int mt = 0; mt < MT; mt++) {
        int r0 = bm + wm * (MT*16) + mt * 16 + gid;
        int r1 = r0 + 8;
        #pragma unroll
        for (int nt = 0; nt < 4; nt++) {
            int col = bn + wn * 32 + nt * 8 + 2 * tg;
            if (col >= g.N) continue;
            float b0 = bs ? bs[col]     : 0.f;
            float b1 = bs ? bs[col + 1] : 0.f;
            #pragma unroll
            for (int half = 0; half < 2; half++) {
                int r = half ? r1 : r0;
                if (r >= g.M) continue;
                size_t o = (size_t)r * g.ldc + col;
                float v0 = acc[mt][nt][half*2+0] + b0;
                float v1 = acc[mt][nt][half*2+1] + b1;
                if (g.wr & WR_F32) *(float2*)(Cf + o) = make_float2(v0, v1);
                if (g.wr & WR_HI) { Chi[o] = to_tf32(v0); Chi[o+1] = to_tf32(v1); }
            }
        }
    }
}

// ---------------- kc2 broadcast ----------------
__global__ void __launch_bounds__(256) kc2b_kernel(const int* __restrict__ catids,
                                                   const float* __restrict__ cat_A)
{
    __shared__ float rows[9][Cx];
    int key = blockIdx.x;
    int v = key >> 5, s = key & 31;
    for (int u = threadIdx.x; u < 9*256; u += 256) {
        int rr = u >> 8, c4 = (u & 255) * 4;
        int srow = (rr == 0) ? key : NKMAX + (v*Rx + (rr-1))*SLOTSx + s;
        *(float4*)&rows[rr][c4] = *(const float4*)(g_skb2f + (size_t)srow*Cx + c4);
    }
    __syncthreads();
    int c = threadIdx.x * 4;
    float4 base = *(float4*)&rows[0][c];
    float4 w[Rx];
    #pragma unroll
    for (int r = 0; r < Rx; r++) w[r] = *(float4*)&rows[r+1][c];
    for (int b = 0; b < Bx; b++) {
        int cid = catids[b]; if (cid < 0) cid = 0;
        const float* ar = cat_A + (cid*Sx + v)*Rx;
        float4 o = base;
        #pragma unroll
        for (int r = 0; r < Rx; r++) {
            float a = ar[r];
            o.x += a*w[r].x; o.y += a*w[r].y; o.z += a*w[r].z; o.w += a*w[r].w;
        }
        uint4 h;
        h.x = to_tf32(o.x); h.y = to_tf32(o.y); h.z = to_tf32(o.z); h.w = to_tf32(o.w);
        *(uint4*)(g_kc2_h + ((size_t)b*NKMAX + key)*Cx + c) = h;
    }
}

// ---------------- vT stacked broadcast ----------------
__global__ void __launch_bounds__(320) vct_kernel(const int* __restrict__ catids,
                                                  const float* __restrict__ cat_A)
{
    __shared__ float sv[NKMAX];
    __shared__ float cbv[2560];
    int c = blockIdx.x;
    const float* src = g_svbTf + (size_t)c*NKB;
    for (int u = threadIdx.x; u < NKB; u += 320) {
        float vle = src[u];
        if (u < NKMAX) sv[u] = vle; else cbv[u - NKMAX] = vle;
    }
    __syncthreads();
    int key = threadIdx.x;
    int v = key >> 5, s = key & 31;
    float base = sv[key];
    unsigned base_h = to_tf32(base);
    float w[Rx];
    #pragma unroll
    for (int r = 0; r < Rx; r++) w[r] = cbv[(v*Rx + r)*SLOTSx + s];
    for (int b = 0; b < Bx; b++) {
        int cid = catids[b]; if (cid < 0) cid = 0;
        const float* ar = cat_A + (cid*Sx + v)*Rx;
        float acc = base;
        #pragma unroll
        for (int r = 0; r < Rx; r++) acc += ar[r] * w[r];
        size_t o = ((size_t)b*Cx + c)*NK2;
        g_vT_h[o + key] = base_h;
        g_vT_h[o + NKMAX + key] = to_tf32(acc);
    }
}

// ---------------- alpha constant tables ----------------
__global__ void aconst_kernel(const float* __restrict__ cat_emb,
                              const float* __restrict__ scale_emb,
                              const float* __restrict__ aW1,
                              const float* __restrict__ ab1)
{
    int idx = blockIdx.x, h = threadIdx.x;
    if (idx < NCATx) {
        float acc = 0.f;
        const float* ce = cat_emb + (size_t)idx * Cx;
        for (int c = 0; c < Cx; c++)
            acc += ce[c] * aW1[(size_t)(Cx + c)*AHx + h];
        g_acat[idx*AHx + h] = acc;
    } else {
        int i = idx - NCATx;
        float acc = ab1[h];
        const float* se = scale_emb + (size_t)i * Cx;
        for (int c = 0; c < Cx; c++)
            acc += se[c] * aW1[(size_t)(2*Cx + c)*AHx + h];
        g_ascale[i*AHx + h] = acc;
    }
}

// ---------------- alpha + masked softmax -> stacked P hi planes ----------------
__global__ void __launch_bounds__(256) softmax_kernel(const int* __restrict__ catids,
                                                      const float* __restrict__ aW2,
                                                      const float* __restrict__ ab2)
{
    int w = threadIdx.x >> 5, lane = threadIdx.x & 31;
    int row = blockIdx.x * 8 + w;
    if (row >= NROW) return;
    int b = row / Lx, l = row % Lx;
    int i = 0;
    #pragma unroll
    for (int u = 1; u < 10; u++) if (l >= c_begin[u]) i = u;
    int nk = (i + 1) * SLOTSx;
    float ls = g_scal[0];
    const float* qrow = g_qlgf + (size_t)row * NBL;

    int cid = catids[b];
    float a = 0.f;
    if (cid >= 0) {
        const float* ac = g_acat + cid*AHx;
        const float* as = g_ascale + i*AHx;
        float acc = 0.f;
        #pragma unroll
        for (int h = lane; h < AHx; h += 32) {
            float xv = qrow[h] + ac[h] + as[h];
            float ge = 0.5f*xv*(1.0f + erff(xv*0.70710678118654752f));
            acc += ge * aW2[h];
        }
        #pragma unroll
        for (int o = 16; o > 0; o >>= 1) acc += __shfl_xor_sync(0xffffffffu, acc, o);
        a = 1.0f/(1.0f + expf(-(acc + ab2[0])));
    }

    #pragma unroll
    for (int s = 0; s < 2; s++) {
        const float* p = qrow + AHx + s * NKMAX;
        unsigned* q = g_P_h + (size_t)row * NK2 + s * NKMAX;
        float wgt = s ? a : (1.0f - a);
        float v[10];
        int cnt = 0;
        float mx = -3.4e38f;
        for (int j = lane; j < nk; j += 32) { float t = p[j]*ls; v[cnt++] = t; mx = fmaxf(mx, t); }
        #pragma unroll
        for (int o = 16; o > 0; o >>= 1) mx = fmaxf(mx, __shfl_xor_sync(0xffffffffu, mx, o));
        float sum = 0.f;
        for (int c2 = 0; c2 < cnt; c2++) { v[c2] = expf(v[c2] - mx); sum += v[c2]; }
        #pragma unroll
        for (int o = 16; o > 0; o >>= 1) sum += __shfl_xor_sync(0xffffffffu, sum, o);
        float inv = wgt / sum;
        cnt = 0;
        for (int j = lane; j < NKMAX; j += 32)
            q[j] = (j < nk) ? to_tf32(v[cnt++] * inv) : 0u;
    }
}

// ---------------- tail ----------------
__global__ void tail_kernel(float* out, int n2, int total) {
    int idx = n2 + blockIdx.x*blockDim.x + threadIdx.x;
    if (idx < total) out[idx] = 0.f;
}

// ---------------- host helpers ----------------
static void launch_g(int mt, int M, int N, int K,
                     const unsigned* Ah, int lda, long long sA,
                     const unsigned* Bh, int nb1, const unsigned* Bh2, int ldb, long long sB,
                     float* Cf, unsigned* Chi, int ldc, long long sC,
                     const float* bias, long long sBias, int wr, int batches)
{
    GemmArgs g;
    g.M=M; g.N=N; g.K=K;
    g.Ah=Ah; g.lda=lda; g.sA=sA;
    g.Bh=Bh; g.nb1=nb1; g.Bh2=Bh2; g.ldb=ldb; g.sB=sB;
    g.Cf=Cf; g.Chi=Chi; g.ldc=ldc; g.sC=sC;
    g.bias=bias; g.sBias=sBias; g.wr=wr;
    if (mt == 4) {
        dim3 grid((N + 127)/128, (M + 127)/128, batches);
        gemm_t<4><<<grid, 256, 110592>>>(g);
    } else {
        dim3 grid((N + 127)/128, (M + 63)/64, batches);
        gemm_t<2><<<grid, 256, 82944>>>(g);
    }
}

static void launch_tsplit(const float* in, int R, int C, unsigned* oh, unsigned* ol,
                          const float* gate)
{
    dim3 grid((C + 31)/32, (R + 31)/32);
    tsplit_kernel<<<grid, dim3(32, 8)>>>(in, R, C, oh, ol, gate);
}

// ---------------- launch ----------------
extern "C" void kernel_launch(void* const* d_in, const int* in_sizes, int n_in,
                              void* d_out, int out_size) {
    const float* x        = (const float*)d_in[0];
    const int*   catids   = (const int*)  d_in[1];
    const float* shmem    = (const float*)d_in[2];
    const float* cat_A    = (const float*)d_in[3];
    const float* cat_B    = (const float*)d_in[4];
    const float* cat_emb  = (const float*)d_in[5];
    const float* scale_emb= (const float*)d_in[6];
    const float* Wq       = (const float*)d_in[7];
    const float* Wk       = (const float*)d_in[8];
    const float* Wv       = (const float*)d_in[9];
    const float* aW1      = (const float*)d_in[10];
    const float* ab1      = (const float*)d_in[11];
    const float* aW2      = (const float*)d_in[12];
    const float* ab2      = (const float*)d_in[13];
    const float* kW1      = (const float*)d_in[14];
    const float* kb1      = (const float*)d_in[15];
    const float* kW2      = (const float*)d_in[16];
    const float* kb2      = (const float*)d_in[17];
    const float* vW1      = (const float*)d_in[18];
    const float* vb1      = (const float*)d_in[19];
    const float* vW2      = (const float*)d_in[20];
    const float* vb2      = (const float*)d_in[21];
    const float* gk       = (const float*)d_in[22];
    const float* gv       = (const float*)d_in[23];
    const float* lt       = (const float*)d_in[24];

    cudaFuncSetAttribute(gemm_t<4>, cudaFuncAttributeMaxDynamicSharedMemorySize, 110592);
    cudaFuncSetAttribute(gemm_t<2>, cudaFuncAttributeMaxDynamicSharedMemorySize, 82944);

    #define SYM(t, p, s) t p; cudaGetSymbolAddress((void**)&p, s)
    SYM(unsigned*, p_x_h, g_x_h);
    SYM(unsigned*, p_Wq_rm, g_Wq_rm_h);
    SYM(unsigned*, p_Wk_rm, g_Wk_rm_h);
    SYM(unsigned*, p_G_h, g_G_h);
    SYM(unsigned*, p_BQ_h, g_BQ_h);
    SYM(unsigned*, p_kc2_h, g_kc2_h);
    SYM(unsigned*, p_WvT_h, g_WvT_h); SYM(unsigned*, p_WvT_l, g_WvT_l);
    SYM(unsigned*, p_aW1T_h, g_aW1T_h); SYM(unsigned*, p_aW1T_l, g_aW1T_l);
    SYM(unsigned*, p_w1T_h, g_w1T_h); SYM(unsigned*, p_w1T_l, g_w1T_l);
    SYM(unsigned*, p_W2gT_h, g_W2gT_h); SYM(unsigned*, p_W2gT_l, g_W2gT_l);
    SYM(unsigned*, p_skb_in, g_skb_in_h);
    SYM(float*,    p_skb2f, g_skb2f);
    SYM(unsigned*, p_skb2h, g_skb2h);
    SYM(float*,    p_svbTf, g_svbTf);
    SYM(unsigned*, p_vT_h, g_vT_h);
    SYM(float*,    p_qlgf, g_qlgf);
    SYM(unsigned*, p_P_h, g_P_h);
    SYM(float*,    p_memf, g_memf);
    SYM(unsigned*, p_mem_h, g_mem_h);
    SYM(unsigned*, p_t1_h, g_t1_h);
    SYM(float*,    p_scal, g_scal);
    SYM(float*,    p_bias1, g_bias1);
    SYM(float*,    p_bias2, g_bias2);
    #undef SYM

    prep_kernel<<<1, 1>>>(gk, gv, lt);
    bias2_kernel<<<4, 256>>>(kb2, vb2, kb1, vb1);

    // -------- operand preparation --------
    cvt_kernel<<<(NQ/4 + 255)/256, 256>>>(x, p_x_h, NQ/4);
    cvt_kernel<<<(NKMAX*Cx/4 + 255)/256, 256>>>(shmem, p_skb_in, NKMAX*Cx/4);
    cvt_kernel<<<(2560*Cx/4 + 255)/256, 256>>>(cat_B, p_skb_in + NKMAX*Cx, 2560*Cx/4);
    cvt_kernel<<<(Cx*Cx/4 + 255)/256, 256>>>(Wq, p_Wq_rm, Cx*Cx/4);
    cvt_kernel<<<(Cx*Cx/4 + 255)/256, 256>>>(Wk, p_Wk_rm, Cx*Cx/4);
    launch_tsplit(Wv, Cx, Cx, p_WvT_h, p_WvT_l, nullptr);
    launch_tsplit(aW1, Cx, AHx, p_aW1T_h, p_aW1T_l, nullptr);
    launch_tsplit(kW1, Cx, MRx, p_w1T_h, p_w1T_l, nullptr);
    launch_tsplit(vW1, Cx, MRx, p_w1T_h + MRx*Cx, p_w1T_l + MRx*Cx, nullptr);
    launch_tsplit(kW2, MRx, Cx, p_W2gT_h, p_W2gT_l, p_scal + 1);
    launch_tsplit(vW2, MRx, Cx, p_W2gT_h + Cx*MRx, p_W2gT_l + Cx*MRx, p_scal + 2);

    // -------- folded weight GEMMs --------
    // G = Wq @ Wk^T
    launch_g(4, Cx, Cx, Cx, p_Wq_rm, Cx, 0, p_Wk_rm, Cx, p_Wk_rm, Cx, 0,
             p_skb2f, p_G_h, Cx, 0, nullptr, 0, WR_HI, 1);
    // [svT|cbvT] = WvT @ [shm;cat_B]^T
    launch_g(4, Cx, NKB, Cx, p_WvT_h, Cx, 0, p_skb_in, NKB, p_skb_in, Cx, 0,
             p_svbTf, p_G_h, NKB, 0, nullptr, 0, WR_F32, 1);
    // skb2 = skbin @ G^T  (rows 0..319 = FsT)
    launch_g(4, NKB, Cx, Cx, p_skb_in, Cx, 0, p_G_h, Cx, p_G_h, Cx, 0,
             p_skb2f, p_skb2h, Cx, 0, nullptr, 0, WR_F32|WR_HI, 1);
    // FaT -> BQ rows 0..127
    launch_g(4, AHx, Cx, Cx, p_aW1T_h, Cx, 0, p_Wq_rm, Cx, p_Wq_rm, Cx, 0,
             p_memf, p_BQ_h, Cx, 0, nullptr, 0, WR_HI, 1);
    // FsT -> BQ rows 128..447
    copyu_kernel<<<(NKMAX*Cx/4 + 255)/256, 256>>>(p_skb2h, p_BQ_h + AHx*Cx, NKMAX*Cx/4);

    kc2b_kernel<<<NKMAX, 256>>>(catids, cat_A);
    vct_kernel<<<Cx, 320>>>(catids, cat_A);
    aconst_kernel<<<NCATx + Sx, AHx>>>(cat_emb, scale_emb, aW1, ab1);

    // qh|lgs|lgc = x @ [BQ ; kc2[b]]^T  (dual-B, split-M)
    launch_g(4, LMAIN, NBL, Cx, p_x_h, Cx, (long long)Lx*Cx,
             p_BQ_h, NQL, p_kc2_h, Cx, (long long)NKMAX*Cx,
             p_qlgf, p_P_h, NBL, (long long)Lx*NBL, nullptr, 0, WR_F32, Bx);
    launch_g(2, LTAIL, NBL, Cx, p_x_h + (size_t)LMAIN*Cx, Cx, (long long)Lx*Cx,
             p_BQ_h, NQL, p_kc2_h, Cx, (long long)NKMAX*Cx,
             p_qlgf + (size_t)LMAIN*NBL, p_P_h, NBL, (long long)Lx*NBL, nullptr, 0, WR_F32, Bx);

    softmax_kernel<<<(NROW + 7)/8, 256>>>(catids, aW2, ab2);

    // mem = P @ vT^T (batched, K=640, split-M) -> hi plane only
    launch_g(4, LMAIN, Cx, NK2, p_P_h, NK2, (long long)Lx*NK2,
             p_vT_h, 0, p_vT_h, NK2, (long long)Cx*NK2,
             p_memf, p_mem_h, Cx, (long long)Lx*Cx, nullptr, 0, WR_HI, Bx);
    launch_g(2, LTAIL, Cx, NK2, p_P_h + (size_t)LMAIN*NK2, NK2, (long long)Lx*NK2,
             p_vT_h, 0, p_vT_h, NK2, (long long)Cx*NK2,
             p_memf, p_mem_h + (size_t)LMAIN*Cx, Cx, (long long)Lx*Cx, nullptr, 0, WR_HI, Bx);

    // heads
    launch_g(4, NROW, 2*MRx, Cx, p_mem_h, Cx, 0, p_w1T_h, 2*MRx, p_w1T_h, Cx, 0,
             p_memf, p_t1_h, 2*MRx, 0, p_bias1, 0, WR_HI, 1);
    launch_g(4, NROW, Cx, MRx, p_t1_h, 2*MRx, MRx,
             p_W2gT_h, 0, p_W2gT_h, MRx, (long long)Cx*MRx,
             (float*)d_out, p_mem_h, Cx, (long long)NROW*Cx,
             p_bias2, Cx, WR_F32, 2);

    tail_kernel<<<1, 256>>>((float*)d_out, 2 * NROW * Cx, out_size);
}

// round 17
// speedup vs baseline: 2.3632x; 1.0392x over previous
#include <cuda_runtime.h>
#include <math.h>

// ---------------- problem constants ----------------
static constexpr int Bx = 32, Lx = 680, Cx = 1024;
static constexpr int Sx = 10, SLOTSx = 32, Rx = 8, NCATx = 22;
static constexpr int MRx = 64, AHx = 128;
static constexpr int NROW = Bx * Lx;            // 21760
static constexpr int NKMAX = Sx * SLOTSx;       // 320
static constexpr int NQ = NROW * Cx;            // 22282240
static constexpr int NKB = NKMAX + 2560;        // 2880
static constexpr int NQL = AHx + NKMAX;         // 448
static constexpr int NBL = NQL + NKMAX;         // 768
static constexpr int NK2 = 2 * NKMAX;           // 640
static constexpr int LMAIN = 640;               // 5*128
static constexpr int LTAIL = Lx - LMAIN;        // 40

__constant__ int c_begin[10] = {0,1,5,14,30,55,91,155,255,424};

// ---------------- device scratch ----------------
__device__ unsigned g_G_h[Cx*Cx];
__device__ unsigned g_BQ_h[NQL*Cx];                // [FaT(128) ; FsT(320)]
__device__ unsigned g_kc2_h[(size_t)Bx*NKMAX*Cx];
__device__ unsigned g_WvT_h[Cx*Cx], g_WvT_l[Cx*Cx];
__device__ unsigned g_aW1T_h[AHx*Cx], g_aW1T_l[AHx*Cx];
__device__ unsigned g_w1T_h[(2*MRx)*Cx], g_w1T_l[(2*MRx)*Cx];
__device__ unsigned g_W2gT_h[2*Cx*MRx], g_W2gT_l[2*Cx*MRx];
__device__ unsigned g_skb_in_h[NKB*Cx];

__device__ float    g_skb2f[NKB*Cx];
__device__ unsigned g_skb2h[NKB*Cx];
__device__ float    g_svbTf[Cx*NKB];
__device__ unsigned g_vT_h[(size_t)Bx*Cx*NK2];
__device__ float    g_qlgf[(size_t)NROW*NBL];      // qh | lgs | lgc
__device__ unsigned g_P_h[NROW*NK2];
__device__ float    g_memf[NQ];
__device__ unsigned g_mem_h[NQ];
__device__ unsigned g_t1_h[NROW*(2*MRx)];
__device__ float    g_acat[NCATx*AHx];
__device__ float    g_ascale[Sx*AHx];
__device__ float    g_scal[4];
__device__ float    g_bias1[2*MRx];
__device__ float    g_bias2[2*Cx];

// ---------------- helpers ----------------
__device__ __forceinline__ void split_tf32(float x, unsigned& hi, unsigned& lo) {
    unsigned h; asm("cvt.rna.tf32.f32 %0, %1;" : "=r"(h) : "f"(x));
    float hf = __uint_as_float(h);
    unsigned l; asm("cvt.rna.tf32.f32 %0, %1;" : "=r"(l) : "f"(x - hf));
    hi = h; lo = l;
}
__device__ __forceinline__ unsigned to_tf32(float x) {
    unsigned h; asm("cvt.rna.tf32.f32 %0, %1;" : "=r"(h) : "f"(x)); return h;
}
__device__ __forceinline__ void mma8(float* d, const unsigned* a, const unsigned* b) {
    asm volatile(
        "mma.sync.aligned.m16n8k8.row.col.f32.tf32.tf32.f32 "
        "{%0,%1,%2,%3}, {%4,%5,%6,%7}, {%8,%9}, {%0,%1,%2,%3};"
        : "+f"(d[0]), "+f"(d[1]), "+f"(d[2]), "+f"(d[3])
        : "r"(a[0]), "r"(a[1]), "r"(a[2]), "r"(a[3]), "r"(b[0]), "r"(b[1]));
}
__device__ __forceinline__ uint4 ldsm4(unsigned a) {
    uint4 r;
    asm volatile("ldmatrix.sync.aligned.m8n8.x4.shared.b16 {%0,%1,%2,%3}, [%4];"
        : "=r"(r.x), "=r"(r.y), "=r"(r.z), "=r"(r.w) : "r"(a));
    return r;
}
__device__ __forceinline__ unsigned smaddr(const void* p) {
    unsigned a;
    asm("{.reg .u64 u; cvta.to.shared.u64 u, %1; cvt.u32.u64 %0, u;}" : "=r"(a) : "l"(p));
    return a;
}
__device__ __forceinline__ void cp16(unsigned dst, const void* src, bool ok) {
    int sz = ok ? 16 : 0;
    asm volatile("cp.async.cg.shared.global [%0], [%1], 16, %2;\n" :: "r"(dst), "l"(src), "r"(sz));
}
__device__ __forceinline__ void cp_commit() { asm volatile("cp.async.commit_group;"); }
template<int N> __device__ __forceinline__ void cp_wait() {
    asm volatile("cp.async.wait_group %0;" :: "n"(N));
}

// ---------------- prep ----------------
__global__ void prep_kernel(const float* gk, const float* gv, const float* lt) {
    float temp = expf(lt[0]);
    temp = fminf(fmaxf(temp, 0.05f), 1.0f);
    g_scal[0] = (1.0f / 32.0f) / temp;
    g_scal[1] = 1.0f / (1.0f + expf(-gk[0]));
    g_scal[2] = 1.0f / (1.0f + expf(-gv[0]));
}
__global__ void bias2_kernel(const float* kb2, const float* vb2,
                             const float* kb1, const float* vb1) {
    int c = blockIdx.x * 256 + threadIdx.x;
    if (c < Cx) {
        g_bias2[c]      = g_scal[1] * kb2[c];
        g_bias2[Cx + c] = g_scal[2] * vb2[c];
    }
    if (c < MRx) {
        g_bias1[c] = kb1[c];
        g_bias1[MRx + c] = vb1[c];
    }
}

// ---------------- fp32 -> tf32 hi plane ----------------
__global__ void cvt_kernel(const float* __restrict__ in, unsigned* __restrict__ hi, int n4) {
    int i = blockIdx.x * 256 + threadIdx.x;
    if (i >= n4) return;
    float4 v = ((const float4*)in)[i];
    uint4 h;
    h.x = to_tf32(v.x); h.y = to_tf32(v.y); h.z = to_tf32(v.z); h.w = to_tf32(v.w);
    ((uint4*)hi)[i] = h;
}
__global__ void copyu_kernel(const unsigned* __restrict__ src, unsigned* __restrict__ dst, int n4) {
    int i = blockIdx.x * 256 + threadIdx.x;
    if (i < n4) ((uint4*)dst)[i] = ((const uint4*)src)[i];
}

// ---------------- transpose + split (optional gate) ----------------
__global__ void tsplit_kernel(const float* __restrict__ in, int R, int C,
                              unsigned* __restrict__ oh, unsigned* __restrict__ ol,
                              const float* __restrict__ gate)
{
    __shared__ float t[32][33];
    int r0 = blockIdx.y * 32, c0 = blockIdx.x * 32;
    int tx = threadIdx.x, ty = threadIdx.y;
    float gt = gate ? *gate : 1.0f;
    #pragma unroll
    for (int i = 0; i < 32; i += 8) {
        int r = r0 + ty + i;
        t[ty + i][tx] = (r < R && c0 + tx < C) ? gt * in[(size_t)r * C + c0 + tx] : 0.f;
    }
    __syncthreads();
    #pragma unroll
    for (int i = 0; i < 32; i += 8) {
        int c = c0 + ty + i, r = r0 + tx;
        if (c < C && r < R) {
            unsigned h, l; split_tf32(t[tx][ty + i], h, l);
            oh[(size_t)c * R + r] = h;
            ol[(size_t)c * R + r] = l;
        }
    }
}

// ---------------- GEMM ----------------
static constexpr int WR_F32 = 1, WR_HI = 4;

struct GemmArgs {
    int M, N, K;
    const unsigned *Ah; int lda; long long sA;
    const unsigned *Bh; int nb1;               // B rows [0,nb1) from Bh (shared)
    const unsigned *Bh2; int ldb; long long sB; // B rows [nb1,N) from Bh2 (z-strided)
    float* Cf; unsigned *Chi; int ldc; long long sC;
    const float* bias; long long sBias;
    int wr;
};

// MT=4 -> BM=128, MT=2 -> BM=64. BN=128, BK=32, 3-stage, 1-pass tf32.
template<int MT>
__global__ void __launch_bounds__(256, 2) gemm_t(GemmArgs g)
{
    constexpr int BK = 32, AW = 36;
    constexpr int BM = MT * 32;
    constexpr int ASZ = BM * AW, BSZ = 128 * AW, STG = ASZ + BSZ;
    constexpr int ACPT = BM / 32;
    extern __shared__ unsigned sm[];

    const int tid = threadIdx.x, lane = tid & 31, wid = tid >> 5;
    const int wm = wid >> 2, wn = wid & 3, tg = lane & 3, gid = lane >> 2;
    const int bm = blockIdx.y * BM, bn = blockIdx.x * 128;
    const long long z = blockIdx.z;

    const unsigned* Ap = g.Ah + z * g.sA;
    const unsigned* Bp2 = g.Bh2 + z * g.sB;
    const unsigned smbase = smaddr(sm);

    const int am = lane >> 3;
    const int a_row = (am & 1) * 8 + (lane & 7);
    const int a_kw  = (am >> 1) * 4;
    const int b_row = (am >> 1) * 8 + (lane & 7);
    const int b_kw  = (am & 1) * 4;
    unsigned aA[MT], bA[2];
    #pragma unroll
    for (int mt = 0; mt < MT; mt++)
        aA[mt] = smbase + (unsigned)((wm*(MT*16) + mt*16 + a_row) * AW + a_kw) * 4u;
    #pragma unroll
    for (int pr = 0; pr < 2; pr++)
        bA[pr] = smbase + (unsigned)ASZ * 4u
               + (unsigned)((wn*32 + pr*16 + b_row) * AW + b_kw) * 4u;

    float acc[MT][4][4];
    #pragma unroll
    for (int mt = 0; mt < MT; mt++)
        #pragma unroll
        for (int nt = 0; nt < 4; nt++)
            #pragma unroll
            for (int u = 0; u < 4; u++) acc[mt][nt][u] = 0.f;

    auto load_stage = [&](int s, int k0) {
        unsigned base = smbase + (unsigned)(s * STG) * 4u;
        #pragma unroll
        for (int j = 0; j < ACPT; j++) {
            int c = tid + j * 256;
            int row = c >> 3, kc = (c & 7) * 4;
            bool ok = (bm + row) < g.M;
            const unsigned* src = ok ? Ap + (size_t)(bm + row) * g.lda + k0 + kc : Ap;
            cp16(base + (unsigned)(row * AW + kc) * 4u, src, ok);
        }
        unsigned bbase = base + (unsigned)ASZ * 4u;
        #pragma unroll
        for (int j = 0; j < 4; j++) {
            int c = tid + j * 256;
            int row = c >> 3, kc = (c & 7) * 4;
            int grow = bn + row;
            bool ok = grow < g.N;
            const unsigned* src;
            if (grow < g.nb1) src = g.Bh + (size_t)grow * g.ldb + k0 + kc;
            else              src = Bp2 + (size_t)(grow - g.nb1) * g.ldb + k0 + kc;
            if (!ok) src = Ap;
            cp16(bbase + (unsigned)(row * AW + kc) * 4u, src, ok);
        }
    };

    auto compute = [&](int s) {
        const unsigned so = (unsigned)(s * STG) * 4u;
        #pragma unroll
        for (int kk = 0; kk < BK; kk += 8) {
            const unsigned kb = so + (unsigned)kk * 4u;
            unsigned bh[4][2];
            #pragma unroll
            for (int pr = 0; pr < 2; pr++) {
                uint4 r = ldsm4(bA[pr] + kb);
                bh[pr*2+0][0] = r.x; bh[pr*2+0][1] = r.y;
                bh[pr*2+1][0] = r.z; bh[pr*2+1][1] = r.w;
            }
            #pragma unroll
            for (int mt = 0; mt < MT; mt++) {
                uint4 ah4 = ldsm4(aA[mt] + kb);
                #pragma unroll
                for (int nt = 0; nt < 4; nt++)
                    mma8(acc[mt][nt], (const unsigned*)&ah4, bh[nt]);
            }
        }
    };

    const int nK = g.K / BK;
    load_stage(0, 0);
    cp_commit();
    if (nK > 1) load_stage(1, BK);
    cp_commit();
    for (int kt = 0; kt < nK; kt++) {
        cp_wait<1>();
        __syncthreads();
        if (kt + 2 < nK) load_stage((kt + 2) % 3, (kt + 2) * BK);
        cp_commit();
        compute(kt % 3);
    }

    float* Cf = g.Cf + z * g.sC;
    unsigned* Chi = g.Chi + z * g.sC;
    const float* bs = g.bias ? g.bias + z * g.sBias : nullptr;
    #pragma unroll
    for (int mt = 0; mt < MT; mt++) {
        int r0 = bm + wm * (MT*16) + mt * 16 + gid;
        int r1 = r0 + 8;
        #pragma unroll
        for (int nt = 0; nt < 4; nt++) {
            int col = bn + wn * 32 + nt * 8 + 2 * tg;
            if (col >= g.N) continue;
            float b0 = bs ? bs[col]     : 0.f;
            float b1 = bs ? bs[col + 1] : 0.f;
            #pragma unroll
            for (int half = 0; half < 2; half++) {
                int r = half ? r1 : r0;
                if (r >= g.M) continue;
                size_t o = (size_t)r * g.ldc + col;
                float v0 = acc[mt][nt][half*2+0] + b0;
                float v1 = acc[mt][nt][half*2+1] + b1;
                if (g.wr & WR_F32) *(float2*)(Cf + o) = make_float2(v0, v1);
                if (g.wr & WR_HI) { Chi[o] = to_tf32(v0); Chi[o+1] = to_tf32(v1); }
            }
        }
    }
}

// ---------------- kc2 broadcast ----------------
__global__ void __launch_bounds__(256) kc2b_kernel(const int* __restrict__ catids,
                                                   const float* __restrict__ cat_A)
{
    __shared__ float rows[9][Cx];
    int key = blockIdx.x;
    int v = key >> 5, s = key & 31;
    for (int u = threadIdx.x; u < 9*256; u += 256) {
        int rr = u >> 8, c4 = (u & 255) * 4;
        int srow = (rr == 0) ? key : NKMAX + (v*Rx + (rr-1))*SLOTSx + s;
        *(float4*)&rows[rr][c4] = *(const float4*)(g_skb2f + (size_t)srow*Cx + c4);
    }
    __syncthreads();
    int c = threadIdx.x * 4;
    float4 base = *(float4*)&rows[0][c];
    float4 w[Rx];
    #pragma unroll
    for (int r = 0; r < Rx; r++) w[r] = *(float4*)&rows[r+1][c];
    for (int b = 0; b < Bx; b++) {
        int cid = catids[b]; if (cid < 0) cid = 0;
        const float* ar = cat_A + (cid*Sx + v)*Rx;
        float4 o = base;
        #pragma unroll
        for (int r = 0; r < Rx; r++) {
            float a = ar[r];
            o.x += a*w[r].x; o.y += a*w[r].y; o.z += a*w[r].z; o.w += a*w[r].w;
        }
        uint4 h;
        h.x = to_tf32(o.x); h.y = to_tf32(o.y); h.z = to_tf32(o.z); h.w = to_tf32(o.w);
        *(uint4*)(g_kc2_h + ((size_t)b*NKMAX + key)*Cx + c) = h;
    }
}

// ---------------- vT stacked broadcast ----------------
__global__ void __launch_bounds__(320) vct_kernel(const int* __restrict__ catids,
                                                  const float* __restrict__ cat_A)
{
    __shared__ float sv[NKMAX];
    __shared__ float cbv[2560];
    int c = blockIdx.x;
    const float* src = g_svbTf + (size_t)c*NKB;
    for (int u = threadIdx.x; u < NKB; u += 320) {
        float vle = src[u];
        if (u < NKMAX) sv[u] = vle; else cbv[u - NKMAX] = vle;
    }
    __syncthreads();
    int key = threadIdx.x;
    int v = key >> 5, s = key & 31;
    float base = sv[key];
    unsigned base_h = to_tf32(base);
    float w[Rx];
    #pragma unroll
    for (int r = 0; r < Rx; r++) w[r] = cbv[(v*Rx + r)*SLOTSx + s];
    for (int b = 0; b < Bx; b++) {
        int cid = catids[b]; if (cid < 0) cid = 0;
        const float* ar = cat_A + (cid*Sx + v)*Rx;
        float acc = base;
        #pragma unroll
        for (int r = 0; r < Rx; r++) acc += ar[r] * w[r];
        size_t o = ((size_t)b*Cx + c)*NK2;
        g_vT_h[o + key] = base_h;
        g_vT_h[o + NKMAX + key] = to_tf32(acc);
    }
}

// ---------------- alpha constant tables ----------------
__global__ void aconst_kernel(const float* __restrict__ cat_emb,
                              const float* __restrict__ scale_emb,
                              const float* __restrict__ aW1,
                              const float* __restrict__ ab1)
{
    int idx = blockIdx.x, h = threadIdx.x;
    if (idx < NCATx) {
        float acc = 0.f;
        const float* ce = cat_emb + (size_t)idx * Cx;
        for (int c = 0; c < Cx; c++)
            acc += ce[c] * aW1[(size_t)(Cx + c)*AHx + h];
        g_acat[idx*AHx + h] = acc;
    } else {
        int i = idx - NCATx;
        float acc = ab1[h];
        const float* se = scale_emb + (size_t)i * Cx;
        for (int c = 0; c < Cx; c++)
            acc += se[c] * aW1[(size_t)(2*Cx + c)*AHx + h];
        g_ascale[i*AHx + h] = acc;
    }
}

// ---------------- alpha + masked softmax -> stacked P hi planes ----------------
__global__ void __launch_bounds__(256) softmax_kernel(const int* __restrict__ catids,
                                                      const float* __restrict__ aW2,
                                                      const float* __restrict__ ab2)
{
    int w = threadIdx.x >> 5, lane = threadIdx.x & 31;
    int row = blockIdx.x * 8 + w;
    if (row >= NROW) return;
    int b = row / Lx, l = row % Lx;
    int i = 0;
    #pragma unroll
    for (int u = 1; u < 10; u++) if (l >= c_begin[u]) i = u;
    int nk = (i + 1) * SLOTSx;
    float ls = g_scal[0];
    const float* qrow = g_qlgf + (size_t)row * NBL;

    int cid = catids[b];
    float a = 0.f;
    if (cid >= 0) {
        const float* ac = g_acat + cid*AHx;
        const float* as = g_ascale + i*AHx;
        float acc = 0.f;
        #pragma unroll
        for (int h = lane; h < AHx; h += 32) {
            float xv = qrow[h] + ac[h] + as[h];
            float ge = 0.5f*xv*(1.0f + erff(xv*0.70710678118654752f));
            acc += ge * aW2[h];
        }
        #pragma unroll
        for (int o = 16; o > 0; o >>= 1) acc += __shfl_xor_sync(0xffffffffu, acc, o);
        a = 1.0f/(1.0f + expf(-(acc + ab2[0])));
    }

    #pragma unroll
    for (int s = 0; s < 2; s++) {
        const float* p = qrow + AHx + s * NKMAX;
        unsigned* q = g_P_h + (size_t)row * NK2 + s * NKMAX;
        float wgt = s ? a : (1.0f - a);
        float v[10];
        int cnt = 0;
        float mx = -3.4e38f;
        for (int j = lane; j < nk; j += 32) { float t = p[j]*ls; v[cnt++] = t; mx = fmaxf(mx, t); }
        #pragma unroll
        for (int o = 16; o > 0; o >>= 1) mx = fmaxf(mx, __shfl_xor_sync(0xffffffffu, mx, o));
        float sum = 0.f;
        for (int c2 = 0; c2 < cnt; c2++) { v[c2] = expf(v[c2] - mx); sum += v[c2]; }
        #pragma unroll
        for (int o = 16; o > 0; o >>= 1) sum += __shfl_xor_sync(0xffffffffu, sum, o);
        float inv = wgt / sum;
        cnt = 0;
        for (int j = lane; j < NKMAX; j += 32)
            q[j] = (j < nk) ? to_tf32(v[cnt++] * inv) : 0u;
    }
}

// ---------------- tail ----------------
__global__ void tail_kernel(float* out, int n2, int total) {
    int idx = n2 + blockIdx.x*blockDim.x + threadIdx.x;
    if (idx < total) out[idx] = 0.f;
}

// ---------------- host helpers ----------------
static void launch_g(int mt, int M, int N, int K,
                     const unsigned* Ah, int lda, long long sA,
                     const unsigned* Bh, int nb1, const unsigned* Bh2, int ldb, long long sB,
                     float* Cf, unsigned* Chi, int ldc, long long sC,
                     const float* bias, long long sBias, int wr, int batches)
{
    GemmArgs g;
    g.M=M; g.N=N; g.K=K;
    g.Ah=Ah; g.lda=lda; g.sA=sA;
    g.Bh=Bh; g.nb1=nb1; g.Bh2=Bh2; g.ldb=ldb; g.sB=sB;
    g.Cf=Cf; g.Chi=Chi; g.ldc=ldc; g.sC=sC;
    g.bias=bias; g.sBias=sBias; g.wr=wr;
    if (mt == 4) {
        dim3 grid((N + 127)/128, (M + 127)/128, batches);
        gemm_t<4><<<grid, 256, 110592>>>(g);
    } else {
        dim3 grid((N + 127)/128, (M + 63)/64, batches);
        gemm_t<2><<<grid, 256, 82944>>>(g);
    }
}

static void launch_tsplit(const float* in, int R, int C, unsigned* oh, unsigned* ol,
                          const float* gate)
{
    dim3 grid((C + 31)/32, (R + 31)/32);
    tsplit_kernel<<<grid, dim3(32, 8)>>>(in, R, C, oh, ol, gate);
}

// ---------------- launch ----------------
extern "C" void kernel_launch(void* const* d_in, const int* in_sizes, int n_in,
                              void* d_out, int out_size) {
    const float* x        = (const float*)d_in[0];
    const int*   catids   = (const int*)  d_in[1];
    const float* shmem    = (const float*)d_in[2];
    const float* cat_A    = (const float*)d_in[3];
    const float* cat_B    = (const float*)d_in[4];
    const float* cat_emb  = (const float*)d_in[5];
    const float* scale_emb= (const float*)d_in[6];
    const float* Wq       = (const float*)d_in[7];
    const float* Wk       = (const float*)d_in[8];
    const float* Wv       = (const float*)d_in[9];
    const float* aW1      = (const float*)d_in[10];
    const float* ab1      = (const float*)d_in[11];
    const float* aW2      = (const float*)d_in[12];
    const float* ab2      = (const float*)d_in[13];
    const float* kW1      = (const float*)d_in[14];
    const float* kb1      = (const float*)d_in[15];
    const float* kW2      = (const float*)d_in[16];
    const float* kb2      = (const float*)d_in[17];
    const float* vW1      = (const float*)d_in[18];
    const float* vb1      = (const float*)d_in[19];
    const float* vW2      = (const float*)d_in[20];
    const float* vb2      = (const float*)d_in[21];
    const float* gk       = (const float*)d_in[22];
    const float* gv       = (const float*)d_in[23];
    const float* lt       = (const float*)d_in[24];

    // raw fp32 bits fed directly as tf32 operands (HW truncates mantissa)
    const unsigned* p_x_raw  = (const unsigned*)x;
    const unsigned* p_Wq_raw = (const unsigned*)Wq;
    const unsigned* p_Wk_raw = (const unsigned*)Wk;

    cudaFuncSetAttribute(gemm_t<4>, cudaFuncAttributeMaxDynamicSharedMemorySize, 110592);
    cudaFuncSetAttribute(gemm_t<2>, cudaFuncAttributeMaxDynamicSharedMemorySize, 82944);

    #define SYM(t, p, s) t p; cudaGetSymbolAddress((void**)&p, s)
    SYM(unsigned*, p_G_h, g_G_h);
    SYM(unsigned*, p_BQ_h, g_BQ_h);
    SYM(unsigned*, p_kc2_h, g_kc2_h);
    SYM(unsigned*, p_WvT_h, g_WvT_h); SYM(unsigned*, p_WvT_l, g_WvT_l);
    SYM(unsigned*, p_aW1T_h, g_aW1T_h); SYM(unsigned*, p_aW1T_l, g_aW1T_l);
    SYM(unsigned*, p_w1T_h, g_w1T_h); SYM(unsigned*, p_w1T_l, g_w1T_l);
    SYM(unsigned*, p_W2gT_h, g_W2gT_h); SYM(unsigned*, p_W2gT_l, g_W2gT_l);
    SYM(unsigned*, p_skb_in, g_skb_in_h);
    SYM(float*,    p_skb2f, g_skb2f);
    SYM(unsigned*, p_skb2h, g_skb2h);
    SYM(float*,    p_svbTf, g_svbTf);
    SYM(unsigned*, p_vT_h, g_vT_h);
    SYM(float*,    p_qlgf, g_qlgf);
    SYM(unsigned*, p_P_h, g_P_h);
    SYM(float*,    p_memf, g_memf);
    SYM(unsigned*, p_mem_h, g_mem_h);
    SYM(unsigned*, p_t1_h, g_t1_h);
    SYM(float*,    p_scal, g_scal);
    SYM(float*,    p_bias1, g_bias1);
    SYM(float*,    p_bias2, g_bias2);
    #undef SYM

    prep_kernel<<<1, 1>>>(gk, gv, lt);
    bias2_kernel<<<4, 256>>>(kb2, vb2, kb1, vb1);

    // -------- operand preparation --------
    cvt_kernel<<<(NKMAX*Cx/4 + 255)/256, 256>>>(shmem, p_skb_in, NKMAX*Cx/4);
    cvt_kernel<<<(2560*Cx/4 + 255)/256, 256>>>(cat_B, p_skb_in + NKMAX*Cx, 2560*Cx/4);
    launch_tsplit(Wv, Cx, Cx, p_WvT_h, p_WvT_l, nullptr);
    launch_tsplit(aW1, Cx, AHx, p_aW1T_h, p_aW1T_l, nullptr);
    launch_tsplit(kW1, Cx, MRx, p_w1T_h, p_w1T_l, nullptr);
    launch_tsplit(vW1, Cx, MRx, p_w1T_h + MRx*Cx, p_w1T_l + MRx*Cx, nullptr);
    launch_tsplit(kW2, MRx, Cx, p_W2gT_h, p_W2gT_l, p_scal + 1);
    launch_tsplit(vW2, MRx, Cx, p_W2gT_h + Cx*MRx, p_W2gT_l + Cx*MRx, p_scal + 2);

    // -------- folded weight GEMMs --------
    // G = Wq @ Wk^T  (raw fp32 operands)
    launch_g(4, Cx, Cx, Cx, p_Wq_raw, Cx, 0, p_Wk_raw, Cx, p_Wk_raw, Cx, 0,
             p_skb2f, p_G_h, Cx, 0, nullptr, 0, WR_HI, 1);
    // [svT|cbvT] = WvT @ [shm;cat_B]^T
    launch_g(4, Cx, NKB, Cx, p_WvT_h, Cx, 0, p_skb_in, NKB, p_skb_in, Cx, 0,
             p_svbTf, p_G_h, NKB, 0, nullptr, 0, WR_F32, 1);
    // skb2 = skbin @ G^T  (rows 0..319 = FsT)
    launch_g(4, NKB, Cx, Cx, p_skb_in, Cx, 0, p_G_h, Cx, p_G_h, Cx, 0,
             p_skb2f, p_skb2h, Cx, 0, nullptr, 0, WR_F32|WR_HI, 1);
    // FaT -> BQ rows 0..127  (raw Wq as B)
    launch_g(4, AHx, Cx, Cx, p_aW1T_h, Cx, 0, p_Wq_raw, Cx, p_Wq_raw, Cx, 0,
             p_memf, p_BQ_h, Cx, 0, nullptr, 0, WR_HI, 1);
    // FsT -> BQ rows 128..447
    copyu_kernel<<<(NKMAX*Cx/4 + 255)/256, 256>>>(p_skb2h, p_BQ_h + AHx*Cx, NKMAX*Cx/4);

    kc2b_kernel<<<NKMAX, 256>>>(catids, cat_A);
    vct_kernel<<<Cx, 320>>>(catids, cat_A);
    aconst_kernel<<<NCATx + Sx, AHx>>>(cat_emb, scale_emb, aW1, ab1);

    // qh|lgs|lgc = x(raw) @ [BQ ; kc2[b]]^T  (dual-B, split-M)
    launch_g(4, LMAIN, NBL, Cx, p_x_raw, Cx, (long long)Lx*Cx,
             p_BQ_h, NQL, p_kc2_h, Cx, (long long)NKMAX*Cx,
             p_qlgf, p_P_h, NBL, (long long)Lx*NBL, nullptr, 0, WR_F32, Bx);
    launch_g(2, LTAIL, NBL, Cx, p_x_raw + (size_t)LMAIN*Cx, Cx, (long long)Lx*Cx,
             p_BQ_h, NQL, p_kc2_h, Cx, (long long)NKMAX*Cx,
             p_qlgf + (size_t)LMAIN*NBL, p_P_h, NBL, (long long)Lx*NBL, nullptr, 0, WR_F32, Bx);

    softmax_kernel<<<(NROW + 7)/8, 256>>>(catids, aW2, ab2);

    // mem = P @ vT^T (batched, K=640, split-M) -> hi plane only
    launch_g(4, LMAIN, Cx, NK2, p_P_h, NK2, (long long)Lx*NK2,
             p_vT_h, 0, p_vT_h, NK2, (long long)Cx*NK2,
             p_memf, p_mem_h, Cx, (long long)Lx*Cx, nullptr, 0, WR_HI, Bx);
    launch_g(2, LTAIL, Cx, NK2, p_P_h + (size_t)LMAIN*NK2, NK2, (long long)Lx*NK2,
             p_vT_h, 0, p_vT_h, NK2, (long long)Cx*NK2,
             p_memf, p_mem_h + (size_t)LMAIN*Cx, Cx, (long long)Lx*Cx, nullptr, 0, WR_HI, Bx);

    // heads
    launch_g(4, NROW, 2*MRx, Cx, p_mem_h, Cx, 0, p_w1T_h, 2*MRx, p_w1T_h, Cx, 0,
             p_memf, p_t1_h, 2*MRx, 0, p_bias1, 0, WR_HI, 1);
    launch_g(4, NROW, Cx, MRx, p_t1_h, 2*MRx, MRx,
             p_W2gT_h, 0, p_W2gT_h, MRx, (long long)Cx*MRx,
             (float*)d_out, p_mem_h, Cx, (long long)NROW*Cx,
             p_bias2, Cx, WR_F32, 2);

    tail_kernel<<<1, 256>>>((float*)d_out, 2 * NROW * Cx, out_size);
}